// round 1
// baseline (speedup 1.0000x reference)
#include <cuda_runtime.h>
#include <math.h>

#define BDIM 256      // batch
#define HDIM 512      // hidden
#define NENC 60
#define S1 62         // nodes in rgcn1
#define S2 63         // nodes in rgcn2
#define NQ 6          // basis rank
#define KDIM 3584     // 6*512 + 512 (self)

// ---------------- scratch (static device global; no allocation) ----------------
// layout (floats):
//  CW0        : 3584*512            = 1,835,008
//  CW1        : 1,835,008
//  INIT       : 256*2*512           =   262,144
//  X1         : 256*62*512          = 8,126,464
//  X2         : 256*63*512          = 8,257,536
//  Z          : 256*63*512          = 8,257,536
//  T          : 256*4*512           =   524,288
//  U          : 256*2*512           =   262,144
//  AC1        : 2*256*6*62*62       = 11,808,768
//  AC2        : 2*256*6*63*63       = 12,192,768
//  F          : 256*63*3584         = 57,802,752
// total = 111,164,416 floats (~445 MB)
static __device__ float g_scratch[111164416];

// ---------------- f32x2 helpers ----------------
__device__ __forceinline__ unsigned long long dup2(float a) {
    unsigned long long d;
    asm("mov.b64 %0, {%1, %1};" : "=l"(d) : "f"(a));
    return d;
}
__device__ __forceinline__ void fma2(unsigned long long &acc, unsigned long long a, unsigned long long b) {
    asm("fma.rn.f32x2 %0, %1, %2, %0;" : "+l"(acc) : "l"(a), "l"(b));
}
__device__ __forceinline__ void unpack2(unsigned long long v, float &lo, float &hi) {
    asm("mov.b64 {%0, %1}, %2;" : "=f"(lo), "=f"(hi) : "l"(v));
}

// ---------------- build combined weight [basis stacked ; self^T] ----------------
__global__ void k_build_cw(const float* __restrict__ basis, const float* __restrict__ selfW,
                           float* __restrict__ CW) {
    int idx = blockIdx.x * 256 + threadIdx.x;           // over 3584*512
    if (idx >= KDIM * HDIM) return;
    int row = idx >> 9;           // /512
    int k   = idx & 511;
    CW[idx] = (row < 3072) ? basis[idx] : selfW[k * HDIM + (row - 3072)];
}

// ---------------- AC = sum_r comb[r,q] * A_r  (rgcn1 adjacency, 62x62) ----------------
__global__ void k_ac1(const int* __restrict__ adj, const float* __restrict__ comb0,
                      const float* __restrict__ comb1, float* __restrict__ AC) {
    __shared__ float sc[2][12][6];
    int t = threadIdx.x;
    if (t < 72) { sc[0][t / 6][t % 6] = comb0[t]; sc[1][t / 6][t % 6] = comb1[t]; }
    __syncthreads();
    int b = blockIdx.x;
    int e = blockIdx.y * 256 + t;
    if (e >= S1 * S1) return;
    int n = e / S1, m = e % S1;
    float a[12];
#pragma unroll
    for (int r = 0; r < 12; r++)
        a[r] = (float)adj[(((size_t)b * 13 + r + 1) * S1 + n) * S1 + m];
#pragma unroll
    for (int L = 0; L < 2; L++)
#pragma unroll
        for (int q = 0; q < NQ; q++) {
            float s = 0.f;
#pragma unroll
            for (int r = 0; r < 12; r++) s += sc[L][r][q] * a[r];
            AC[((((size_t)L * BDIM + b) * NQ + q) * S1 + n) * S1 + m] = s;
        }
}

// ---------------- AC for rgcn2 (63x63, built from updated adjacency on the fly) ----------------
__global__ void k_ac2(const int* __restrict__ adj, const float* __restrict__ comb0,
                      const float* __restrict__ comb1, float* __restrict__ AC) {
    __shared__ float sc[2][12][6];
    int t = threadIdx.x;
    if (t < 72) { sc[0][t / 6][t % 6] = comb0[t]; sc[1][t / 6][t % 6] = comb1[t]; }
    __syncthreads();
    int b = blockIdx.x;
    int e = blockIdx.y * 256 + t;
    if (e >= S2 * S2) return;
    int n = e / S2, m = e % S2;
    // keep = [0..61, 63]: index 62 maps to original 63
    int oi = (n == 62) ? 63 : n;
    int oj = (m == 62) ? 63 : m;
    float a[12];
#pragma unroll
    for (int r = 0; r < 12; r++) {
        int v = 0;
        if (oi < 62 && oj < 62)
            v = adj[(((size_t)b * 13 + r + 1) * S1 + oi) * S1 + oj];
        a[r] = (float)v;
    }
    // parity masks (channels 11/12) on the 64-node graph: pairs differ by exactly 2
    int lo = min(oi, oj), hi = max(oi, oj);
    if (hi - lo == 2) {
        int ni = lo >> 1;
        int ch = ((lo & 1) == 0) ? ((ni & 1) ? 12 : 11) : ((ni & 1) ? 11 : 12);
        a[ch - 1] = 1.f;
    }
#pragma unroll
    for (int L = 0; L < 2; L++)
#pragma unroll
        for (int q = 0; q < NQ; q++) {
            float s = 0.f;
#pragma unroll
            for (int r = 0; r < 12; r++) s += sc[L][r][q] * a[r];
            AC[((((size_t)L * BDIM + b) * NQ + q) * S2 + n) * S2 + m] = s;
        }
}

// ---------------- initial node embedding (B,2,512) ----------------
__global__ void k_initial(const int* __restrict__ player,
                          const float* __restrict__ Ax, const float* __restrict__ Ay,
                          const float* __restrict__ Bx, const float* __restrict__ By,
                          const float* __restrict__ emb, const float* __restrict__ cW,
                          const float* __restrict__ cb, const float* __restrict__ inW,
                          const float* __restrict__ inb, float* __restrict__ out) {
    __shared__ float feat[2][64];
    int b = blockIdx.x, t = threadIdx.x;
    if (t < 64) {
        int p = t >> 5, l = t & 31;
        float x = p ? Bx[b] : Ax[b];
        float y = p ? By[b] : Ay[b];
        float v = cW[l * 2] * x + cW[l * 2 + 1] * y + cb[l];
        feat[p][l] = fmaxf(v, 0.f);
    } else if (t < 128) {
        int tt = t - 64;
        int p = tt >> 5, l = tt & 31;
        feat[p][32 + l] = emb[player[b * 2 + p] * 32 + l];
    }
    __syncthreads();
    for (int o = t; o < 1024; o += 256) {
        int p = o >> 9, h = o & 511;
        float s = inb[h];
        const float* w = inW + h * 64;
        const float* f = feat[p];
#pragma unroll
        for (int j = 0; j < 64; j++) s += w[j] * f[j];
        out[((size_t)b * 2 + p) * HDIM + h] = s;
    }
}

// ---------------- assemble node features ----------------
__global__ void k_x1(const float* __restrict__ enc, const float* __restrict__ init,
                     float* __restrict__ X1) {
    size_t i = (size_t)blockIdx.x * 256 + threadIdx.x;   // B*62*512
    int b = (int)(i / (S1 * HDIM));
    int rem = (int)(i % (S1 * HDIM));
    int n = rem / HDIM, h = rem & 511;
    X1[i] = (n < NENC) ? enc[((size_t)b * NENC + n) * HDIM + h]
                       : init[((size_t)b * 2 + (n - NENC)) * HDIM + h];
}

__global__ void k_x2(const float* __restrict__ enc, const float* __restrict__ T,
                     const float* __restrict__ init, float* __restrict__ X2) {
    size_t i = (size_t)blockIdx.x * 256 + threadIdx.x;   // B*63*512
    int b = (int)(i / (S2 * HDIM));
    int rem = (int)(i % (S2 * HDIM));
    int n = rem / HDIM, h = rem & 511;
    float v;
    if (n < 58)       v = enc[((size_t)b * NENC + n) * HDIM + h];
    else if (n < 62)  v = T[((size_t)b * 4 + (n - 58)) * HDIM + h];
    else              v = init[((size_t)b * 2 + 1) * HDIM + h];
    X2[i] = v;
}

// ---------------- message aggregation: F[b,i,q*512+h] = sum_m AC[b,q,row,m]*X[b,m,h]; tail = X[row] ----------------
__global__ void k_msg(const float* __restrict__ AC, const float* __restrict__ X,
                      float* __restrict__ F, int nodes, int nRows, int rowBase, int rowStride) {
    int b = blockIdx.y, i = blockIdx.x;
    int row = rowBase + i * rowStride;
    __shared__ unsigned long long sA[NQ][64];
    int t = threadIdx.x;
    for (int e = t; e < NQ * nodes; e += 256) {
        int q = e / nodes, m = e % nodes;
        float a = AC[(((size_t)b * NQ + q) * nodes + row) * nodes + m];
        sA[q][m] = dup2(a);
    }
    __syncthreads();
    unsigned long long acc[NQ] = {0ULL, 0ULL, 0ULL, 0ULL, 0ULL, 0ULL};
    const float* xb = X + (size_t)b * nodes * HDIM;
    int h = t * 2;
    for (int m = 0; m < nodes; m++) {
        unsigned long long xv = *(const unsigned long long*)(xb + (size_t)m * HDIM + h);
#pragma unroll
        for (int q = 0; q < NQ; q++) fma2(acc[q], sA[q][m], xv);
    }
    float* Fp = F + ((size_t)b * nRows + i) * KDIM;
#pragma unroll
    for (int q = 0; q < NQ; q++)
        *(unsigned long long*)(Fp + q * HDIM + h) = acc[q];
    *(unsigned long long*)(Fp + 3072 + h) = *(const unsigned long long*)(xb + (size_t)row * HDIM + h);
}

// ---------------- SGEMM: C[M,512] = act(A[M,KDIM] @ B[KDIM,512]), f32x2 inner ----------------
#define BM 128
#define BN 128
#define BK 8
__global__ __launch_bounds__(256, 2)
void k_gemm(const float* __restrict__ A, const float* __restrict__ Bw,
            float* __restrict__ C, int act) {
    __shared__ float As[BK][BM];
    __shared__ float Bs[BK][BN];
    int tid = threadIdx.x;
    int brow = blockIdx.x, bcol = blockIdx.y;

    int arow = tid >> 1;
    int ak   = (tid & 1) * 4;
    int bk   = tid >> 5;
    int bc4  = (tid & 31) * 4;
    const float* Aptr = A + ((size_t)(brow * BM + arow)) * KDIM + ak;
    const float* Bptr = Bw + (size_t)bk * HDIM + bcol * BN + bc4;

    int tx = tid & 15, ty = tid >> 4;
    int r0  = ty * 8;
    int c0a = tx * 4;
    int c0b = 64 + tx * 4;

    unsigned long long acc[8][4];
#pragma unroll
    for (int i = 0; i < 8; i++)
#pragma unroll
        for (int j = 0; j < 4; j++) acc[i][j] = 0ULL;

    for (int kt = 0; kt < KDIM; kt += BK) {
        float4 av = *(const float4*)(Aptr + kt);
        float4 bv = *(const float4*)(Bptr + (size_t)kt * HDIM);
        As[ak + 0][arow] = av.x;
        As[ak + 1][arow] = av.y;
        As[ak + 2][arow] = av.z;
        As[ak + 3][arow] = av.w;
        *(float4*)&Bs[bk][bc4] = bv;
        __syncthreads();
#pragma unroll
        for (int k = 0; k < BK; k++) {
            float4 a0 = *(const float4*)&As[k][r0];
            float4 a1 = *(const float4*)&As[k][r0 + 4];
            ulonglong2 bA = *(const ulonglong2*)&Bs[k][c0a];
            ulonglong2 bB = *(const ulonglong2*)&Bs[k][c0b];
            unsigned long long b2[4] = {bA.x, bA.y, bB.x, bB.y};
            float aarr[8] = {a0.x, a0.y, a0.z, a0.w, a1.x, a1.y, a1.z, a1.w};
#pragma unroll
            for (int i = 0; i < 8; i++) {
                unsigned long long ad = dup2(aarr[i]);
#pragma unroll
                for (int j = 0; j < 4; j++) fma2(acc[i][j], ad, b2[j]);
            }
        }
        __syncthreads();
    }

    int colbase = bcol * BN;
#pragma unroll
    for (int i = 0; i < 8; i++) {
        float* Cp = C + ((size_t)(brow * BM + r0 + i)) * HDIM + colbase;
#pragma unroll
        for (int j = 0; j < 4; j++) {
            float lo, hi;
            unpack2(acc[i][j], lo, hi);
            if (act) {
                lo = 1.f / (1.f + expf(-lo));
                hi = 1.f / (1.f + expf(-hi));
            } else {
                lo = fmaxf(lo, 0.f);
                hi = fmaxf(hi, 0.f);
            }
            int c = (j < 2) ? (c0a + 2 * j) : (c0b + 2 * (j - 2));
            float2 w2; w2.x = lo; w2.y = hi;
            *(float2*)(Cp + c) = w2;
        }
    }
}

// ---------------- final logits: [black(U row1) | white(U row0)] @ typeW^T + b ----------------
__global__ void k_logits(const float* __restrict__ U, const float* __restrict__ tW,
                         const float* __restrict__ tb, float* __restrict__ out) {
    int b = blockIdx.x;
    int w = threadIdx.x >> 5, lane = threadIdx.x & 31;
    if (w >= 11) return;
    const float* black = U + ((size_t)b * 2 + 1) * HDIM;   // tmp2[:,62]
    const float* white = U + ((size_t)b * 2 + 0) * HDIM;   // tmp2[:,60]
    const float* row = tW + w * 1024;
    float s = 0.f;
    for (int j = lane; j < HDIM; j += 32)
        s += black[j] * row[j] + white[j] * row[HDIM + j];
#pragma unroll
    for (int o = 16; o; o >>= 1) s += __shfl_down_sync(0xffffffffu, s, o);
    if (lane == 0) out[b * 11 + w] = s + tb[w];
}

// ---------------- host ----------------
extern "C" void kernel_launch(void* const* d_in, const int* in_sizes, int n_in,
                              void* d_out, int out_size) {
    // 'step' may or may not be materialized as an input (it is a python int, value 32)
    int s = (n_in >= 21 && in_sizes[1] == 1) ? 1 : 0;

    const int*   player = (const int*)d_in[0];
    const float* enc    = (const float*)d_in[1 + s];
    const int*   adj    = (const int*)d_in[2 + s];
    const float* Ax     = (const float*)d_in[3 + s];
    const float* Ay     = (const float*)d_in[4 + s];
    const float* Bx     = (const float*)d_in[5 + s];
    const float* By     = (const float*)d_in[6 + s];
    const float* emb    = (const float*)d_in[7 + s];
    const float* coordW = (const float*)d_in[8 + s];
    const float* coordB = (const float*)d_in[9 + s];
    const float* inW    = (const float*)d_in[10 + s];
    const float* inB    = (const float*)d_in[11 + s];
    const float* basis0 = (const float*)d_in[12 + s];
    const float* comb0  = (const float*)d_in[13 + s];
    const float* self0  = (const float*)d_in[14 + s];
    const float* basis1 = (const float*)d_in[15 + s];
    const float* comb1  = (const float*)d_in[16 + s];
    const float* self1  = (const float*)d_in[17 + s];
    const float* typeW  = (const float*)d_in[18 + s];
    const float* typeB  = (const float*)d_in[19 + s];

    float* base = nullptr;
    cudaGetSymbolAddress((void**)&base, g_scratch);
    float* CW0  = base;
    float* CW1  = CW0 + 1835008;
    float* INIT = CW1 + 1835008;
    float* X1   = INIT + 262144;
    float* X2v  = X1 + 8126464;
    float* Z    = X2v + 8257536;
    float* T    = Z + 8257536;
    float* U    = T + 524288;
    float* AC1  = U + 262144;       // [2][B][6][62][62]
    float* AC2  = AC1 + 11808768;   // [2][B][6][63][63]
    float* F    = AC2 + 12192768;

    const size_t AC1_L = (size_t)BDIM * NQ * S1 * S1;
    const size_t AC2_L = (size_t)BDIM * NQ * S2 * S2;

    k_build_cw<<<(KDIM * HDIM) / 256, 256>>>(basis0, self0, CW0);
    k_build_cw<<<(KDIM * HDIM) / 256, 256>>>(basis1, self1, CW1);
    k_ac1<<<dim3(BDIM, (S1 * S1 + 255) / 256), 256>>>(adj, comb0, comb1, AC1);
    k_ac2<<<dim3(BDIM, (S2 * S2 + 255) / 256), 256>>>(adj, comb0, comb1, AC2);
    k_initial<<<BDIM, 256>>>(player, Ax, Ay, Bx, By, emb, coordW, coordB, inW, inB, INIT);
    k_x1<<<(BDIM * S1 * HDIM) / 256, 256>>>(enc, INIT, X1);

    // rgcn1 layer1: all 62 rows
    k_msg<<<dim3(S1, BDIM), 256>>>(AC1, X1, F, S1, S1, 0, 1);
    k_gemm<<<dim3(BDIM * S1 / BM, HDIM / BN), 256>>>(F, CW0, Z, 0);
    // rgcn1 layer2: only rows 58..61 feed the output
    k_msg<<<dim3(4, BDIM), 256>>>(AC1 + AC1_L, Z, F, S1, 4, 58, 1);
    k_gemm<<<dim3(BDIM * 4 / BM, HDIM / BN), 256>>>(F, CW1, T, 1);

    k_x2<<<(BDIM * S2 * HDIM) / 256, 256>>>(enc, T, INIT, X2v);

    // rgcn2 layer1: all 63 rows
    k_msg<<<dim3(S2, BDIM), 256>>>(AC2, X2v, F, S2, S2, 0, 1);
    k_gemm<<<dim3(BDIM * S2 / BM, HDIM / BN), 256>>>(F, CW0, Z, 0);
    // rgcn2 layer2: only rows 60 (white) and 62 (black)
    k_msg<<<dim3(2, BDIM), 256>>>(AC2 + AC2_L, Z, F, S2, 2, 60, 2);
    k_gemm<<<dim3(BDIM * 2 / BM, HDIM / BN), 256>>>(F, CW1, U, 1);

    k_logits<<<BDIM, 352>>>(U, typeW, typeB, (float*)d_out);
}

// round 3
// speedup vs baseline: 1.7074x; 1.7074x over previous
#include <cuda_runtime.h>
#include <math.h>

#define B      256
#define HDIM   512
#define NENC   60
#define S1     62
#define S2     63
#define NQ     6
#define KDIM   3584      // 6*512 + 512
#define NODES  66        // union: enc(60) + init(2) + T(4)

typedef unsigned long long ull;

// ---------------- scratch ----------------
static __device__ float g_scratch[117980160];

// ---------------- f32x2 helpers ----------------
__device__ __forceinline__ ull dup2(float a) {
    ull d; asm("mov.b64 %0, {%1, %1};" : "=l"(d) : "f"(a)); return d;
}
__device__ __forceinline__ void fma2(ull &acc, ull a, ull b) {
    asm("fma.rn.f32x2 %0, %1, %2, %0;" : "+l"(acc) : "l"(a), "l"(b));
}
__device__ __forceinline__ void unpack2(ull v, float &lo, float &hi) {
    asm("mov.b64 {%0, %1}, %2;" : "=f"(lo), "=f"(hi) : "l"(v));
}

// ---------------- weight builders ----------------
// CWy[h][c]: c<3072 -> basis0[q][h][k] (c=q*512+k); c>=3072 -> self0[k][h]
__global__ void k_build_cwy(const float* __restrict__ basis, const float* __restrict__ selfW,
                            float* __restrict__ CW) {
    int idx = blockIdx.x * 256 + threadIdx.x;      // over 512*3584
    if (idx >= HDIM * KDIM) return;
    int h = idx / KDIM;
    int c = idx - h * KDIM;
    float v;
    if (c < 3072) {
        int q = c >> 9, k = c & 511;
        v = basis[((size_t)q * 512 + h) * 512 + k];
    } else {
        int k = c - 3072;
        v = selfW[(size_t)k * 512 + h];
    }
    CW[idx] = v;
}

// CW1: [3584 rows][512]: rows<3072 = basis1 flat; rows>=3072: self1^T
__global__ void k_build_cw1(const float* __restrict__ basis, const float* __restrict__ selfW,
                            float* __restrict__ CW) {
    int idx = blockIdx.x * 256 + threadIdx.x;      // over 3584*512
    if (idx >= KDIM * HDIM) return;
    int row = idx >> 9;
    int k   = idx & 511;
    CW[idx] = (row < 3072) ? basis[idx] : selfW[(size_t)k * HDIM + (row - 3072)];
}

// ---------------- AC builders (combine layout for L0 + msg layout for L1) ----------------
__global__ void k_ac1(const int* __restrict__ adj, const float* __restrict__ comb0,
                      const float* __restrict__ comb1, float* __restrict__ ACc,
                      float* __restrict__ ACm) {
    __shared__ float sc[2][12][6];
    int t = threadIdx.x;
    if (t < 72) { sc[0][t / 6][t % 6] = comb0[t]; sc[1][t / 6][t % 6] = comb1[t]; }
    __syncthreads();
    int b = blockIdx.x;
    int e = blockIdx.y * 256 + t;
    if (e >= S1 * S1) return;
    int n = e / S1, m = e % S1;
    float a[12];
#pragma unroll
    for (int r = 0; r < 12; r++)
        a[r] = (float)adj[(((size_t)b * 13 + r + 1) * S1 + n) * S1 + m];
#pragma unroll
    for (int q = 0; q < NQ; q++) {
        float s0 = 0.f, s1 = 0.f;
#pragma unroll
        for (int r = 0; r < 12; r++) { s0 += sc[0][r][q] * a[r]; s1 += sc[1][r][q] * a[r]; }
        ACc[((size_t)b * S1 + n) * (NQ * S1) + q * S1 + m] = s0;
        ACm[(((size_t)b * NQ + q) * S1 + n) * S1 + m] = s1;
    }
}

__global__ void k_ac2(const int* __restrict__ adj, const float* __restrict__ comb0,
                      const float* __restrict__ comb1, float* __restrict__ ACc,
                      float* __restrict__ ACm) {
    __shared__ float sc[2][12][6];
    int t = threadIdx.x;
    if (t < 72) { sc[0][t / 6][t % 6] = comb0[t]; sc[1][t / 6][t % 6] = comb1[t]; }
    __syncthreads();
    int b = blockIdx.x;
    int e = blockIdx.y * 256 + t;
    if (e >= S2 * S2) return;
    int n = e / S2, m = e % S2;
    int oi = (n == 62) ? 63 : n;
    int oj = (m == 62) ? 63 : m;
    float a[12];
#pragma unroll
    for (int r = 0; r < 12; r++) {
        int v = 0;
        if (oi < 62 && oj < 62)
            v = adj[(((size_t)b * 13 + r + 1) * S1 + oi) * S1 + oj];
        a[r] = (float)v;
    }
    int lo = min(oi, oj), hi = max(oi, oj);
    if (hi - lo == 2) {
        int ni = lo >> 1;
        int ch = ((lo & 1) == 0) ? ((ni & 1) ? 12 : 11) : ((ni & 1) ? 11 : 12);
        a[ch - 1] = 1.f;
    }
#pragma unroll
    for (int q = 0; q < NQ; q++) {
        float s0 = 0.f, s1 = 0.f;
#pragma unroll
        for (int r = 0; r < 12; r++) { s0 += sc[0][r][q] * a[r]; s1 += sc[1][r][q] * a[r]; }
        ACc[((size_t)b * S2 + n) * (NQ * S2) + q * S2 + m] = s0;
        ACm[(((size_t)b * NQ + q) * S2 + n) * S2 + m] = s1;
    }
}

// ---------------- initial node embedding (B,2,512) ----------------
__global__ void k_initial(const int* __restrict__ player,
                          const float* __restrict__ Ax, const float* __restrict__ Ay,
                          const float* __restrict__ Bx, const float* __restrict__ By,
                          const float* __restrict__ emb, const float* __restrict__ cW,
                          const float* __restrict__ cb, const float* __restrict__ inW,
                          const float* __restrict__ inb, float* __restrict__ out) {
    __shared__ float feat[2][64];
    int b = blockIdx.x, t = threadIdx.x;
    if (t < 64) {
        int p = t >> 5, l = t & 31;
        float x = p ? Bx[b] : Ax[b];
        float y = p ? By[b] : Ay[b];
        float v = cW[l * 2] * x + cW[l * 2 + 1] * y + cb[l];
        feat[p][l] = fmaxf(v, 0.f);
    } else if (t < 128) {
        int tt = t - 64;
        int p = tt >> 5, l = tt & 31;
        feat[p][32 + l] = emb[player[b * 2 + p] * 32 + l];
    }
    __syncthreads();
    for (int o = t; o < 1024; o += 256) {
        int p = o >> 9, h = o & 511;
        float s = inb[h];
        const float* w = inW + h * 64;
        const float* f = feat[p];
#pragma unroll
        for (int j = 0; j < 64; j++) s += w[j] * f[j];
        out[((size_t)b * 2 + p) * HDIM + h] = s;
    }
}

// ---------------- XU builders (node-major: XU[node][b][h]) ----------------
__global__ void k_xu(const float* __restrict__ enc, const float* __restrict__ init,
                     float* __restrict__ XU) {
    size_t i = (size_t)blockIdx.x * 256 + threadIdx.x;   // 62*B*512
    int node = (int)(i / (B * HDIM));
    int rem  = (int)(i % (B * HDIM));
    int b = rem >> 9, h = rem & 511;
    XU[i] = (node < NENC) ? enc[((size_t)b * NENC + node) * HDIM + h]
                          : init[((size_t)b * 2 + (node - NENC)) * HDIM + h];
}

__global__ void k_copyT(const float* __restrict__ Tb, float* __restrict__ XU) {
    size_t i = (size_t)blockIdx.x * 256 + threadIdx.x;   // 4*B*512
    int j = (int)(i / (B * HDIM));
    int rem = (int)(i % (B * HDIM));
    int b = rem >> 9, h = rem & 511;
    XU[(((size_t)(62 + j)) * B + b) * HDIM + h] = Tb[((size_t)b * 4 + j) * HDIM + h];
}

// ---------------- generic SGEMM: C[M,N'] = act(A[M,K] @ Bw[K,ldn]), f32x2 ----------------
// act: 0 = none, 2 = sigmoid
__global__ __launch_bounds__(256, 2)
void k_gemm(const float* __restrict__ A, const float* __restrict__ Bw,
            float* __restrict__ C, int K, int lda, int ldn, int act) {
    __shared__ __align__(16) float As[8][128];
    __shared__ __align__(16) float Bs[8][128];
    int tid = threadIdx.x;
    int brow = blockIdx.x, bcol = blockIdx.y;

    int arow = tid >> 1;
    int ak   = (tid & 1) * 4;
    int bk   = tid >> 5;
    int bc4  = (tid & 31) * 4;
    const float* Aptr = A + (size_t)(brow * 128 + arow) * lda + ak;
    const float* Bptr = Bw + (size_t)bk * ldn + bcol * 128 + bc4;

    int tx = tid & 15, ty = tid >> 4;
    int r0  = ty * 8;
    int c0a = tx * 4;
    int c0b = 64 + tx * 4;

    ull acc[8][4];
#pragma unroll
    for (int i = 0; i < 8; i++)
#pragma unroll
        for (int j = 0; j < 4; j++) acc[i][j] = 0ULL;

    for (int kt = 0; kt < K; kt += 8) {
        float4 av = *(const float4*)(Aptr + kt);
        float4 bv = *(const float4*)(Bptr + (size_t)kt * ldn);
        As[ak + 0][arow] = av.x;
        As[ak + 1][arow] = av.y;
        As[ak + 2][arow] = av.z;
        As[ak + 3][arow] = av.w;
        *(float4*)&Bs[bk][bc4] = bv;
        __syncthreads();
#pragma unroll
        for (int k = 0; k < 8; k++) {
            float4 a0 = *(const float4*)&As[k][r0];
            float4 a1 = *(const float4*)&As[k][r0 + 4];
            ulonglong2 bA = *(const ulonglong2*)&Bs[k][c0a];
            ulonglong2 bB = *(const ulonglong2*)&Bs[k][c0b];
            ull b2[4] = {bA.x, bA.y, bB.x, bB.y};
            float aarr[8] = {a0.x, a0.y, a0.z, a0.w, a1.x, a1.y, a1.z, a1.w};
#pragma unroll
            for (int i = 0; i < 8; i++) {
                ull ad = dup2(aarr[i]);
#pragma unroll
                for (int j = 0; j < 4; j++) fma2(acc[i][j], ad, b2[j]);
            }
        }
        __syncthreads();
    }

    int colbase = bcol * 128;
#pragma unroll
    for (int i = 0; i < 8; i++) {
        float* Cp = C + (size_t)(brow * 128 + r0 + i) * ldn + colbase;
#pragma unroll
        for (int j = 0; j < 4; j++) {
            float lo, hi;
            unpack2(acc[i][j], lo, hi);
            if (act == 2) {
                lo = 1.f / (1.f + expf(-lo));
                hi = 1.f / (1.f + expf(-hi));
            }
            int c = (j < 2) ? (c0a + 2 * j) : (c0b + 2 * (j - 2));
            float2 w2; w2.x = lo; w2.y = hi;
            *(float2*)(Cp + c) = w2;
        }
    }
}

// ---------------- combine: Z[b,n,:] = relu( sum_q AC_q[b,n,:] @ Y_q[b] + Y_self[b,n,:] ) ----------
// ACc layout: [b][n][q*S+m]; Y layout: [node][b][3584] (q-block cols + self cols 3072..)
template<int S, int RG>
__global__ __launch_bounds__(256)
void k_combine(const float* __restrict__ ACc, const float* __restrict__ Y,
               float* __restrict__ Z) {
    const int K = 6 * S;
    __shared__ __align__(16) float As[8][64];
    __shared__ __align__(16) float Bs[8][128];
    __shared__ int boff[6 * 63];
    int t = threadIdx.x;
    int b = blockIdx.y;
    int nb = blockIdx.x * 128;

    for (int k = t; k < K; k += 256) {
        int q = k / S, m = k - q * S;
        int node = (RG == 1) ? m : (m < 58 ? m : (m < 62 ? 62 + (m - 58) : 61));
        boff[k] = node * (B * KDIM) + q * HDIM;
    }
    __syncthreads();

    int ty = t >> 5, tx = t & 31;
    int r0 = ty * 8, c0 = tx * 4;
    ull acc[8][2];
#pragma unroll
    for (int i = 0; i < 8; i++) { acc[i][0] = 0ULL; acc[i][1] = 0ULL; }

    const float* Yb = Y + (size_t)b * KDIM + nb;
    const float* Ab = ACc + (size_t)b * S * K;

    for (int kt = 0; kt < K; kt += 8) {
        // A: 64 rows x 8 k, 2 per thread
        int e = t;
#pragma unroll
        for (int rep = 0; rep < 2; rep++, e += 256) {
            int kk = e & 7, n = e >> 3;
            int k = kt + kk;
            float v = 0.f;
            if (n < S && k < K) v = Ab[(size_t)n * K + k];
            As[kk][n] = v;
        }
        // B: 8 k-rows x 128 cols, one float4 per thread
        {
            int kk = t >> 5, c4 = (t & 31) * 4;
            int k = kt + kk;
            float4 v = {0.f, 0.f, 0.f, 0.f};
            if (k < K) v = *(const float4*)(Yb + boff[k] + c4);
            *(float4*)&Bs[kk][c4] = v;
        }
        __syncthreads();
#pragma unroll
        for (int kk = 0; kk < 8; kk++) {
            float4 a0 = *(const float4*)&As[kk][r0];
            float4 a1 = *(const float4*)&As[kk][r0 + 4];
            ulonglong2 bv = *(const ulonglong2*)&Bs[kk][c0];
            float aa[8] = {a0.x, a0.y, a0.z, a0.w, a1.x, a1.y, a1.z, a1.w};
#pragma unroll
            for (int i = 0; i < 8; i++) {
                ull ad = dup2(aa[i]);
                fma2(acc[i][0], ad, bv.x);
                fma2(acc[i][1], ad, bv.y);
            }
        }
        __syncthreads();
    }

#pragma unroll
    for (int i = 0; i < 8; i++) {
        int n = r0 + i;
        if (n < S) {
            int node = (RG == 1) ? n : (n < 58 ? n : (n < 62 ? 62 + (n - 58) : 61));
            float4 sv = *(const float4*)(Y + (size_t)node * (B * KDIM) + (size_t)b * KDIM
                                           + 3072 + nb + c0);
            float l0, h0, l1, h1;
            unpack2(acc[i][0], l0, h0);
            unpack2(acc[i][1], l1, h1);
            float4 o;
            o.x = fmaxf(l0 + sv.x, 0.f);
            o.y = fmaxf(h0 + sv.y, 0.f);
            o.z = fmaxf(l1 + sv.z, 0.f);
            o.w = fmaxf(h1 + sv.w, 0.f);
            *(float4*)(Z + ((size_t)b * S + n) * HDIM + nb + c0) = o;
        }
    }
}

// ---------------- layer-2 message aggregation (msg-first, few rows) ----------------
__global__ void k_msg(const float* __restrict__ ACm, const float* __restrict__ X,
                      float* __restrict__ F, int nodes, int nRows, int rowBase, int rowStride) {
    int b = blockIdx.y, i = blockIdx.x;
    int row = rowBase + i * rowStride;
    __shared__ __align__(16) ull sA[NQ][64];
    int t = threadIdx.x;
    for (int e = t; e < NQ * nodes; e += 256) {
        int q = e / nodes, m = e % nodes;
        float a = ACm[(((size_t)b * NQ + q) * nodes + row) * nodes + m];
        sA[q][m] = dup2(a);
    }
    __syncthreads();
    ull acc[NQ] = {0ULL, 0ULL, 0ULL, 0ULL, 0ULL, 0ULL};
    const float* xb = X + (size_t)b * nodes * HDIM;
    int h = t * 2;
    for (int m = 0; m < nodes; m++) {
        ull xv = *(const ull*)(xb + (size_t)m * HDIM + h);
#pragma unroll
        for (int q = 0; q < NQ; q++) fma2(acc[q], sA[q][m], xv);
    }
    float* Fp = F + ((size_t)b * nRows + i) * KDIM;
#pragma unroll
    for (int q = 0; q < NQ; q++)
        *(ull*)(Fp + q * HDIM + h) = acc[q];
    *(ull*)(Fp + 3072 + h) = *(const ull*)(xb + (size_t)row * HDIM + h);
}

// ---------------- final logits ----------------
__global__ void k_logits(const float* __restrict__ U, const float* __restrict__ tW,
                         const float* __restrict__ tb, float* __restrict__ out) {
    int b = blockIdx.x;
    int w = threadIdx.x >> 5, lane = threadIdx.x & 31;
    if (w >= 11) return;
    const float* black = U + ((size_t)b * 2 + 1) * HDIM;
    const float* white = U + ((size_t)b * 2 + 0) * HDIM;
    const float* row = tW + w * 1024;
    float s = 0.f;
    for (int j = lane; j < HDIM; j += 32)
        s += black[j] * row[j] + white[j] * row[HDIM + j];
#pragma unroll
    for (int o = 16; o; o >>= 1) s += __shfl_down_sync(0xffffffffu, s, o);
    if (lane == 0) out[b * 11 + w] = s + tb[w];
}

// ---------------- host ----------------
extern "C" void kernel_launch(void* const* d_in, const int* in_sizes, int n_in,
                              void* d_out, int out_size) {
    int s = (n_in >= 21 && in_sizes[1] == 1) ? 1 : 0;

    const int*   player = (const int*)d_in[0];
    const float* enc    = (const float*)d_in[1 + s];
    const int*   adj    = (const int*)d_in[2 + s];
    const float* Ax     = (const float*)d_in[3 + s];
    const float* Ay     = (const float*)d_in[4 + s];
    const float* Bx     = (const float*)d_in[5 + s];
    const float* By     = (const float*)d_in[6 + s];
    const float* emb    = (const float*)d_in[7 + s];
    const float* coordW = (const float*)d_in[8 + s];
    const float* coordB = (const float*)d_in[9 + s];
    const float* inW    = (const float*)d_in[10 + s];
    const float* inB    = (const float*)d_in[11 + s];
    const float* basis0 = (const float*)d_in[12 + s];
    const float* comb0  = (const float*)d_in[13 + s];
    const float* self0  = (const float*)d_in[14 + s];
    const float* basis1 = (const float*)d_in[15 + s];
    const float* comb1  = (const float*)d_in[16 + s];
    const float* self1  = (const float*)d_in[17 + s];
    const float* typeW  = (const float*)d_in[18 + s];
    const float* typeB  = (const float*)d_in[19 + s];

    float* base = nullptr;
    cudaGetSymbolAddress((void**)&base, g_scratch);
    float* CWy  = base;
    float* CW1  = CWy  + 1835008;
    float* INIT = CW1  + 1835008;
    float* XU   = INIT + 262144;
    float* Y    = XU   + 8650752;
    float* Z1   = Y    + 60555264;
    float* Z2   = Z1   + 8126464;
    float* Tb   = Z2   + 8257536;
    float* U    = Tb   + 524288;
    float* AC1c = U    + 262144;
    float* AC1m = AC1c + 5904384;
    float* AC2c = AC1m + 5904384;
    float* AC2m = AC2c + 6096384;
    float* F    = AC2m + 6096384;

    // weights + adjacency + initial embedding
    k_build_cwy<<<(HDIM * KDIM + 255) / 256, 256>>>(basis0, self0, CWy);
    k_build_cw1<<<(KDIM * HDIM + 255) / 256, 256>>>(basis1, self1, CW1);
    k_ac1<<<dim3(B, (S1 * S1 + 255) / 256), 256>>>(adj, comb0, comb1, AC1c, AC1m);
    k_ac2<<<dim3(B, (S2 * S2 + 255) / 256), 256>>>(adj, comb0, comb1, AC2c, AC2m);
    k_initial<<<B, 256>>>(player, Ax, Ay, Bx, By, emb, coordW, coordB, inW, inB, INIT);
    k_xu<<<(62 * B * HDIM) / 256, 256>>>(enc, INIT, XU);

    // Y = XU @ CWy for the 62 shared nodes  (M=15872, K=512, N=3584)
    k_gemm<<<dim3(62 * B / 128, KDIM / 128), 256>>>(XU, CWy, Y, HDIM, HDIM, KDIM, 0);

    // rgcn1 layer1: combine
    k_combine<S1, 1><<<dim3(HDIM / 128, B), 256>>>(AC1c, Y, Z1);
    // rgcn1 layer2 (rows 58..61) -> Tb
    k_msg<<<dim3(4, B), 256>>>(AC1m, Z1, F, S1, 4, 58, 1);
    k_gemm<<<dim3(4 * B / 128, HDIM / 128), 256>>>(F, CW1, Tb, KDIM, KDIM, HDIM, 2);

    // T rows into XU nodes 62..65, then Y for those 4 nodes (M=1024)
    k_copyT<<<(4 * B * HDIM) / 256, 256>>>(Tb, XU);
    k_gemm<<<dim3(4 * B / 128, KDIM / 128), 256>>>(XU + (size_t)62 * B * HDIM, CWy,
                                                   Y + (size_t)62 * B * KDIM,
                                                   HDIM, HDIM, KDIM, 0);

    // rgcn2 layer1: combine
    k_combine<S2, 2><<<dim3(HDIM / 128, B), 256>>>(AC2c, Y, Z2);
    // rgcn2 layer2 (rows 60, 62) -> U
    k_msg<<<dim3(2, B), 256>>>(AC2m, Z2, F, S2, 2, 60, 2);
    k_gemm<<<dim3(2 * B / 128, HDIM / 128), 256>>>(F, CW1, U, KDIM, KDIM, HDIM, 2);

    k_logits<<<B, 352>>>(U, typeW, typeB, (float*)d_out);
}

// round 5
// speedup vs baseline: 2.1637x; 1.2673x over previous
#include <cuda_runtime.h>
#include <cuda_bf16.h>
#include <math.h>
#include <stdint.h>

#define B      256
#define HDIM   512
#define NENC   60
#define S1     62
#define S2     63
#define NQ     6
#define KDIM   3584      // 6*512 + 512
#define KEXT   1536      // split bf16 extended K (hi|hi|lo x hi|lo|hi)

typedef unsigned long long ull;

// ---------------- scratch ----------------
// float offsets:
//  CW1   @0          1,835,008
//  INIT  @1835008      262,144
//  Y     @2097152   60,555,264
//  Z1    @62652416   8,126,464
//  Z2    @70778880   8,257,536
//  Tb    @79036416     524,288
//  U     @79560704     262,144
//  AC1c  @79822848   5,904,384
//  AC1m  @85727232   5,904,384
//  AC2c  @91631616   6,096,384
//  AC2m  @97728000   6,096,384
//  F     @103824384  3,670,016
//  AEXT  @107494400 12,976,128  (bf16: 66*256*1536)
//  BEXT  @120470528  2,752,512  (bf16: 3584*1536)
static __device__ float g_scratch[123223040];

// ---------------- f32x2 helpers ----------------
__device__ __forceinline__ ull dup2(float a) {
    ull d; asm("mov.b64 %0, {%1, %1};" : "=l"(d) : "f"(a)); return d;
}
__device__ __forceinline__ void fma2(ull &acc, ull a, ull b) {
    asm("fma.rn.f32x2 %0, %1, %2, %0;" : "+l"(acc) : "l"(a), "l"(b));
}
__device__ __forceinline__ void unpack2(ull v, float &lo, float &hi) {
    asm("mov.b64 {%0, %1}, %2;" : "=f"(lo), "=f"(hi) : "l"(v));
}

__device__ __forceinline__ uint32_t smem_u32(const void* p) {
    uint32_t a;
    asm("{ .reg .u64 t; cvta.to.shared.u64 t, %1; cvt.u32.u64 %0, t; }" : "=r"(a) : "l"(p));
    return a;
}
__device__ __forceinline__ void cp16(uint32_t s, const void* g) {
    asm volatile("cp.async.cg.shared.global [%0], [%1], 16;" :: "r"(s), "l"(g));
}
#define CP_COMMIT() asm volatile("cp.async.commit_group;" ::: "memory")
#define CP_WAIT(n)  asm volatile("cp.async.wait_group %0;" :: "n"(n) : "memory")

__device__ __forceinline__ void ldsm_x4(uint32_t &r0, uint32_t &r1, uint32_t &r2, uint32_t &r3, uint32_t addr) {
    asm volatile("ldmatrix.sync.aligned.m8n8.x4.shared.b16 {%0,%1,%2,%3}, [%4];"
        : "=r"(r0), "=r"(r1), "=r"(r2), "=r"(r3) : "r"(addr));
}
__device__ __forceinline__ void mma16816(float* d, const uint32_t* a, uint32_t b0, uint32_t b1) {
    asm volatile("mma.sync.aligned.m16n8k16.row.col.f32.bf16.bf16.f32 "
        "{%0,%1,%2,%3}, {%4,%5,%6,%7}, {%8,%9}, {%0,%1,%2,%3};"
        : "+f"(d[0]), "+f"(d[1]), "+f"(d[2]), "+f"(d[3])
        : "r"(a[0]), "r"(a[1]), "r"(a[2]), "r"(a[3]), "r"(b0), "r"(b1));
}

// ---------------- CW1 (layer-2 weight) builder ----------------
__global__ void k_build_cw1(const float* __restrict__ basis, const float* __restrict__ selfW,
                            float* __restrict__ CW) {
    int idx = blockIdx.x * 256 + threadIdx.x;
    if (idx >= KDIM * HDIM) return;
    int row = idx >> 9;
    int k   = idx & 511;
    CW[idx] = (row < 3072) ? basis[idx] : selfW[(size_t)k * HDIM + (row - 3072)];
}

// ---------------- AC builders ----------------
__global__ void k_ac1(const int* __restrict__ adj, const float* __restrict__ comb0,
                      const float* __restrict__ comb1, float* __restrict__ ACc,
                      float* __restrict__ ACm) {
    __shared__ float sc[2][12][6];
    int t = threadIdx.x;
    if (t < 72) { sc[0][t / 6][t % 6] = comb0[t]; sc[1][t / 6][t % 6] = comb1[t]; }
    __syncthreads();
    int b = blockIdx.x;
    int e = blockIdx.y * 256 + t;
    if (e >= S1 * S1) return;
    int n = e / S1, m = e % S1;
    float a[12];
#pragma unroll
    for (int r = 0; r < 12; r++)
        a[r] = (float)adj[(((size_t)b * 13 + r + 1) * S1 + n) * S1 + m];
#pragma unroll
    for (int q = 0; q < NQ; q++) {
        float s0 = 0.f, s1 = 0.f;
#pragma unroll
        for (int r = 0; r < 12; r++) { s0 += sc[0][r][q] * a[r]; s1 += sc[1][r][q] * a[r]; }
        ACc[((size_t)b * S1 + n) * (NQ * S1) + q * S1 + m] = s0;
        ACm[(((size_t)b * NQ + q) * S1 + n) * S1 + m] = s1;
    }
}

__global__ void k_ac2(const int* __restrict__ adj, const float* __restrict__ comb0,
                      const float* __restrict__ comb1, float* __restrict__ ACc,
                      float* __restrict__ ACm) {
    __shared__ float sc[2][12][6];
    int t = threadIdx.x;
    if (t < 72) { sc[0][t / 6][t % 6] = comb0[t]; sc[1][t / 6][t % 6] = comb1[t]; }
    __syncthreads();
    int b = blockIdx.x;
    int e = blockIdx.y * 256 + t;
    if (e >= S2 * S2) return;
    int n = e / S2, m = e % S2;
    int oi = (n == 62) ? 63 : n;
    int oj = (m == 62) ? 63 : m;
    float a[12];
#pragma unroll
    for (int r = 0; r < 12; r++) {
        int v = 0;
        if (oi < 62 && oj < 62)
            v = adj[(((size_t)b * 13 + r + 1) * S1 + oi) * S1 + oj];
        a[r] = (float)v;
    }
    int lo = min(oi, oj), hi = max(oi, oj);
    if (hi - lo == 2) {
        int ni = lo >> 1;
        int ch = ((lo & 1) == 0) ? ((ni & 1) ? 12 : 11) : ((ni & 1) ? 11 : 12);
        a[ch - 1] = 1.f;
    }
#pragma unroll
    for (int q = 0; q < NQ; q++) {
        float s0 = 0.f, s1 = 0.f;
#pragma unroll
        for (int r = 0; r < 12; r++) { s0 += sc[0][r][q] * a[r]; s1 += sc[1][r][q] * a[r]; }
        ACc[((size_t)b * S2 + n) * (NQ * S2) + q * S2 + m] = s0;
        ACm[(((size_t)b * NQ + q) * S2 + n) * S2 + m] = s1;
    }
}

// ---------------- initial node embedding (B,2,512) ----------------
__global__ void k_initial(const int* __restrict__ player,
                          const float* __restrict__ Ax, const float* __restrict__ Ay,
                          const float* __restrict__ Bx, const float* __restrict__ By,
                          const float* __restrict__ emb, const float* __restrict__ cW,
                          const float* __restrict__ cb, const float* __restrict__ inW,
                          const float* __restrict__ inb, float* __restrict__ out) {
    __shared__ float feat[2][64];
    int b = blockIdx.x, t = threadIdx.x;
    if (t < 64) {
        int p = t >> 5, l = t & 31;
        float x = p ? Bx[b] : Ax[b];
        float y = p ? By[b] : Ay[b];
        float v = cW[l * 2] * x + cW[l * 2 + 1] * y + cb[l];
        feat[p][l] = fmaxf(v, 0.f);
    } else if (t < 128) {
        int tt = t - 64;
        int p = tt >> 5, l = tt & 31;
        feat[p][32 + l] = emb[player[b * 2 + p] * 32 + l];
    }
    __syncthreads();
    for (int o = t; o < 1024; o += 256) {
        int p = o >> 9, h = o & 511;
        float s = inb[h];
        const float* w = inW + h * 64;
        const float* f = feat[p];
#pragma unroll
        for (int j = 0; j < 64; j++) s += w[j] * f[j];
        out[((size_t)b * 2 + p) * HDIM + h] = s;
    }
}

// ---------------- A_ext builders (bf16 split: [hi | hi | lo]) ----------------
__global__ void k_aext(const float* __restrict__ enc, const float* __restrict__ init,
                       __nv_bfloat16* __restrict__ A) {
    size_t i = (size_t)blockIdx.x * 256 + threadIdx.x;   // 62*256*512
    if (i >= (size_t)62 * B * HDIM) return;
    int m = (int)(i >> 9);
    int h = (int)(i & 511);
    int node = m >> 8, b = m & 255;
    float x = (node < NENC) ? enc[((size_t)b * NENC + node) * HDIM + h]
                            : init[((size_t)b * 2 + (node - NENC)) * HDIM + h];
    __nv_bfloat16 hi = __float2bfloat16(x);
    float lo = x - __bfloat162float(hi);
    __nv_bfloat16* row = A + (size_t)m * KEXT;
    row[h] = hi;
    row[512 + h] = hi;
    row[1024 + h] = __float2bfloat16(lo);
}

__global__ void k_aextT(const float* __restrict__ Tb, __nv_bfloat16* __restrict__ A) {
    size_t i = (size_t)blockIdx.x * 256 + threadIdx.x;   // 4*256*512
    if (i >= (size_t)4 * B * HDIM) return;
    int m = (int)(i >> 9);
    int h = (int)(i & 511);
    int j = m >> 8, b = m & 255;
    float x = Tb[((size_t)b * 4 + j) * HDIM + h];
    __nv_bfloat16 hi = __float2bfloat16(x);
    float lo = x - __bfloat162float(hi);
    __nv_bfloat16* row = A + (size_t)((62 + j) * B + b) * KEXT;
    row[h] = hi;
    row[512 + h] = hi;
    row[1024 + h] = __float2bfloat16(lo);
}

// ---------------- B_ext builder (bf16 split: [hi | lo | hi]) ----------------
__global__ void k_bext(const float* __restrict__ basis, const float* __restrict__ selfW,
                       __nv_bfloat16* __restrict__ Bm) {
    size_t i = (size_t)blockIdx.x * 256 + threadIdx.x;   // 3584*512
    if (i >= (size_t)KDIM * HDIM) return;
    int n = (int)(i >> 9);
    int k = (int)(i & 511);
    float w;
    if (n < 3072) {
        int q = n >> 9, j = n & 511;
        w = basis[((size_t)q * 512 + k) * 512 + j];
    } else {
        w = selfW[(size_t)(n - 3072) * 512 + k];
    }
    __nv_bfloat16 hi = __float2bfloat16(w);
    float lo = w - __bfloat162float(hi);
    __nv_bfloat16* row = Bm + (size_t)n * KEXT;
    row[k] = hi;
    row[512 + k] = __float2bfloat16(lo);
    row[1024 + k] = hi;
}

// ---------------- mma.sync bf16 GEMM: Y[m][n] = sum_k A[m][k]*B[n][k] ----------------
// CTA 128x128, 8 warps of 32x64, KT=32, 3-stage cp.async pipeline.
#define KT 32
#define STAGES 3
#define ASTRIDE 40                      // bf16 per smem row (32 + 8 pad)
#define STAGE_ELT (128 * ASTRIDE)       // 5120 bf16 per stage per operand
#define STAGE_BYTES (STAGE_ELT * 2)

__global__ __launch_bounds__(256, 2)
void k_mma(const __nv_bfloat16* __restrict__ A, const __nv_bfloat16* __restrict__ Bm,
           float* __restrict__ C, int Mbase) {
    extern __shared__ __align__(16) __nv_bfloat16 sm[];
    int tid = threadIdx.x;
    int wid = tid >> 5, lane = tid & 31;
    int m0 = Mbase + blockIdx.x * 128;
    int n0 = blockIdx.y * 128;
    int wm = (wid & 3) * 32;    // warp m offset in tile
    int wn = (wid >> 2) * 64;   // warp n offset in tile

    uint32_t sA0 = smem_u32(sm);
    uint32_t sB0 = sA0 + STAGES * STAGE_BYTES;

    const __nv_bfloat16* Ag = A + (size_t)m0 * KEXT;
    const __nv_bfloat16* Bg = Bm + (size_t)n0 * KEXT;

    // load coords: 512 16B-chunks per operand per stage; 2 per thread
    int r0l = (tid + 0) >> 2,   c0l = (tid + 0) & 3;
    int r1l = (tid + 256) >> 2, c1l = (tid + 256) & 3;

    float acc[2][8][4];
#pragma unroll
    for (int i = 0; i < 2; i++)
#pragma unroll
        for (int j = 0; j < 8; j++)
#pragma unroll
            for (int k = 0; k < 4; k++) acc[i][j][k] = 0.f;

    // prologue: stages 0..STAGES-2
#pragma unroll
    for (int s = 0; s < STAGES - 1; s++) {
        int kt = s * KT;
        cp16(sA0 + s * STAGE_BYTES + (r0l * ASTRIDE + c0l * 8) * 2, Ag + (size_t)r0l * KEXT + kt + c0l * 8);
        cp16(sA0 + s * STAGE_BYTES + (r1l * ASTRIDE + c1l * 8) * 2, Ag + (size_t)r1l * KEXT + kt + c1l * 8);
        cp16(sB0 + s * STAGE_BYTES + (r0l * ASTRIDE + c0l * 8) * 2, Bg + (size_t)r0l * KEXT + kt + c0l * 8);
        cp16(sB0 + s * STAGE_BYTES + (r1l * ASTRIDE + c1l * 8) * 2, Bg + (size_t)r1l * KEXT + kt + c1l * 8);
        CP_COMMIT();
    }

    // ldmatrix lane address components
    int a_row = wm + (lane & 15);
    int a_koff = (lane >> 4) * 8;
    int b_row = wn + ((lane >> 4) * 8) + (lane & 7);
    int b_koff = ((lane >> 3) & 1) * 8;

    const int KITER = KEXT / KT;   // 48
    for (int it = 0; it < KITER; it++) {
        int s = it % STAGES;
        CP_WAIT(STAGES - 2);
        __syncthreads();

        uint32_t aBase = sA0 + s * STAGE_BYTES;
        uint32_t bBase = sB0 + s * STAGE_BYTES;
#pragma unroll
        for (int kk = 0; kk < 2; kk++) {
            uint32_t af[2][4];
#pragma unroll
            for (int mt = 0; mt < 2; mt++) {
                uint32_t addr = aBase + ((a_row + mt * 16) * ASTRIDE + kk * 16 + a_koff) * 2;
                ldsm_x4(af[mt][0], af[mt][1], af[mt][2], af[mt][3], addr);
            }
#pragma unroll
            for (int np = 0; np < 4; np++) {
                uint32_t b0, b1, b2, b3;
                uint32_t addr = bBase + ((b_row + np * 16) * ASTRIDE + kk * 16 + b_koff) * 2;
                ldsm_x4(b0, b1, b2, b3, addr);
#pragma unroll
                for (int mt = 0; mt < 2; mt++) {
                    mma16816(acc[mt][np * 2],     af[mt], b0, b1);
                    mma16816(acc[mt][np * 2 + 1], af[mt], b2, b3);
                }
            }
        }
        __syncthreads();

        int nit = it + STAGES - 1;
        if (nit < KITER) {
            int ns = nit % STAGES;
            int kt = nit * KT;
            cp16(sA0 + ns * STAGE_BYTES + (r0l * ASTRIDE + c0l * 8) * 2, Ag + (size_t)r0l * KEXT + kt + c0l * 8);
            cp16(sA0 + ns * STAGE_BYTES + (r1l * ASTRIDE + c1l * 8) * 2, Ag + (size_t)r1l * KEXT + kt + c1l * 8);
            cp16(sB0 + ns * STAGE_BYTES + (r0l * ASTRIDE + c0l * 8) * 2, Bg + (size_t)r0l * KEXT + kt + c0l * 8);
            cp16(sB0 + ns * STAGE_BYTES + (r1l * ASTRIDE + c1l * 8) * 2, Bg + (size_t)r1l * KEXT + kt + c1l * 8);
        }
        CP_COMMIT();
    }

    // epilogue
    int crow = m0 + wm + (lane >> 2);
    int ccol = n0 + wn + (lane & 3) * 2;
#pragma unroll
    for (int mt = 0; mt < 2; mt++) {
#pragma unroll
        for (int nt = 0; nt < 8; nt++) {
            float2 v01; v01.x = acc[mt][nt][0]; v01.y = acc[mt][nt][1];
            float2 v23; v23.x = acc[mt][nt][2]; v23.y = acc[mt][nt][3];
            int row = crow + mt * 16;
            int col = ccol + nt * 8;
            *(float2*)(C + (size_t)row * KDIM + col) = v01;
            *(float2*)(C + (size_t)(row + 8) * KDIM + col) = v23;
        }
    }
}

// ---------------- combine: Z[b,n,:] = relu( sum_q AC_q[b,n,:] @ Y_q[b] + Y_self[b,n,:] ) ----------
template<int S, int RG>
__global__ __launch_bounds__(256)
void k_combine(const float* __restrict__ ACc, const float* __restrict__ Y,
               float* __restrict__ Z) {
    const int K = 6 * S;
    __shared__ __align__(16) float As[8][64];
    __shared__ __align__(16) float Bs[8][128];
    __shared__ int boff[6 * 63];
    int t = threadIdx.x;
    int b = blockIdx.y;
    int nb = blockIdx.x * 128;

    for (int k = t; k < K; k += 256) {
        int q = k / S, m = k - q * S;
        int node = (RG == 1) ? m : (m < 58 ? m : (m < 62 ? 62 + (m - 58) : 61));
        boff[k] = node * (B * KDIM) + q * HDIM;
    }
    __syncthreads();

    int ty = t >> 5, tx = t & 31;
    int r0 = ty * 8, c0 = tx * 4;
    ull acc[8][2];
#pragma unroll
    for (int i = 0; i < 8; i++) { acc[i][0] = 0ULL; acc[i][1] = 0ULL; }

    const float* Yb = Y + (size_t)b * KDIM + nb;
    const float* Ab = ACc + (size_t)b * S * K;

    for (int kt = 0; kt < K; kt += 8) {
        int e = t;
#pragma unroll
        for (int rep = 0; rep < 2; rep++, e += 256) {
            int kk = e & 7, n = e >> 3;
            int k = kt + kk;
            float v = 0.f;
            if (n < S && k < K) v = Ab[(size_t)n * K + k];
            As[kk][n] = v;
        }
        {
            int kk = t >> 5, c4 = (t & 31) * 4;
            int k = kt + kk;
            float4 v = {0.f, 0.f, 0.f, 0.f};
            if (k < K) v = *(const float4*)(Yb + boff[k] + c4);
            *(float4*)&Bs[kk][c4] = v;
        }
        __syncthreads();
#pragma unroll
        for (int kk = 0; kk < 8; kk++) {
            float4 a0 = *(const float4*)&As[kk][r0];
            float4 a1 = *(const float4*)&As[kk][r0 + 4];
            ulonglong2 bv = *(const ulonglong2*)&Bs[kk][c0];
            float aa[8] = {a0.x, a0.y, a0.z, a0.w, a1.x, a1.y, a1.z, a1.w};
#pragma unroll
            for (int i = 0; i < 8; i++) {
                ull ad = dup2(aa[i]);
                fma2(acc[i][0], ad, bv.x);
                fma2(acc[i][1], ad, bv.y);
            }
        }
        __syncthreads();
    }

#pragma unroll
    for (int i = 0; i < 8; i++) {
        int n = r0 + i;
        if (n < S) {
            int node = (RG == 1) ? n : (n < 58 ? n : (n < 62 ? 62 + (n - 58) : 61));
            float4 sv = *(const float4*)(Y + (size_t)node * (B * KDIM) + (size_t)b * KDIM
                                           + 3072 + nb + c0);
            float l0, h0, l1, h1;
            unpack2(acc[i][0], l0, h0);
            unpack2(acc[i][1], l1, h1);
            float4 o;
            o.x = fmaxf(l0 + sv.x, 0.f);
            o.y = fmaxf(h0 + sv.y, 0.f);
            o.z = fmaxf(l1 + sv.z, 0.f);
            o.w = fmaxf(h1 + sv.w, 0.f);
            *(float4*)(Z + ((size_t)b * S + n) * HDIM + nb + c0) = o;
        }
    }
}

// ---------------- layer-2 message aggregation ----------------
__global__ void k_msg(const float* __restrict__ ACm, const float* __restrict__ X,
                      float* __restrict__ F, int nodes, int nRows, int rowBase, int rowStride) {
    int b = blockIdx.y, i = blockIdx.x;
    int row = rowBase + i * rowStride;
    __shared__ __align__(16) ull sA[NQ][64];
    int t = threadIdx.x;
    for (int e = t; e < NQ * nodes; e += 256) {
        int q = e / nodes, m = e % nodes;
        float a = ACm[(((size_t)b * NQ + q) * nodes + row) * nodes + m];
        sA[q][m] = dup2(a);
    }
    __syncthreads();
    ull acc[NQ] = {0ULL, 0ULL, 0ULL, 0ULL, 0ULL, 0ULL};
    const float* xb = X + (size_t)b * nodes * HDIM;
    int h = t * 2;
    for (int m = 0; m < nodes; m++) {
        ull xv = *(const ull*)(xb + (size_t)m * HDIM + h);
#pragma unroll
        for (int q = 0; q < NQ; q++) fma2(acc[q], sA[q][m], xv);
    }
    float* Fp = F + ((size_t)b * nRows + i) * KDIM;
#pragma unroll
    for (int q = 0; q < NQ; q++)
        *(ull*)(Fp + q * HDIM + h) = acc[q];
    *(ull*)(Fp + 3072 + h) = *(const ull*)(xb + (size_t)row * HDIM + h);
}

// ---------------- fp32 SGEMM (layer-2, small M): C = sigmoid(A[M,K] @ Bw[K,ldn]) ----------------
__global__ __launch_bounds__(256, 2)
void k_gemm(const float* __restrict__ A, const float* __restrict__ Bw,
            float* __restrict__ C, int K, int lda, int ldn, int act) {
    __shared__ __align__(16) float As[8][128];
    __shared__ __align__(16) float Bs[8][128];
    int tid = threadIdx.x;
    int brow = blockIdx.x, bcol = blockIdx.y;

    int arow = tid >> 1;
    int ak   = (tid & 1) * 4;
    int bk   = tid >> 5;
    int bc4  = (tid & 31) * 4;
    const float* Aptr = A + (size_t)(brow * 128 + arow) * lda + ak;
    const float* Bptr = Bw + (size_t)bk * ldn + bcol * 128 + bc4;

    int tx = tid & 15, ty = tid >> 4;
    int r0  = ty * 8;
    int c0a = tx * 4;
    int c0b = 64 + tx * 4;

    ull acc[8][4];
#pragma unroll
    for (int i = 0; i < 8; i++)
#pragma unroll
        for (int j = 0; j < 4; j++) acc[i][j] = 0ULL;

    for (int kt = 0; kt < K; kt += 8) {
        float4 av = *(const float4*)(Aptr + kt);
        float4 bv = *(const float4*)(Bptr + (size_t)kt * ldn);
        As[ak + 0][arow] = av.x;
        As[ak + 1][arow] = av.y;
        As[ak + 2][arow] = av.z;
        As[ak + 3][arow] = av.w;
        *(float4*)&Bs[bk][bc4] = bv;
        __syncthreads();
#pragma unroll
        for (int k = 0; k < 8; k++) {
            float4 a0 = *(const float4*)&As[k][r0];
            float4 a1 = *(const float4*)&As[k][r0 + 4];
            ulonglong2 bA = *(const ulonglong2*)&Bs[k][c0a];
            ulonglong2 bB = *(const ulonglong2*)&Bs[k][c0b];
            ull b2[4] = {bA.x, bA.y, bB.x, bB.y};
            float aarr[8] = {a0.x, a0.y, a0.z, a0.w, a1.x, a1.y, a1.z, a1.w};
#pragma unroll
            for (int i = 0; i < 8; i++) {
                ull ad = dup2(aarr[i]);
#pragma unroll
                for (int j = 0; j < 4; j++) fma2(acc[i][j], ad, b2[j]);
            }
        }
        __syncthreads();
    }

    int colbase = bcol * 128;
#pragma unroll
    for (int i = 0; i < 8; i++) {
        float* Cp = C + (size_t)(brow * 128 + r0 + i) * ldn + colbase;
#pragma unroll
        for (int j = 0; j < 4; j++) {
            float lo, hi;
            unpack2(acc[i][j], lo, hi);
            if (act == 2) {
                lo = 1.f / (1.f + expf(-lo));
                hi = 1.f / (1.f + expf(-hi));
            }
            int c = (j < 2) ? (c0a + 2 * j) : (c0b + 2 * (j - 2));
            float2 w2; w2.x = lo; w2.y = hi;
            *(float2*)(Cp + c) = w2;
        }
    }
}

// ---------------- final logits ----------------
__global__ void k_logits(const float* __restrict__ U, const float* __restrict__ tW,
                         const float* __restrict__ tb, float* __restrict__ out) {
    int b = blockIdx.x;
    int w = threadIdx.x >> 5, lane = threadIdx.x & 31;
    if (w >= 11) return;
    const float* black = U + ((size_t)b * 2 + 1) * HDIM;
    const float* white = U + ((size_t)b * 2 + 0) * HDIM;
    const float* row = tW + w * 1024;
    float s = 0.f;
    for (int j = lane; j < HDIM; j += 32)
        s += black[j] * row[j] + white[j] * row[HDIM + j];
#pragma unroll
    for (int o = 16; o; o >>= 1) s += __shfl_down_sync(0xffffffffu, s, o);
    if (lane == 0) out[b * 11 + w] = s + tb[w];
}

// ---------------- host ----------------
extern "C" void kernel_launch(void* const* d_in, const int* in_sizes, int n_in,
                              void* d_out, int out_size) {
    int s = (n_in >= 21 && in_sizes[1] == 1) ? 1 : 0;

    const int*   player = (const int*)d_in[0];
    const float* enc    = (const float*)d_in[1 + s];
    const int*   adj    = (const int*)d_in[2 + s];
    const float* Ax     = (const float*)d_in[3 + s];
    const float* Ay     = (const float*)d_in[4 + s];
    const float* Bx     = (const float*)d_in[5 + s];
    const float* By     = (const float*)d_in[6 + s];
    const float* emb    = (const float*)d_in[7 + s];
    const float* coordW = (const float*)d_in[8 + s];
    const float* coordB = (const float*)d_in[9 + s];
    const float* inW    = (const float*)d_in[10 + s];
    const float* inB    = (const float*)d_in[11 + s];
    const float* basis0 = (const float*)d_in[12 + s];
    const float* comb0  = (const float*)d_in[13 + s];
    const float* self0  = (const float*)d_in[14 + s];
    const float* basis1 = (const float*)d_in[15 + s];
    const float* comb1  = (const float*)d_in[16 + s];
    const float* self1  = (const float*)d_in[17 + s];
    const float* typeW  = (const float*)d_in[18 + s];
    const float* typeB  = (const float*)d_in[19 + s];

    float* base = nullptr;
    cudaGetSymbolAddress((void**)&base, g_scratch);
    float* CW1  = base;
    float* INIT = base + 1835008;
    float* Y    = base + 2097152;
    float* Z1   = base + 62652416;
    float* Z2   = base + 70778880;
    float* Tb   = base + 79036416;
    float* U    = base + 79560704;
    float* AC1c = base + 79822848;
    float* AC1m = base + 85727232;
    float* AC2c = base + 91631616;
    float* AC2m = base + 97728000;
    float* F    = base + 103824384;
    __nv_bfloat16* AEXT = (__nv_bfloat16*)(base + 107494400);
    __nv_bfloat16* BEXT = (__nv_bfloat16*)(base + 120470528);

    const int mma_smem = 2 * STAGES * STAGE_BYTES;   // 61440
    cudaFuncSetAttribute(k_mma, cudaFuncAttributeMaxDynamicSharedMemorySize, mma_smem);

    k_build_cw1<<<(KDIM * HDIM + 255) / 256, 256>>>(basis1, self1, CW1);
    k_ac1<<<dim3(B, (S1 * S1 + 255) / 256), 256>>>(adj, comb0, comb1, AC1c, AC1m);
    k_ac2<<<dim3(B, (S2 * S2 + 255) / 256), 256>>>(adj, comb0, comb1, AC2c, AC2m);
    k_initial<<<B, 256>>>(player, Ax, Ay, Bx, By, emb, coordW, coordB, inW, inB, INIT);
    k_aext<<<(62 * B * HDIM + 255) / 256, 256>>>(enc, INIT, AEXT);
    k_bext<<<(KDIM * HDIM + 255) / 256, 256>>>(basis0, self0, BEXT);

    // Y = A_ext @ B_ext^T for the 62 shared nodes (mma.sync bf16-split)
    k_mma<<<dim3(62 * B / 128, KDIM / 128), 256, mma_smem>>>(AEXT, BEXT, Y, 0);

    // rgcn1 layer1: combine
    k_combine<S1, 1><<<dim3(HDIM / 128, B), 256>>>(AC1c, Y, Z1);
    // rgcn1 layer2 (rows 58..61) -> Tb (sigmoid)
    k_msg<<<dim3(4, B), 256>>>(AC1m, Z1, F, S1, 4, 58, 1);
    k_gemm<<<dim3(4 * B / 128, HDIM / 128), 256>>>(F, CW1, Tb, KDIM, KDIM, HDIM, 2);

    // T nodes -> A_ext rows 62..65, then their Y projection
    k_aextT<<<(4 * B * HDIM + 255) / 256, 256>>>(Tb, AEXT);
    k_mma<<<dim3(4 * B / 128, KDIM / 128), 256, mma_smem>>>(AEXT, BEXT, Y, 62 * B);

    // rgcn2 layer1: combine
    k_combine<S2, 2><<<dim3(HDIM / 128, B), 256>>>(AC2c, Y, Z2);
    // rgcn2 layer2 (rows 60, 62) -> U (sigmoid)
    k_msg<<<dim3(2, B), 256>>>(AC2m, Z2, F, S2, 2, 60, 2);
    k_gemm<<<dim3(2 * B / 128, HDIM / 128), 256>>>(F, CW1, U, KDIM, KDIM, HDIM, 2);

    k_logits<<<B, 352>>>(U, typeW, typeB, (float*)d_out);
}

// round 6
// speedup vs baseline: 3.5823x; 1.6556x over previous
#include <cuda_runtime.h>
#include <cuda_bf16.h>
#include <math.h>
#include <stdint.h>

#define B      256
#define HDIM   512
#define NENC   60
#define S1     62
#define S2     63
#define NQ     6
#define KDIM   3584      // 6*512 + 512
#define KEXT   1536      // Y-GEMM split K (hi|hi|lo x hi|lo|hi)

typedef unsigned long long ull;

// ---------------- scratch (float offsets) ----------------
//  CW1   @0            1,835,008
//  INIT  @1,835,008      262,144
//  FEAT  @2,097,152       32,768
//  Y     @2,129,920   60,555,264
//  Z1    @62,685,184   8,126,464
//  Z2    @70,811,648   8,257,536
//  Tb    @79,069,184     524,288
//  U     @79,593,472     262,144
//  AC1m  @79,855,616   5,904,384
//  AC2m  @85,760,000   6,096,384
//  F     @91,856,384   3,670,016
//  AEXT  @95,526,400  12,976,128 (bf16 66*256*1536)
//  BEXT  @108,502,528  2,752,512 (bf16 3584*1536)
//  YH    @111,255,040 25,952,256 (bf16 66*256*3072)
//  YL    @137,207,296 25,952,256
//  A1E   @163,159,552  9,175,040 (bf16 256*64*1120)
//  A2E   @172,334,592  9,437,184 (bf16 256*64*1152)
static __device__ float g_scratch[181771776];

// ---------------- helpers ----------------
__device__ __forceinline__ ull dup2(float a) {
    ull d; asm("mov.b64 %0, {%1, %1};" : "=l"(d) : "f"(a)); return d;
}
__device__ __forceinline__ void fma2(ull &acc, ull a, ull b) {
    asm("fma.rn.f32x2 %0, %1, %2, %0;" : "+l"(acc) : "l"(a), "l"(b));
}
__device__ __forceinline__ void unpack2(ull v, float &lo, float &hi) {
    asm("mov.b64 {%0, %1}, %2;" : "=f"(lo), "=f"(hi) : "l"(v));
}
__device__ __forceinline__ uint32_t smem_u32(const void* p) {
    uint32_t a;
    asm("{ .reg .u64 t; cvta.to.shared.u64 t, %1; cvt.u32.u64 %0, t; }" : "=r"(a) : "l"(p));
    return a;
}
__device__ __forceinline__ void cp16(uint32_t s, const void* g) {
    asm volatile("cp.async.cg.shared.global [%0], [%1], 16;" :: "r"(s), "l"(g));
}
#define CP_COMMIT() asm volatile("cp.async.commit_group;" ::: "memory")
#define CP_WAIT(n)  asm volatile("cp.async.wait_group %0;" :: "n"(n) : "memory")

__device__ __forceinline__ void ldsm_x4(uint32_t &r0, uint32_t &r1, uint32_t &r2, uint32_t &r3, uint32_t addr) {
    asm volatile("ldmatrix.sync.aligned.m8n8.x4.shared.b16 {%0,%1,%2,%3}, [%4];"
        : "=r"(r0), "=r"(r1), "=r"(r2), "=r"(r3) : "r"(addr));
}
__device__ __forceinline__ void ldsm_x4_t(uint32_t &r0, uint32_t &r1, uint32_t &r2, uint32_t &r3, uint32_t addr) {
    asm volatile("ldmatrix.sync.aligned.m8n8.x4.trans.shared.b16 {%0,%1,%2,%3}, [%4];"
        : "=r"(r0), "=r"(r1), "=r"(r2), "=r"(r3) : "r"(addr));
}
__device__ __forceinline__ void mma16816(float* d, const uint32_t* a, uint32_t b0, uint32_t b1) {
    asm volatile("mma.sync.aligned.m16n8k16.row.col.f32.bf16.bf16.f32 "
        "{%0,%1,%2,%3}, {%4,%5,%6,%7}, {%8,%9}, {%0,%1,%2,%3};"
        : "+f"(d[0]), "+f"(d[1]), "+f"(d[2]), "+f"(d[3])
        : "r"(a[0]), "r"(a[1]), "r"(a[2]), "r"(a[3]), "r"(b0), "r"(b1));
}

// ---------------- CW1 (layer-2 weight, fp32 [K][N]) ----------------
__global__ void k_build_cw1(const float* __restrict__ basis, const float* __restrict__ selfW,
                            float* __restrict__ CW) {
    int idx = blockIdx.x * 256 + threadIdx.x;
    if (idx >= KDIM * HDIM) return;
    int row = idx >> 9;
    int k   = idx & 511;
    CW[idx] = (row < 3072) ? basis[idx] : selfW[(size_t)k * HDIM + (row - 3072)];
}

// ---------------- AC builders: bf16 split combine operand + fp32 msg layout ----------------
__global__ void k_ac1(const int* __restrict__ adj, const float* __restrict__ comb0,
                      const float* __restrict__ comb1, __nv_bfloat16* __restrict__ AE,
                      float* __restrict__ ACm) {
    __shared__ float sc[2][12][6];
    int t = threadIdx.x;
    if (t < 72) { sc[0][t / 6][t % 6] = comb0[t]; sc[1][t / 6][t % 6] = comb1[t]; }
    __syncthreads();
    int b = blockIdx.x;
    int e = blockIdx.y * 256 + t;
    if (e >= 64 * S1) return;
    int n = e / S1, m = e % S1;
    __nv_bfloat16* rowA = AE + ((size_t)b * 64 + n) * 1120;
    if (m < 4) rowA[1116 + m] = __float2bfloat16(0.f);
    bool valid = (n < S1);
    float a[12];
#pragma unroll
    for (int r = 0; r < 12; r++)
        a[r] = valid ? (float)adj[(((size_t)b * 13 + r + 1) * S1 + n) * S1 + m] : 0.f;
#pragma unroll
    for (int q = 0; q < NQ; q++) {
        float s0 = 0.f, s1 = 0.f;
#pragma unroll
        for (int r = 0; r < 12; r++) { s0 += sc[0][r][q] * a[r]; s1 += sc[1][r][q] * a[r]; }
        __nv_bfloat16 hi = __float2bfloat16(s0);
        float lo = s0 - __bfloat162float(hi);
        int c = q * S1 + m;
        rowA[c] = hi;
        rowA[372 + c] = hi;
        rowA[744 + c] = __float2bfloat16(lo);
        if (valid)
            ACm[(((size_t)b * NQ + q) * S1 + n) * S1 + m] = s1;
    }
}

__global__ void k_ac2(const int* __restrict__ adj, const float* __restrict__ comb0,
                      const float* __restrict__ comb1, __nv_bfloat16* __restrict__ AE,
                      float* __restrict__ ACm) {
    __shared__ float sc[2][12][6];
    int t = threadIdx.x;
    if (t < 72) { sc[0][t / 6][t % 6] = comb0[t]; sc[1][t / 6][t % 6] = comb1[t]; }
    __syncthreads();
    int b = blockIdx.x;
    int e = blockIdx.y * 256 + t;
    if (e >= 64 * S2) return;
    int n = e / S2, m = e % S2;
    __nv_bfloat16* rowA = AE + ((size_t)b * 64 + n) * 1152;
    if (m < 18) rowA[1134 + m] = __float2bfloat16(0.f);
    bool valid = (n < S2);
    int oi = (n == 62) ? 63 : n;
    int oj = (m == 62) ? 63 : m;
    float a[12];
#pragma unroll
    for (int r = 0; r < 12; r++) {
        int v = 0;
        if (valid && oi < 62 && oj < 62)
            v = adj[(((size_t)b * 13 + r + 1) * S1 + oi) * S1 + oj];
        a[r] = (float)v;
    }
    if (valid) {
        int lo2 = min(oi, oj), hi2 = max(oi, oj);
        if (hi2 - lo2 == 2) {
            int ni = lo2 >> 1;
            int ch = ((lo2 & 1) == 0) ? ((ni & 1) ? 12 : 11) : ((ni & 1) ? 11 : 12);
            a[ch - 1] = 1.f;
        }
    }
#pragma unroll
    for (int q = 0; q < NQ; q++) {
        float s0 = 0.f, s1 = 0.f;
#pragma unroll
        for (int r = 0; r < 12; r++) { s0 += sc[0][r][q] * a[r]; s1 += sc[1][r][q] * a[r]; }
        __nv_bfloat16 hi = __float2bfloat16(s0);
        float lo = s0 - __bfloat162float(hi);
        int c = q * S2 + m;
        rowA[c] = hi;
        rowA[378 + c] = hi;
        rowA[756 + c] = __float2bfloat16(lo);
        if (valid)
            ACm[(((size_t)b * NQ + q) * S2 + n) * S2 + m] = s1;
    }
}

// ---------------- initial embedding, two-stage ----------------
__global__ void k_feat(const int* __restrict__ player,
                       const float* __restrict__ Ax, const float* __restrict__ Ay,
                       const float* __restrict__ Bx, const float* __restrict__ By,
                       const float* __restrict__ emb, const float* __restrict__ cW,
                       const float* __restrict__ cb, float* __restrict__ feat) {
    int i = blockIdx.x * 256 + threadIdx.x;
    if (i >= 512 * 64) return;
    int m = i >> 6, l = i & 63;
    int b = m >> 1, p = m & 1;
    float v;
    if (l < 32) {
        float x = p ? Bx[b] : Ax[b];
        float y = p ? By[b] : Ay[b];
        v = fmaxf(cW[l * 2] * x + cW[l * 2 + 1] * y + cb[l], 0.f);
    } else {
        v = emb[player[b * 2 + p] * 32 + (l - 32)];
    }
    feat[m * 64 + l] = v;
}

__global__ __launch_bounds__(256)
void k_init2(const float* __restrict__ feat, const float* __restrict__ inW,
             const float* __restrict__ inb, float* __restrict__ INIT) {
    __shared__ __align__(16) float As[64][65];
    __shared__ __align__(16) float Bs[64][65];
    int t = threadIdx.x;
    int mb = blockIdx.x * 64, hb = blockIdx.y * 64;
#pragma unroll
    for (int j = 0; j < 16; j++) {
        int i = t + j * 256;
        int r = i >> 6, c = i & 63;
        As[r][c] = feat[(mb + r) * 64 + c];
        Bs[r][c] = inW[(hb + r) * 64 + c];
    }
    __syncthreads();
    int tx = t & 15, ty = t >> 4;
    int r0 = ty * 4, c0 = tx * 4;
    float acc[4][4] = {};
    for (int k = 0; k < 64; k++) {
        float av[4], bv[4];
#pragma unroll
        for (int i = 0; i < 4; i++) av[i] = As[r0 + i][k];
#pragma unroll
        for (int j = 0; j < 4; j++) bv[j] = Bs[c0 + j][k];
#pragma unroll
        for (int i = 0; i < 4; i++)
#pragma unroll
            for (int j = 0; j < 4; j++) acc[i][j] += av[i] * bv[j];
    }
#pragma unroll
    for (int i = 0; i < 4; i++)
#pragma unroll
        for (int j = 0; j < 4; j++)
            INIT[(size_t)(mb + r0 + i) * 512 + hb + c0 + j] = acc[i][j] + inb[hb + c0 + j];
}

// ---------------- A_ext builders (bf16 split [hi|hi|lo]) ----------------
__global__ void k_aext(const float* __restrict__ enc, const float* __restrict__ init,
                       __nv_bfloat16* __restrict__ A) {
    size_t i = (size_t)blockIdx.x * 256 + threadIdx.x;
    if (i >= (size_t)62 * B * HDIM) return;
    int m = (int)(i >> 9);
    int h = (int)(i & 511);
    int node = m >> 8, b = m & 255;
    float x = (node < NENC) ? enc[((size_t)b * NENC + node) * HDIM + h]
                            : init[((size_t)b * 2 + (node - NENC)) * HDIM + h];
    __nv_bfloat16 hi = __float2bfloat16(x);
    float lo = x - __bfloat162float(hi);
    __nv_bfloat16* row = A + (size_t)m * KEXT;
    row[h] = hi;
    row[512 + h] = hi;
    row[1024 + h] = __float2bfloat16(lo);
}

__global__ void k_aextT(const float* __restrict__ Tb, __nv_bfloat16* __restrict__ A) {
    size_t i = (size_t)blockIdx.x * 256 + threadIdx.x;
    if (i >= (size_t)4 * B * HDIM) return;
    int m = (int)(i >> 9);
    int h = (int)(i & 511);
    int j = m >> 8, b = m & 255;
    float x = Tb[((size_t)b * 4 + j) * HDIM + h];
    __nv_bfloat16 hi = __float2bfloat16(x);
    float lo = x - __bfloat162float(hi);
    __nv_bfloat16* row = A + (size_t)((62 + j) * B + b) * KEXT;
    row[h] = hi;
    row[512 + h] = hi;
    row[1024 + h] = __float2bfloat16(lo);
}

// ---------------- B_ext builder (bf16 split [hi|lo|hi]) ----------------
__global__ void k_bext(const float* __restrict__ basis, const float* __restrict__ selfW,
                       __nv_bfloat16* __restrict__ Bm) {
    size_t i = (size_t)blockIdx.x * 256 + threadIdx.x;
    if (i >= (size_t)KDIM * HDIM) return;
    int n = (int)(i >> 9);
    int k = (int)(i & 511);
    float w;
    if (n < 3072) {
        int q = n >> 9, j = n & 511;
        w = basis[((size_t)q * 512 + k) * 512 + j];
    } else {
        w = selfW[(size_t)(n - 3072) * 512 + k];
    }
    __nv_bfloat16 hi = __float2bfloat16(w);
    float lo = w - __bfloat162float(hi);
    __nv_bfloat16* row = Bm + (size_t)n * KEXT;
    row[k] = hi;
    row[512 + k] = __float2bfloat16(lo);
    row[1024 + k] = hi;
}

// ---------------- Y-GEMM mma.sync: also emits YH/YL bf16 for q-part ----------------
#define KT 32
#define STAGES 3
#define ASTRIDE 40
#define STAGE_ELT (128 * ASTRIDE)
#define STAGE_BYTES (STAGE_ELT * 2)

__global__ __launch_bounds__(256, 2)
void k_mma(const __nv_bfloat16* __restrict__ A, const __nv_bfloat16* __restrict__ Bm,
           float* __restrict__ C, __nv_bfloat16* __restrict__ YHp,
           __nv_bfloat16* __restrict__ YLp, int Mbase) {
    extern __shared__ __align__(16) __nv_bfloat16 sm[];
    int tid = threadIdx.x;
    int wid = tid >> 5, lane = tid & 31;
    int m0 = Mbase + blockIdx.x * 128;
    int n0 = blockIdx.y * 128;
    int wm = (wid & 3) * 32;
    int wn = (wid >> 2) * 64;

    uint32_t sA0 = smem_u32(sm);
    uint32_t sB0 = sA0 + STAGES * STAGE_BYTES;

    const __nv_bfloat16* Ag = A + (size_t)m0 * KEXT;
    const __nv_bfloat16* Bg = Bm + (size_t)n0 * KEXT;

    int r0l = (tid + 0) >> 2,   c0l = (tid + 0) & 3;
    int r1l = (tid + 256) >> 2, c1l = (tid + 256) & 3;

    float acc[2][8][4];
#pragma unroll
    for (int i = 0; i < 2; i++)
#pragma unroll
        for (int j = 0; j < 8; j++)
#pragma unroll
            for (int k = 0; k < 4; k++) acc[i][j][k] = 0.f;

#pragma unroll
    for (int s = 0; s < STAGES - 1; s++) {
        int kt = s * KT;
        cp16(sA0 + s * STAGE_BYTES + (r0l * ASTRIDE + c0l * 8) * 2, Ag + (size_t)r0l * KEXT + kt + c0l * 8);
        cp16(sA0 + s * STAGE_BYTES + (r1l * ASTRIDE + c1l * 8) * 2, Ag + (size_t)r1l * KEXT + kt + c1l * 8);
        cp16(sB0 + s * STAGE_BYTES + (r0l * ASTRIDE + c0l * 8) * 2, Bg + (size_t)r0l * KEXT + kt + c0l * 8);
        cp16(sB0 + s * STAGE_BYTES + (r1l * ASTRIDE + c1l * 8) * 2, Bg + (size_t)r1l * KEXT + kt + c1l * 8);
        CP_COMMIT();
    }

    int a_row = wm + (lane & 15);
    int a_koff = (lane >> 4) * 8;
    int b_row = wn + ((lane >> 4) * 8) + (lane & 7);
    int b_koff = ((lane >> 3) & 1) * 8;

    const int KITER = KEXT / KT;
    for (int it = 0; it < KITER; it++) {
        int s = it % STAGES;
        CP_WAIT(STAGES - 2);
        __syncthreads();

        uint32_t aBase = sA0 + s * STAGE_BYTES;
        uint32_t bBase = sB0 + s * STAGE_BYTES;
#pragma unroll
        for (int kk = 0; kk < 2; kk++) {
            uint32_t af[2][4];
#pragma unroll
            for (int mt = 0; mt < 2; mt++) {
                uint32_t addr = aBase + ((a_row + mt * 16) * ASTRIDE + kk * 16 + a_koff) * 2;
                ldsm_x4(af[mt][0], af[mt][1], af[mt][2], af[mt][3], addr);
            }
#pragma unroll
            for (int np = 0; np < 4; np++) {
                uint32_t b0, b1, b2, b3;
                uint32_t addr = bBase + ((b_row + np * 16) * ASTRIDE + kk * 16 + b_koff) * 2;
                ldsm_x4(b0, b1, b2, b3, addr);
#pragma unroll
                for (int mt = 0; mt < 2; mt++) {
                    mma16816(acc[mt][np * 2],     af[mt], b0, b1);
                    mma16816(acc[mt][np * 2 + 1], af[mt], b2, b3);
                }
            }
        }
        __syncthreads();

        int nit = it + STAGES - 1;
        if (nit < KITER) {
            int ns = nit % STAGES;
            int kt = nit * KT;
            cp16(sA0 + ns * STAGE_BYTES + (r0l * ASTRIDE + c0l * 8) * 2, Ag + (size_t)r0l * KEXT + kt + c0l * 8);
            cp16(sA0 + ns * STAGE_BYTES + (r1l * ASTRIDE + c1l * 8) * 2, Ag + (size_t)r1l * KEXT + kt + c1l * 8);
            cp16(sB0 + ns * STAGE_BYTES + (r0l * ASTRIDE + c0l * 8) * 2, Bg + (size_t)r0l * KEXT + kt + c0l * 8);
            cp16(sB0 + ns * STAGE_BYTES + (r1l * ASTRIDE + c1l * 8) * 2, Bg + (size_t)r1l * KEXT + kt + c1l * 8);
        }
        CP_COMMIT();
    }

    // epilogue
    int crow = m0 + wm + (lane >> 2);
    int ccol = wn + (lane & 3) * 2;
    bool selfPart = (n0 >= 3072);
#pragma unroll
    for (int mt = 0; mt < 2; mt++) {
#pragma unroll
        for (int nt = 0; nt < 8; nt++) {
            int r1 = crow + mt * 16;
            int r2 = r1 + 8;
            int cl = ccol + nt * 8;
            int gc = n0 + cl;
            float2 v01; v01.x = acc[mt][nt][0]; v01.y = acc[mt][nt][1];
            float2 v23; v23.x = acc[mt][nt][2]; v23.y = acc[mt][nt][3];
            if (selfPart) {
                *(float2*)(C + (size_t)r1 * KDIM + gc) = v01;
                *(float2*)(C + (size_t)r2 * KDIM + gc) = v23;
            } else {
                __nv_bfloat16 h0 = __float2bfloat16(v01.x);
                __nv_bfloat16 h1 = __float2bfloat16(v01.y);
                __nv_bfloat16 h2 = __float2bfloat16(v23.x);
                __nv_bfloat16 h3 = __float2bfloat16(v23.y);
                __nv_bfloat162 hp1; hp1.x = h0; hp1.y = h1;
                __nv_bfloat162 hp2; hp2.x = h2; hp2.y = h3;
                __nv_bfloat162 lp1;
                lp1.x = __float2bfloat16(v01.x - __bfloat162float(h0));
                lp1.y = __float2bfloat16(v01.y - __bfloat162float(h1));
                __nv_bfloat162 lp2;
                lp2.x = __float2bfloat16(v23.x - __bfloat162float(h2));
                lp2.y = __float2bfloat16(v23.y - __bfloat162float(h3));
                *(__nv_bfloat162*)(YHp + (size_t)r1 * 3072 + gc) = hp1;
                *(__nv_bfloat162*)(YHp + (size_t)r2 * 3072 + gc) = hp2;
                *(__nv_bfloat162*)(YLp + (size_t)r1 * 3072 + gc) = lp1;
                *(__nv_bfloat162*)(YLp + (size_t)r2 * 3072 + gc) = lp2;
            }
        }
    }
}

// ---------------- combine via mma.sync: Z = relu(AC_split @ Y_split + Y_self) ----------------
// A: AE [b][64][KE] row-major; B: gathered rows of YH/YL ([K][N] -> ldmatrix.trans)
#define BSTR 264
template<int S, int RG>
__global__ __launch_bounds__(256, 2)
void k_combine_mma(const __nv_bfloat16* __restrict__ AE,
                   const __nv_bfloat16* __restrict__ YHp,
                   const __nv_bfloat16* __restrict__ YLp,
                   const float* __restrict__ Yf,
                   float* __restrict__ Z) {
    constexpr int KC = 6 * S;
    constexpr int KE = (S == 62) ? 1120 : 1152;
    constexpr int KIT = KE / 32;
    constexpr int RPB = KE * 8;
    extern __shared__ char dyn[];
    ull* rp = (ull*)dyn;
    uint32_t aOff = smem_u32(dyn) + RPB;
    uint32_t bOff = aOff + 3 * 5120;

    int tid = threadIdx.x, wid = tid >> 5, lane = tid & 31;
    int b = blockIdx.y;
    int n0c = blockIdx.x * 256;

    for (int k = tid; k < KE; k += 256) {
        int p = k / KC, r = k - p * KC;
        if (p > 2) { p = 0; r = 0; }
        int q = r / S, m = r - q * S;
        int node = (RG == 1) ? m : (m < 58 ? m : (m < 62 ? 62 + (m - 58) : 61));
        const __nv_bfloat16* src = (p == 1) ? YLp : YHp;
        rp[k] = (ull)(src + ((size_t)node * B + b) * 3072 + q * 512 + n0c);
    }
    __syncthreads();

    const __nv_bfloat16* Ab = AE + (size_t)b * 64 * KE;
    int arow = tid >> 2, ac = tid & 3;

    float acc[2][8][4];
#pragma unroll
    for (int i = 0; i < 2; i++)
#pragma unroll
        for (int j = 0; j < 8; j++)
#pragma unroll
            for (int k = 0; k < 4; k++) acc[i][j][k] = 0.f;

    // prologue
#pragma unroll
    for (int s = 0; s < 2; s++) {
        int kt = s * 32;
        cp16(aOff + s * 5120 + (arow * ASTRIDE + ac * 8) * 2, Ab + (size_t)arow * KE + kt + ac * 8);
#pragma unroll
        for (int j = 0; j < 4; j++) {
            int i = tid + j * 256;
            int kr = i >> 5, c = i & 31;
            cp16(bOff + s * 16896 + (kr * BSTR + c * 8) * 2, (const char*)rp[kt + kr] + c * 16);
        }
        CP_COMMIT();
    }

    int wm = (wid & 1) * 32, wn = (wid >> 1) * 64;
    int a_row = wm + (lane & 15);
    int a_koff = (lane >> 4) * 8;
    int grp = lane >> 3, lrow = lane & 7;

    for (int it = 0; it < KIT; it++) {
        CP_WAIT(1);
        __syncthreads();
        uint32_t aB = aOff + (it % 3) * 5120;
        uint32_t bB = bOff + (it % 3) * 16896;
#pragma unroll
        for (int kk = 0; kk < 2; kk++) {
            uint32_t af[2][4];
#pragma unroll
            for (int mt = 0; mt < 2; mt++) {
                uint32_t addr = aB + ((a_row + mt * 16) * ASTRIDE + kk * 16 + a_koff) * 2;
                ldsm_x4(af[mt][0], af[mt][1], af[mt][2], af[mt][3], addr);
            }
#pragma unroll
            for (int np = 0; np < 4; np++) {
                uint32_t b0, b1, b2, b3;
                uint32_t addr = bB + ((kk * 16 + (grp & 1) * 8 + lrow) * BSTR
                                      + wn + np * 16 + (grp >> 1) * 8) * 2;
                ldsm_x4_t(b0, b1, b2, b3, addr);
#pragma unroll
                for (int mt = 0; mt < 2; mt++) {
                    mma16816(acc[mt][np * 2],     af[mt], b0, b1);
                    mma16816(acc[mt][np * 2 + 1], af[mt], b2, b3);
                }
            }
        }
        __syncthreads();
        int nit = it + 2;
        if (nit < KIT) {
            int ns = nit % 3;
            int kt = nit * 32;
            cp16(aOff + ns * 5120 + (arow * ASTRIDE + ac * 8) * 2, Ab + (size_t)arow * KE + kt + ac * 8);
#pragma unroll
            for (int j = 0; j < 4; j++) {
                int i = tid + j * 256;
                int kr = i >> 5, c = i & 31;
                cp16(bOff + ns * 16896 + (kr * BSTR + c * 8) * 2, (const char*)rp[kt + kr] + c * 16);
            }
        }
        CP_COMMIT();
    }

    // epilogue: + self, relu, store
    int crow = wm + (lane >> 2);
    int ccol = wn + (lane & 3) * 2;
#pragma unroll
    for (int mt = 0; mt < 2; mt++) {
#pragma unroll
        for (int nt = 0; nt < 8; nt++) {
            int g = n0c + ccol + nt * 8;
#pragma unroll
            for (int half = 0; half < 2; half++) {
                int n = crow + mt * 16 + half * 8;
                float x = acc[mt][nt][half * 2];
                float y = acc[mt][nt][half * 2 + 1];
                if (n < S) {
                    int node = (RG == 1) ? n : (n < 58 ? n : (n < 62 ? 62 + (n - 58) : 61));
                    const float* sp = Yf + ((size_t)node * B + b) * KDIM + 3072 + g;
                    float2 o;
                    o.x = fmaxf(x + sp[0], 0.f);
                    o.y = fmaxf(y + sp[1], 0.f);
                    *(float2*)(Z + ((size_t)b * S + n) * 512 + g) = o;
                }
            }
        }
    }
}

// ---------------- layer-2 message aggregation (fp32) ----------------
__global__ void k_msg(const float* __restrict__ ACm, const float* __restrict__ X,
                      float* __restrict__ F, int nodes, int nRows, int rowBase, int rowStride) {
    int b = blockIdx.y, i = blockIdx.x;
    int row = rowBase + i * rowStride;
    __shared__ __align__(16) ull sA[NQ][64];
    int t = threadIdx.x;
    for (int e = t; e < NQ * nodes; e += 256) {
        int q = e / nodes, m = e % nodes;
        float a = ACm[(((size_t)b * NQ + q) * nodes + row) * nodes + m];
        sA[q][m] = dup2(a);
    }
    __syncthreads();
    ull acc[NQ] = {0ULL, 0ULL, 0ULL, 0ULL, 0ULL, 0ULL};
    const float* xb = X + (size_t)b * nodes * HDIM;
    int h = t * 2;
    for (int m = 0; m < nodes; m++) {
        ull xv = *(const ull*)(xb + (size_t)m * HDIM + h);
#pragma unroll
        for (int q = 0; q < NQ; q++) fma2(acc[q], sA[q][m], xv);
    }
    float* Fp = F + ((size_t)b * nRows + i) * KDIM;
#pragma unroll
    for (int q = 0; q < NQ; q++)
        *(ull*)(Fp + q * HDIM + h) = acc[q];
    *(ull*)(Fp + 3072 + h) = *(const ull*)(xb + (size_t)row * HDIM + h);
}

// ---------------- fp32 SGEMM tile 64x64 (layer-2): C = sigmoid(A @ Bw) ----------------
__global__ __launch_bounds__(256)
void k_gemm64(const float* __restrict__ A, const float* __restrict__ Bw,
              float* __restrict__ C, int K, int lda, int ldn) {
    __shared__ __align__(16) float As[16][64];
    __shared__ __align__(16) float Bs[16][68];
    int tid = threadIdx.x;
    int mb = blockIdx.x * 64, nb = blockIdx.y * 64;

    int arow = tid >> 2, ak = (tid & 3) * 4;
    int bk = tid >> 4, bn4 = (tid & 15) * 4;
    const float* Aptr = A + (size_t)(mb + arow) * lda + ak;
    const float* Bptr = Bw + (size_t)bk * ldn + nb + bn4;

    int tx = tid & 15, ty = tid >> 4;
    int r0 = ty * 4, c0 = tx * 4;

    ull acc[4][2];
#pragma unroll
    for (int i = 0; i < 4; i++) { acc[i][0] = 0ULL; acc[i][1] = 0ULL; }

    for (int kt = 0; kt < K; kt += 16) {
        float4 av = *(const float4*)(Aptr + kt);
        float4 bv = *(const float4*)(Bptr + (size_t)kt * ldn);
        As[ak + 0][arow] = av.x;
        As[ak + 1][arow] = av.y;
        As[ak + 2][arow] = av.z;
        As[ak + 3][arow] = av.w;
        *(float4*)&Bs[bk][bn4] = bv;
        __syncthreads();
#pragma unroll
        for (int k = 0; k < 16; k++) {
            float4 a4 = *(const float4*)&As[k][r0];
            ulonglong2 b2 = *(const ulonglong2*)&Bs[k][c0];
            float aa[4] = {a4.x, a4.y, a4.z, a4.w};
#pragma unroll
            for (int i = 0; i < 4; i++) {
                ull ad = dup2(aa[i]);
                fma2(acc[i][0], ad, b2.x);
                fma2(acc[i][1], ad, b2.y);
            }
        }
        __syncthreads();
    }

#pragma unroll
    for (int i = 0; i < 4; i++) {
        float* Cp = C + (size_t)(mb + r0 + i) * ldn + nb + c0;
        float l0, h0, l1, h1;
        unpack2(acc[i][0], l0, h0);
        unpack2(acc[i][1], l1, h1);
        float4 o;
        o.x = 1.f / (1.f + expf(-l0));
        o.y = 1.f / (1.f + expf(-h0));
        o.z = 1.f / (1.f + expf(-l1));
        o.w = 1.f / (1.f + expf(-h1));
        *(float4*)Cp = o;
    }
}

// ---------------- final logits ----------------
__global__ void k_logits(const float* __restrict__ U, const float* __restrict__ tW,
                         const float* __restrict__ tb, float* __restrict__ out) {
    int b = blockIdx.x;
    int w = threadIdx.x >> 5, lane = threadIdx.x & 31;
    if (w >= 11) return;
    const float* black = U + ((size_t)b * 2 + 1) * HDIM;
    const float* white = U + ((size_t)b * 2 + 0) * HDIM;
    const float* row = tW + w * 1024;
    float s = 0.f;
    for (int j = lane; j < HDIM; j += 32)
        s += black[j] * row[j] + white[j] * row[HDIM + j];
#pragma unroll
    for (int o = 16; o; o >>= 1) s += __shfl_down_sync(0xffffffffu, s, o);
    if (lane == 0) out[b * 11 + w] = s + tb[w];
}

// ---------------- host ----------------
extern "C" void kernel_launch(void* const* d_in, const int* in_sizes, int n_in,
                              void* d_out, int out_size) {
    int s = (n_in >= 21 && in_sizes[1] == 1) ? 1 : 0;

    const int*   player = (const int*)d_in[0];
    const float* enc    = (const float*)d_in[1 + s];
    const int*   adj    = (const int*)d_in[2 + s];
    const float* Ax     = (const float*)d_in[3 + s];
    const float* Ay     = (const float*)d_in[4 + s];
    const float* Bx     = (const float*)d_in[5 + s];
    const float* By     = (const float*)d_in[6 + s];
    const float* emb    = (const float*)d_in[7 + s];
    const float* coordW = (const float*)d_in[8 + s];
    const float* coordB = (const float*)d_in[9 + s];
    const float* inW    = (const float*)d_in[10 + s];
    const float* inB    = (const float*)d_in[11 + s];
    const float* basis0 = (const float*)d_in[12 + s];
    const float* comb0  = (const float*)d_in[13 + s];
    const float* self0  = (const float*)d_in[14 + s];
    const float* basis1 = (const float*)d_in[15 + s];
    const float* comb1  = (const float*)d_in[16 + s];
    const float* self1  = (const float*)d_in[17 + s];
    const float* typeW  = (const float*)d_in[18 + s];
    const float* typeB  = (const float*)d_in[19 + s];

    float* base = nullptr;
    cudaGetSymbolAddress((void**)&base, g_scratch);
    float* CW1  = base;
    float* INIT = base + 1835008;
    float* FEAT = base + 2097152;
    float* Y    = base + 2129920;
    float* Z1   = base + 62685184;
    float* Z2   = base + 70811648;
    float* Tb   = base + 79069184;
    float* U    = base + 79593472;
    float* AC1m = base + 79855616;
    float* AC2m = base + 85760000;
    float* F    = base + 91856384;
    __nv_bfloat16* AEXT = (__nv_bfloat16*)(base + 95526400);
    __nv_bfloat16* BEXT = (__nv_bfloat16*)(base + 108502528);
    __nv_bfloat16* YH   = (__nv_bfloat16*)(base + 111255040);
    __nv_bfloat16* YL   = (__nv_bfloat16*)(base + 137207296);
    __nv_bfloat16* A1E  = (__nv_bfloat16*)(base + 163159552);
    __nv_bfloat16* A2E  = (__nv_bfloat16*)(base + 172334592);

    const int mma_smem = 2 * STAGES * STAGE_BYTES;   // 61440
    cudaFuncSetAttribute(k_mma, cudaFuncAttributeMaxDynamicSharedMemorySize, mma_smem);
    cudaFuncSetAttribute(k_combine_mma<62, 1>, cudaFuncAttributeMaxDynamicSharedMemorySize, 75008);
    cudaFuncSetAttribute(k_combine_mma<63, 2>, cudaFuncAttributeMaxDynamicSharedMemorySize, 75264);

    k_build_cw1<<<(KDIM * HDIM + 255) / 256, 256>>>(basis1, self1, CW1);
    k_ac1<<<dim3(B, 16), 256>>>(adj, comb0, comb1, A1E, AC1m);
    k_ac2<<<dim3(B, 16), 256>>>(adj, comb0, comb1, A2E, AC2m);
    k_feat<<<128, 256>>>(player, Ax, Ay, Bx, By, emb, coordW, coordB, FEAT);
    k_init2<<<dim3(8, 8), 256>>>(FEAT, inW, inB, INIT);
    k_aext<<<(62 * B * HDIM + 255) / 256, 256>>>(enc, INIT, AEXT);
    k_bext<<<(KDIM * HDIM + 255) / 256, 256>>>(basis0, self0, BEXT);

    // Y projection for the 62 shared nodes
    k_mma<<<dim3(62 * B / 128, KDIM / 128), 256, mma_smem>>>(AEXT, BEXT, Y, YH, YL, 0);

    // rgcn1 layer1 combine (mma) -> Z1
    k_combine_mma<62, 1><<<dim3(2, B), 256, 75008>>>(A1E, YH, YL, Y, Z1);
    // rgcn1 layer2 (rows 58..61) -> Tb
    k_msg<<<dim3(4, B), 256>>>(AC1m, Z1, F, S1, 4, 58, 1);
    k_gemm64<<<dim3(4 * B / 64, HDIM / 64), 256>>>(F, CW1, Tb, KDIM, KDIM, HDIM);

    // T nodes -> AEXT rows 62..65, project
    k_aextT<<<(4 * B * HDIM + 255) / 256, 256>>>(Tb, AEXT);
    k_mma<<<dim3(4 * B / 128, KDIM / 128), 256, mma_smem>>>(AEXT, BEXT, Y, YH, YL, 62 * B);

    // rgcn2 layer1 combine (mma) -> Z2
    k_combine_mma<63, 2><<<dim3(2, B), 256, 75264>>>(A2E, YH, YL, Y, Z2);
    // rgcn2 layer2 (rows 60, 62) -> U
    k_msg<<<dim3(2, B), 256>>>(AC2m, Z2, F, S2, 2, 60, 2);
    k_gemm64<<<dim3(2 * B / 64, HDIM / 64), 256>>>(F, CW1, U, KDIM, KDIM, HDIM);

    k_logits<<<B, 352>>>(U, typeW, typeB, (float*)d_out);
}

// round 7
// speedup vs baseline: 3.6490x; 1.0186x over previous
#include <cuda_runtime.h>
#include <cuda_bf16.h>
#include <math.h>
#include <stdint.h>

#define B      256
#define HDIM   512
#define NENC   60
#define S1     62
#define S2     63
#define NQ     6
#define KDIM   3584      // 6*512 + 512
#define KEXT   1536      // Y-GEMM split K (hi|hi|lo x hi|lo|hi)

typedef unsigned long long ull;

// ---------------- scratch (float offsets) ----------------
static __device__ float g_scratch[181771776];

// ---------------- helpers ----------------
__device__ __forceinline__ ull dup2(float a) {
    ull d; asm("mov.b64 %0, {%1, %1};" : "=l"(d) : "f"(a)); return d;
}
__device__ __forceinline__ void fma2(ull &acc, ull a, ull b) {
    asm("fma.rn.f32x2 %0, %1, %2, %0;" : "+l"(acc) : "l"(a), "l"(b));
}
__device__ __forceinline__ void unpack2(ull v, float &lo, float &hi) {
    asm("mov.b64 {%0, %1}, %2;" : "=f"(lo), "=f"(hi) : "l"(v));
}
__device__ __forceinline__ uint32_t smem_u32(const void* p) {
    uint32_t a;
    asm("{ .reg .u64 t; cvta.to.shared.u64 t, %1; cvt.u32.u64 %0, t; }" : "=r"(a) : "l"(p));
    return a;
}
__device__ __forceinline__ void cp16(uint32_t s, const void* g) {
    asm volatile("cp.async.cg.shared.global [%0], [%1], 16;" :: "r"(s), "l"(g));
}
#define CP_COMMIT() asm volatile("cp.async.commit_group;" ::: "memory")
#define CP_WAIT(n)  asm volatile("cp.async.wait_group %0;" :: "n"(n) : "memory")

__device__ __forceinline__ void ldsm_x4(uint32_t &r0, uint32_t &r1, uint32_t &r2, uint32_t &r3, uint32_t addr) {
    asm volatile("ldmatrix.sync.aligned.m8n8.x4.shared.b16 {%0,%1,%2,%3}, [%4];"
        : "=r"(r0), "=r"(r1), "=r"(r2), "=r"(r3) : "r"(addr));
}
__device__ __forceinline__ void ldsm_x4_t(uint32_t &r0, uint32_t &r1, uint32_t &r2, uint32_t &r3, uint32_t addr) {
    asm volatile("ldmatrix.sync.aligned.m8n8.x4.trans.shared.b16 {%0,%1,%2,%3}, [%4];"
        : "=r"(r0), "=r"(r1), "=r"(r2), "=r"(r3) : "r"(addr));
}
__device__ __forceinline__ void mma16816(float* d, const uint32_t* a, uint32_t b0, uint32_t b1) {
    asm volatile("mma.sync.aligned.m16n8k16.row.col.f32.bf16.bf16.f32 "
        "{%0,%1,%2,%3}, {%4,%5,%6,%7}, {%8,%9}, {%0,%1,%2,%3};"
        : "+f"(d[0]), "+f"(d[1]), "+f"(d[2]), "+f"(d[3])
        : "r"(a[0]), "r"(a[1]), "r"(a[2]), "r"(a[3]), "r"(b0), "r"(b1));
}

// ---------------- CW1 (layer-2 weight, fp32 [K][N]) ----------------
__global__ void k_build_cw1(const float* __restrict__ basis, const float* __restrict__ selfW,
                            float* __restrict__ CW) {
    int idx = blockIdx.x * 256 + threadIdx.x;
    if (idx >= KDIM * HDIM) return;
    int row = idx >> 9;
    int k   = idx & 511;
    CW[idx] = (row < 3072) ? basis[idx] : selfW[(size_t)k * HDIM + (row - 3072)];
}

// ---------------- AC builders: bf16 split combine operand + fp32 msg layout ----------------
__global__ void k_ac1(const int* __restrict__ adj, const float* __restrict__ comb0,
                      const float* __restrict__ comb1, __nv_bfloat16* __restrict__ AE,
                      float* __restrict__ ACm) {
    __shared__ float sc[2][12][6];
    int t = threadIdx.x;
    if (t < 72) { sc[0][t / 6][t % 6] = comb0[t]; sc[1][t / 6][t % 6] = comb1[t]; }
    __syncthreads();
    int b = blockIdx.x;
    int e = blockIdx.y * 256 + t;
    if (e >= 64 * S1) return;
    int n = e / S1, m = e % S1;
    __nv_bfloat16* rowA = AE + ((size_t)b * 64 + n) * 1120;
    if (m < 4) rowA[1116 + m] = __float2bfloat16(0.f);
    bool valid = (n < S1);
    float a[12];
#pragma unroll
    for (int r = 0; r < 12; r++)
        a[r] = valid ? (float)adj[(((size_t)b * 13 + r + 1) * S1 + n) * S1 + m] : 0.f;
#pragma unroll
    for (int q = 0; q < NQ; q++) {
        float s0 = 0.f, s1 = 0.f;
#pragma unroll
        for (int r = 0; r < 12; r++) { s0 += sc[0][r][q] * a[r]; s1 += sc[1][r][q] * a[r]; }
        __nv_bfloat16 hi = __float2bfloat16(s0);
        float lo = s0 - __bfloat162float(hi);
        int c = q * S1 + m;
        rowA[c] = hi;
        rowA[372 + c] = hi;
        rowA[744 + c] = __float2bfloat16(lo);
        if (valid)
            ACm[(((size_t)b * NQ + q) * S1 + n) * S1 + m] = s1;
    }
}

__global__ void k_ac2(const int* __restrict__ adj, const float* __restrict__ comb0,
                      const float* __restrict__ comb1, __nv_bfloat16* __restrict__ AE,
                      float* __restrict__ ACm) {
    __shared__ float sc[2][12][6];
    int t = threadIdx.x;
    if (t < 72) { sc[0][t / 6][t % 6] = comb0[t]; sc[1][t / 6][t % 6] = comb1[t]; }
    __syncthreads();
    int b = blockIdx.x;
    int e = blockIdx.y * 256 + t;
    if (e >= 64 * S2) return;
    int n = e / S2, m = e % S2;
    __nv_bfloat16* rowA = AE + ((size_t)b * 64 + n) * 1152;
    if (m < 18) rowA[1134 + m] = __float2bfloat16(0.f);
    bool valid = (n < S2);
    int oi = (n == 62) ? 63 : n;
    int oj = (m == 62) ? 63 : m;
    float a[12];
#pragma unroll
    for (int r = 0; r < 12; r++) {
        int v = 0;
        if (valid && oi < 62 && oj < 62)
            v = adj[(((size_t)b * 13 + r + 1) * S1 + oi) * S1 + oj];
        a[r] = (float)v;
    }
    if (valid) {
        int lo2 = min(oi, oj), hi2 = max(oi, oj);
        if (hi2 - lo2 == 2) {
            int ni = lo2 >> 1;
            int ch = ((lo2 & 1) == 0) ? ((ni & 1) ? 12 : 11) : ((ni & 1) ? 11 : 12);
            a[ch - 1] = 1.f;
        }
    }
#pragma unroll
    for (int q = 0; q < NQ; q++) {
        float s0 = 0.f, s1 = 0.f;
#pragma unroll
        for (int r = 0; r < 12; r++) { s0 += sc[0][r][q] * a[r]; s1 += sc[1][r][q] * a[r]; }
        __nv_bfloat16 hi = __float2bfloat16(s0);
        float lo = s0 - __bfloat162float(hi);
        int c = q * S2 + m;
        rowA[c] = hi;
        rowA[378 + c] = hi;
        rowA[756 + c] = __float2bfloat16(lo);
        if (valid)
            ACm[(((size_t)b * NQ + q) * S2 + n) * S2 + m] = s1;
    }
}

// ---------------- initial embedding, two-stage ----------------
__global__ void k_feat(const int* __restrict__ player,
                       const float* __restrict__ Ax, const float* __restrict__ Ay,
                       const float* __restrict__ Bx, const float* __restrict__ By,
                       const float* __restrict__ emb, const float* __restrict__ cW,
                       const float* __restrict__ cb, float* __restrict__ feat) {
    int i = blockIdx.x * 256 + threadIdx.x;
    if (i >= 512 * 64) return;
    int m = i >> 6, l = i & 63;
    int b = m >> 1, p = m & 1;
    float v;
    if (l < 32) {
        float x = p ? Bx[b] : Ax[b];
        float y = p ? By[b] : Ay[b];
        v = fmaxf(cW[l * 2] * x + cW[l * 2 + 1] * y + cb[l], 0.f);
    } else {
        v = emb[player[b * 2 + p] * 32 + (l - 32)];
    }
    feat[m * 64 + l] = v;
}

__global__ __launch_bounds__(256)
void k_init2(const float* __restrict__ feat, const float* __restrict__ inW,
             const float* __restrict__ inb, float* __restrict__ INIT) {
    __shared__ __align__(16) float As[64][65];
    __shared__ __align__(16) float Bs[64][65];
    int t = threadIdx.x;
    int mb = blockIdx.x * 64, hb = blockIdx.y * 64;
#pragma unroll
    for (int j = 0; j < 16; j++) {
        int i = t + j * 256;
        int r = i >> 6, c = i & 63;
        As[r][c] = feat[(mb + r) * 64 + c];
        Bs[r][c] = inW[(hb + r) * 64 + c];
    }
    __syncthreads();
    int tx = t & 15, ty = t >> 4;
    int r0 = ty * 4, c0 = tx * 4;
    float acc[4][4] = {};
    for (int k = 0; k < 64; k++) {
        float av[4], bv[4];
#pragma unroll
        for (int i = 0; i < 4; i++) av[i] = As[r0 + i][k];
#pragma unroll
        for (int j = 0; j < 4; j++) bv[j] = Bs[c0 + j][k];
#pragma unroll
        for (int i = 0; i < 4; i++)
#pragma unroll
            for (int j = 0; j < 4; j++) acc[i][j] += av[i] * bv[j];
    }
#pragma unroll
    for (int i = 0; i < 4; i++)
#pragma unroll
        for (int j = 0; j < 4; j++)
            INIT[(size_t)(mb + r0 + i) * 512 + hb + c0 + j] = acc[i][j] + inb[hb + c0 + j];
}

// ---------------- A_ext builders (bf16 split [hi|hi|lo]) ----------------
__global__ void k_aext(const float* __restrict__ enc, const float* __restrict__ init,
                       __nv_bfloat16* __restrict__ A) {
    size_t i = (size_t)blockIdx.x * 256 + threadIdx.x;
    if (i >= (size_t)62 * B * HDIM) return;
    int m = (int)(i >> 9);
    int h = (int)(i & 511);
    int node = m >> 8, b = m & 255;
    float x = (node < NENC) ? enc[((size_t)b * NENC + node) * HDIM + h]
                            : init[((size_t)b * 2 + (node - NENC)) * HDIM + h];
    __nv_bfloat16 hi = __float2bfloat16(x);
    float lo = x - __bfloat162float(hi);
    __nv_bfloat16* row = A + (size_t)m * KEXT;
    row[h] = hi;
    row[512 + h] = hi;
    row[1024 + h] = __float2bfloat16(lo);
}

__global__ void k_aextT(const float* __restrict__ Tb, __nv_bfloat16* __restrict__ A) {
    size_t i = (size_t)blockIdx.x * 256 + threadIdx.x;
    if (i >= (size_t)4 * B * HDIM) return;
    int m = (int)(i >> 9);
    int h = (int)(i & 511);
    int j = m >> 8, b = m & 255;
    float x = Tb[((size_t)b * 4 + j) * HDIM + h];
    __nv_bfloat16 hi = __float2bfloat16(x);
    float lo = x - __bfloat162float(hi);
    __nv_bfloat16* row = A + (size_t)((62 + j) * B + b) * KEXT;
    row[h] = hi;
    row[512 + h] = hi;
    row[1024 + h] = __float2bfloat16(lo);
}

// ---------------- B_ext builder (bf16 split [hi|lo|hi]) ----------------
__global__ void k_bext(const float* __restrict__ basis, const float* __restrict__ selfW,
                       __nv_bfloat16* __restrict__ Bm) {
    size_t i = (size_t)blockIdx.x * 256 + threadIdx.x;
    if (i >= (size_t)KDIM * HDIM) return;
    int n = (int)(i >> 9);
    int k = (int)(i & 511);
    float w;
    if (n < 3072) {
        int q = n >> 9, j = n & 511;
        w = basis[((size_t)q * 512 + k) * 512 + j];
    } else {
        w = selfW[(size_t)(n - 3072) * 512 + k];
    }
    __nv_bfloat16 hi = __float2bfloat16(w);
    float lo = w - __bfloat162float(hi);
    __nv_bfloat16* row = Bm + (size_t)n * KEXT;
    row[k] = hi;
    row[512 + k] = __float2bfloat16(lo);
    row[1024 + k] = hi;
}

// ---------------- Y-GEMM mma.sync: emits YH/YL bf16 (q-part) + fp32 C (self part) ----------------
#define KT 32
#define STAGES 4
#define ASTRIDE 40
#define STAGE_ELT (128 * ASTRIDE)
#define STAGE_BYTES (STAGE_ELT * 2)

__global__ __launch_bounds__(256, 2)
void k_mma(const __nv_bfloat16* __restrict__ A, const __nv_bfloat16* __restrict__ Bm,
           float* __restrict__ C, __nv_bfloat16* __restrict__ YHp,
           __nv_bfloat16* __restrict__ YLp, int Mbase) {
    extern __shared__ __align__(16) __nv_bfloat16 sm[];
    int tid = threadIdx.x;
    int wid = tid >> 5, lane = tid & 31;
    int m0 = Mbase + blockIdx.x * 128;
    int n0 = blockIdx.y * 128;
    int wm = (wid & 3) * 32;
    int wn = (wid >> 2) * 64;

    uint32_t sA0 = smem_u32(sm);
    uint32_t sB0 = sA0 + STAGES * STAGE_BYTES;

    const __nv_bfloat16* Ag = A + (size_t)m0 * KEXT;
    const __nv_bfloat16* Bg = Bm + (size_t)n0 * KEXT;

    int r0l = (tid + 0) >> 2,   c0l = (tid + 0) & 3;
    int r1l = (tid + 256) >> 2, c1l = (tid + 256) & 3;

    float acc[2][8][4];
#pragma unroll
    for (int i = 0; i < 2; i++)
#pragma unroll
        for (int j = 0; j < 8; j++)
#pragma unroll
            for (int k = 0; k < 4; k++) acc[i][j][k] = 0.f;

#pragma unroll
    for (int s = 0; s < STAGES - 1; s++) {
        int kt = s * KT;
        cp16(sA0 + s * STAGE_BYTES + (r0l * ASTRIDE + c0l * 8) * 2, Ag + (size_t)r0l * KEXT + kt + c0l * 8);
        cp16(sA0 + s * STAGE_BYTES + (r1l * ASTRIDE + c1l * 8) * 2, Ag + (size_t)r1l * KEXT + kt + c1l * 8);
        cp16(sB0 + s * STAGE_BYTES + (r0l * ASTRIDE + c0l * 8) * 2, Bg + (size_t)r0l * KEXT + kt + c0l * 8);
        cp16(sB0 + s * STAGE_BYTES + (r1l * ASTRIDE + c1l * 8) * 2, Bg + (size_t)r1l * KEXT + kt + c1l * 8);
        CP_COMMIT();
    }

    int a_row = wm + (lane & 15);
    int a_koff = (lane >> 4) * 8;
    int b_row = wn + ((lane >> 4) * 8) + (lane & 7);
    int b_koff = ((lane >> 3) & 1) * 8;

    const int KITER = KEXT / KT;
    for (int it = 0; it < KITER; it++) {
        int s = it % STAGES;
        CP_WAIT(STAGES - 2);
        __syncthreads();

        uint32_t aBase = sA0 + s * STAGE_BYTES;
        uint32_t bBase = sB0 + s * STAGE_BYTES;
#pragma unroll
        for (int kk = 0; kk < 2; kk++) {
            uint32_t af[2][4];
#pragma unroll
            for (int mt = 0; mt < 2; mt++) {
                uint32_t addr = aBase + ((a_row + mt * 16) * ASTRIDE + kk * 16 + a_koff) * 2;
                ldsm_x4(af[mt][0], af[mt][1], af[mt][2], af[mt][3], addr);
            }
#pragma unroll
            for (int np = 0; np < 4; np++) {
                uint32_t b0, b1, b2, b3;
                uint32_t addr = bBase + ((b_row + np * 16) * ASTRIDE + kk * 16 + b_koff) * 2;
                ldsm_x4(b0, b1, b2, b3, addr);
#pragma unroll
                for (int mt = 0; mt < 2; mt++) {
                    mma16816(acc[mt][np * 2],     af[mt], b0, b1);
                    mma16816(acc[mt][np * 2 + 1], af[mt], b2, b3);
                }
            }
        }
        // no tail sync: next writes target stage (it+STAGES-1)%STAGES, which was
        // last read at iter it-1; the top-of-loop CP_WAIT+sync already ordered that.
        int nit = it + STAGES - 1;
        if (nit < KITER) {
            int ns = nit % STAGES;
            int kt = nit * KT;
            cp16(sA0 + ns * STAGE_BYTES + (r0l * ASTRIDE + c0l * 8) * 2, Ag + (size_t)r0l * KEXT + kt + c0l * 8);
            cp16(sA0 + ns * STAGE_BYTES + (r1l * ASTRIDE + c1l * 8) * 2, Ag + (size_t)r1l * KEXT + kt + c1l * 8);
            cp16(sB0 + ns * STAGE_BYTES + (r0l * ASTRIDE + c0l * 8) * 2, Bg + (size_t)r0l * KEXT + kt + c0l * 8);
            cp16(sB0 + ns * STAGE_BYTES + (r1l * ASTRIDE + c1l * 8) * 2, Bg + (size_t)r1l * KEXT + kt + c1l * 8);
        }
        CP_COMMIT();
    }

    // epilogue
    int crow = m0 + wm + (lane >> 2);
    int ccol = wn + (lane & 3) * 2;
    bool selfPart = (n0 >= 3072);
#pragma unroll
    for (int mt = 0; mt < 2; mt++) {
#pragma unroll
        for (int nt = 0; nt < 8; nt++) {
            int r1 = crow + mt * 16;
            int r2 = r1 + 8;
            int cl = ccol + nt * 8;
            int gc = n0 + cl;
            float2 v01; v01.x = acc[mt][nt][0]; v01.y = acc[mt][nt][1];
            float2 v23; v23.x = acc[mt][nt][2]; v23.y = acc[mt][nt][3];
            if (selfPart) {
                *(float2*)(C + (size_t)r1 * KDIM + gc) = v01;
                *(float2*)(C + (size_t)r2 * KDIM + gc) = v23;
            } else {
                __nv_bfloat16 h0 = __float2bfloat16(v01.x);
                __nv_bfloat16 h1 = __float2bfloat16(v01.y);
                __nv_bfloat16 h2 = __float2bfloat16(v23.x);
                __nv_bfloat16 h3 = __float2bfloat16(v23.y);
                __nv_bfloat162 hp1; hp1.x = h0; hp1.y = h1;
                __nv_bfloat162 hp2; hp2.x = h2; hp2.y = h3;
                __nv_bfloat162 lp1;
                lp1.x = __float2bfloat16(v01.x - __bfloat162float(h0));
                lp1.y = __float2bfloat16(v01.y - __bfloat162float(h1));
                __nv_bfloat162 lp2;
                lp2.x = __float2bfloat16(v23.x - __bfloat162float(h2));
                lp2.y = __float2bfloat16(v23.y - __bfloat162float(h3));
                *(__nv_bfloat162*)(YHp + (size_t)r1 * 3072 + gc) = hp1;
                *(__nv_bfloat162*)(YHp + (size_t)r2 * 3072 + gc) = hp2;
                *(__nv_bfloat162*)(YLp + (size_t)r1 * 3072 + gc) = lp1;
                *(__nv_bfloat162*)(YLp + (size_t)r2 * 3072 + gc) = lp2;
            }
        }
    }
}

// ---------------- combine via mma.sync: Z = relu(AC_split @ Y_split + Y_self) ----------------
#define BSTR 264
#define CSTG 4
template<int S, int RG>
__global__ __launch_bounds__(256, 2)
void k_combine_mma(const __nv_bfloat16* __restrict__ AE,
                   const __nv_bfloat16* __restrict__ YHp,
                   const __nv_bfloat16* __restrict__ YLp,
                   const float* __restrict__ Yf,
                   float* __restrict__ Z) {
    constexpr int KC = 6 * S;
    constexpr int KE = (S == 62) ? 1120 : 1152;
    constexpr int KIT = KE / 32;
    constexpr int RPB = KE * 8;
    extern __shared__ char dyn[];
    ull* rp = (ull*)dyn;
    uint32_t aOff = smem_u32(dyn) + RPB;
    uint32_t bOff = aOff + CSTG * 5120;

    int tid = threadIdx.x, wid = tid >> 5, lane = tid & 31;
    int b = blockIdx.y;
    int n0c = blockIdx.x * 256;

    for (int k = tid; k < KE; k += 256) {
        int p = k / KC, r = k - p * KC;
        if (p > 2) { p = 0; r = 0; }
        int q = r / S, m = r - q * S;
        int node = (RG == 1) ? m : (m < 58 ? m : (m < 62 ? 62 + (m - 58) : 61));
        const __nv_bfloat16* src = (p == 1) ? YLp : YHp;
        rp[k] = (ull)(src + ((size_t)node * B + b) * 3072 + q * 512 + n0c);
    }
    __syncthreads();

    const __nv_bfloat16* Ab = AE + (size_t)b * 64 * KE;
    int arow = tid >> 2, ac = tid & 3;

    float acc[2][8][4];
#pragma unroll
    for (int i = 0; i < 2; i++)
#pragma unroll
        for (int j = 0; j < 8; j++)
#pragma unroll
            for (int k = 0; k < 4; k++) acc[i][j][k] = 0.f;

    // prologue
#pragma unroll
    for (int s = 0; s < CSTG - 1; s++) {
        int kt = s * 32;
        cp16(aOff + s * 5120 + (arow * ASTRIDE + ac * 8) * 2, Ab + (size_t)arow * KE + kt + ac * 8);
#pragma unroll
        for (int j = 0; j < 4; j++) {
            int i = tid + j * 256;
            int kr = i >> 5, c = i & 31;
            cp16(bOff + s * 16896 + (kr * BSTR + c * 8) * 2, (const char*)rp[kt + kr] + c * 16);
        }
        CP_COMMIT();
    }

    int wm = (wid & 1) * 32, wn = (wid >> 1) * 64;
    int a_row = wm + (lane & 15);
    int a_koff = (lane >> 4) * 8;
    int grp = lane >> 3, lrow = lane & 7;

    for (int it = 0; it < KIT; it++) {
        CP_WAIT(CSTG - 2);
        __syncthreads();
        uint32_t aB = aOff + (it % CSTG) * 5120;
        uint32_t bB = bOff + (it % CSTG) * 16896;
#pragma unroll
        for (int kk = 0; kk < 2; kk++) {
            uint32_t af[2][4];
#pragma unroll
            for (int mt = 0; mt < 2; mt++) {
                uint32_t addr = aB + ((a_row + mt * 16) * ASTRIDE + kk * 16 + a_koff) * 2;
                ldsm_x4(af[mt][0], af[mt][1], af[mt][2], af[mt][3], addr);
            }
#pragma unroll
            for (int np = 0; np < 4; np++) {
                uint32_t b0, b1, b2, b3;
                uint32_t addr = bB + ((kk * 16 + (grp & 1) * 8 + lrow) * BSTR
                                      + wn + np * 16 + (grp >> 1) * 8) * 2;
                ldsm_x4_t(b0, b1, b2, b3, addr);
#pragma unroll
                for (int mt = 0; mt < 2; mt++) {
                    mma16816(acc[mt][np * 2],     af[mt], b0, b1);
                    mma16816(acc[mt][np * 2 + 1], af[mt], b2, b3);
                }
            }
        }
        int nit = it + CSTG - 1;
        if (nit < KIT) {
            int ns = nit % CSTG;
            int kt = nit * 32;
            cp16(aOff + ns * 5120 + (arow * ASTRIDE + ac * 8) * 2, Ab + (size_t)arow * KE + kt + ac * 8);
#pragma unroll
            for (int j = 0; j < 4; j++) {
                int i = tid + j * 256;
                int kr = i >> 5, c = i & 31;
                cp16(bOff + ns * 16896 + (kr * BSTR + c * 8) * 2, (const char*)rp[kt + kr] + c * 16);
            }
        }
        CP_COMMIT();
    }

    // epilogue: + self, relu, store
    int crow = wm + (lane >> 2);
    int ccol = wn + (lane & 3) * 2;
#pragma unroll
    for (int mt = 0; mt < 2; mt++) {
#pragma unroll
        for (int nt = 0; nt < 8; nt++) {
            int g = n0c + ccol + nt * 8;
#pragma unroll
            for (int half = 0; half < 2; half++) {
                int n = crow + mt * 16 + half * 8;
                float x = acc[mt][nt][half * 2];
                float y = acc[mt][nt][half * 2 + 1];
                if (n < S) {
                    int node = (RG == 1) ? n : (n < 58 ? n : (n < 62 ? 62 + (n - 58) : 61));
                    const float* sp = Yf + ((size_t)node * B + b) * KDIM + 3072 + g;
                    float2 o;
                    o.x = fmaxf(x + sp[0], 0.f);
                    o.y = fmaxf(y + sp[1], 0.f);
                    *(float2*)(Z + ((size_t)b * S + n) * 512 + g) = o;
                }
            }
        }
    }
}

// ---------------- layer-2 message aggregation (fp32) ----------------
__global__ void k_msg(const float* __restrict__ ACm, const float* __restrict__ X,
                      float* __restrict__ F, int nodes, int nRows, int rowBase, int rowStride) {
    int b = blockIdx.y, i = blockIdx.x;
    int row = rowBase + i * rowStride;
    __shared__ __align__(16) ull sA[NQ][64];
    int t = threadIdx.x;
    for (int e = t; e < NQ * nodes; e += 256) {
        int q = e / nodes, m = e % nodes;
        float a = ACm[(((size_t)b * NQ + q) * nodes + row) * nodes + m];
        sA[q][m] = dup2(a);
    }
    __syncthreads();
    ull acc[NQ] = {0ULL, 0ULL, 0ULL, 0ULL, 0ULL, 0ULL};
    const float* xb = X + (size_t)b * nodes * HDIM;
    int h = t * 2;
    for (int m = 0; m < nodes; m++) {
        ull xv = *(const ull*)(xb + (size_t)m * HDIM + h);
#pragma unroll
        for (int q = 0; q < NQ; q++) fma2(acc[q], sA[q][m], xv);
    }
    float* Fp = F + ((size_t)b * nRows + i) * KDIM;
#pragma unroll
    for (int q = 0; q < NQ; q++)
        *(ull*)(Fp + q * HDIM + h) = acc[q];
    *(ull*)(Fp + 3072 + h) = *(const ull*)(xb + (size_t)row * HDIM + h);
}

// ---------------- fp32 SGEMM tile 64x64 (layer-2): C = sigmoid(A @ Bw) ----------------
__global__ __launch_bounds__(256)
void k_gemm64(const float* __restrict__ A, const float* __restrict__ Bw,
              float* __restrict__ C, int K, int lda, int ldn) {
    __shared__ __align__(16) float As[16][64];
    __shared__ __align__(16) float Bs[16][68];
    int tid = threadIdx.x;
    int mb = blockIdx.x * 64, nb = blockIdx.y * 64;

    int arow = tid >> 2, ak = (tid & 3) * 4;
    int bk = tid >> 4, bn4 = (tid & 15) * 4;
    const float* Aptr = A + (size_t)(mb + arow) * lda + ak;
    const float* Bptr = Bw + (size_t)bk * ldn + nb + bn4;

    int tx = tid & 15, ty = tid >> 4;
    int r0 = ty * 4, c0 = tx * 4;

    ull acc[4][2];
#pragma unroll
    for (int i = 0; i < 4; i++) { acc[i][0] = 0ULL; acc[i][1] = 0ULL; }

    for (int kt = 0; kt < K; kt += 16) {
        float4 av = *(const float4*)(Aptr + kt);
        float4 bv = *(const float4*)(Bptr + (size_t)kt * ldn);
        As[ak + 0][arow] = av.x;
        As[ak + 1][arow] = av.y;
        As[ak + 2][arow] = av.z;
        As[ak + 3][arow] = av.w;
        *(float4*)&Bs[bk][bn4] = bv;
        __syncthreads();
#pragma unroll
        for (int k = 0; k < 16; k++) {
            float4 a4 = *(const float4*)&As[k][r0];
            ulonglong2 b2 = *(const ulonglong2*)&Bs[k][c0];
            float aa[4] = {a4.x, a4.y, a4.z, a4.w};
#pragma unroll
            for (int i = 0; i < 4; i++) {
                ull ad = dup2(aa[i]);
                fma2(acc[i][0], ad, b2.x);
                fma2(acc[i][1], ad, b2.y);
            }
        }
        __syncthreads();
    }

#pragma unroll
    for (int i = 0; i < 4; i++) {
        float* Cp = C + (size_t)(mb + r0 + i) * ldn + nb + c0;
        float l0, h0, l1, h1;
        unpack2(acc[i][0], l0, h0);
        unpack2(acc[i][1], l1, h1);
        float4 o;
        o.x = 1.f / (1.f + expf(-l0));
        o.y = 1.f / (1.f + expf(-h0));
        o.z = 1.f / (1.f + expf(-l1));
        o.w = 1.f / (1.f + expf(-h1));
        *(float4*)Cp = o;
    }
}

// ---------------- final logits ----------------
__global__ void k_logits(const float* __restrict__ U, const float* __restrict__ tW,
                         const float* __restrict__ tb, float* __restrict__ out) {
    int b = blockIdx.x;
    int w = threadIdx.x >> 5, lane = threadIdx.x & 31;
    if (w >= 11) return;
    const float* black = U + ((size_t)b * 2 + 1) * HDIM;
    const float* white = U + ((size_t)b * 2 + 0) * HDIM;
    const float* row = tW + w * 1024;
    float s = 0.f;
    for (int j = lane; j < HDIM; j += 32)
        s += black[j] * row[j] + white[j] * row[HDIM + j];
#pragma unroll
    for (int o = 16; o; o >>= 1) s += __shfl_down_sync(0xffffffffu, s, o);
    if (lane == 0) out[b * 11 + w] = s + tb[w];
}

// ---------------- host ----------------
extern "C" void kernel_launch(void* const* d_in, const int* in_sizes, int n_in,
                              void* d_out, int out_size) {
    int s = (n_in >= 21 && in_sizes[1] == 1) ? 1 : 0;

    const int*   player = (const int*)d_in[0];
    const float* enc    = (const float*)d_in[1 + s];
    const int*   adj    = (const int*)d_in[2 + s];
    const float* Ax     = (const float*)d_in[3 + s];
    const float* Ay     = (const float*)d_in[4 + s];
    const float* Bx     = (const float*)d_in[5 + s];
    const float* By     = (const float*)d_in[6 + s];
    const float* emb    = (const float*)d_in[7 + s];
    const float* coordW = (const float*)d_in[8 + s];
    const float* coordB = (const float*)d_in[9 + s];
    const float* inW    = (const float*)d_in[10 + s];
    const float* inB    = (const float*)d_in[11 + s];
    const float* basis0 = (const float*)d_in[12 + s];
    const float* comb0  = (const float*)d_in[13 + s];
    const float* self0  = (const float*)d_in[14 + s];
    const float* basis1 = (const float*)d_in[15 + s];
    const float* comb1  = (const float*)d_in[16 + s];
    const float* self1  = (const float*)d_in[17 + s];
    const float* typeW  = (const float*)d_in[18 + s];
    const float* typeB  = (const float*)d_in[19 + s];

    float* base = nullptr;
    cudaGetSymbolAddress((void**)&base, g_scratch);
    float* CW1  = base;
    float* INIT = base + 1835008;
    float* FEAT = base + 2097152;
    float* Y    = base + 2129920;
    float* Z1   = base + 62685184;
    float* Z2   = base + 70811648;
    float* Tb   = base + 79069184;
    float* U    = base + 79593472;
    float* AC1m = base + 79855616;
    float* AC2m = base + 85760000;
    float* F    = base + 91856384;
    __nv_bfloat16* AEXT = (__nv_bfloat16*)(base + 95526400);
    __nv_bfloat16* BEXT = (__nv_bfloat16*)(base + 108502528);
    __nv_bfloat16* YH   = (__nv_bfloat16*)(base + 111255040);
    __nv_bfloat16* YL   = (__nv_bfloat16*)(base + 137207296);
    __nv_bfloat16* A1E  = (__nv_bfloat16*)(base + 163159552);
    __nv_bfloat16* A2E  = (__nv_bfloat16*)(base + 172334592);

    const int mma_smem = 2 * STAGES * STAGE_BYTES;   // 81920
    const int c1_smem = 1120 * 8 + CSTG * (5120 + 16896);   // 97024
    const int c2_smem = 1152 * 8 + CSTG * (5120 + 16896);   // 97280
    cudaFuncSetAttribute(k_mma, cudaFuncAttributeMaxDynamicSharedMemorySize, mma_smem);
    cudaFuncSetAttribute(k_combine_mma<62, 1>, cudaFuncAttributeMaxDynamicSharedMemorySize, c1_smem);
    cudaFuncSetAttribute(k_combine_mma<63, 2>, cudaFuncAttributeMaxDynamicSharedMemorySize, c2_smem);

    // launch order chosen so k_mma (grid1) is the 6th launch -> ncu -s 5 profiles it
    k_feat<<<128, 256>>>(player, Ax, Ay, Bx, By, emb, coordW, coordB, FEAT);         // 1
    k_init2<<<dim3(8, 8), 256>>>(FEAT, inW, inB, INIT);                              // 2
    k_aext<<<(62 * B * HDIM + 255) / 256, 256>>>(enc, INIT, AEXT);                   // 3
    k_bext<<<(KDIM * HDIM + 255) / 256, 256>>>(basis0, self0, BEXT);                 // 4
    k_build_cw1<<<(KDIM * HDIM + 255) / 256, 256>>>(basis1, self1, CW1);             // 5
    // Y projection for the 62 shared nodes                                          // 6
    k_mma<<<dim3(62 * B / 128, KDIM / 128), 256, mma_smem>>>(AEXT, BEXT, Y, YH, YL, 0);

    k_ac1<<<dim3(B, 16), 256>>>(adj, comb0, comb1, A1E, AC1m);
    k_ac2<<<dim3(B, 16), 256>>>(adj, comb0, comb1, A2E, AC2m);

    // rgcn1 layer1 combine (mma) -> Z1
    k_combine_mma<62, 1><<<dim3(2, B), 256, c1_smem>>>(A1E, YH, YL, Y, Z1);
    // rgcn1 layer2 (rows 58..61) -> Tb
    k_msg<<<dim3(4, B), 256>>>(AC1m, Z1, F, S1, 4, 58, 1);
    k_gemm64<<<dim3(4 * B / 64, HDIM / 64), 256>>>(F, CW1, Tb, KDIM, KDIM, HDIM);

    // T nodes -> AEXT rows 62..65, project
    k_aextT<<<(4 * B * HDIM + 255) / 256, 256>>>(Tb, AEXT);
    k_mma<<<dim3(4 * B / 128, KDIM / 128), 256, mma_smem>>>(AEXT, BEXT, Y, YH, YL, 62 * B);

    // rgcn2 layer1 combine (mma) -> Z2
    k_combine_mma<63, 2><<<dim3(2, B), 256, c2_smem>>>(A2E, YH, YL, Y, Z2);
    // rgcn2 layer2 (rows 60, 62) -> U
    k_msg<<<dim3(2, B), 256>>>(AC2m, Z2, F, S2, 2, 60, 2);
    k_gemm64<<<dim3(2 * B / 64, HDIM / 64), 256>>>(F, CW1, U, KDIM, KDIM, HDIM);

    k_logits<<<B, 352>>>(U, typeW, typeB, (float*)d_out);
}

// round 8
// speedup vs baseline: 3.6908x; 1.0114x over previous
#include <cuda_runtime.h>
#include <cuda_bf16.h>
#include <math.h>
#include <stdint.h>

#define B      256
#define HDIM   512
#define NENC   60
#define S1     62
#define S2     63
#define NQ     6
#define KDIM   3584      // 6*512 + 512
#define KEXT   1536      // Y-GEMM split K (hi|hi|lo x hi|lo|hi)

typedef unsigned long long ull;

// ---------------- scratch (float offsets) ----------------
static __device__ float g_scratch[181771776];

// ---------------- helpers ----------------
__device__ __forceinline__ ull dup2(float a) {
    ull d; asm("mov.b64 %0, {%1, %1};" : "=l"(d) : "f"(a)); return d;
}
__device__ __forceinline__ void fma2(ull &acc, ull a, ull b) {
    asm("fma.rn.f32x2 %0, %1, %2, %0;" : "+l"(acc) : "l"(a), "l"(b));
}
__device__ __forceinline__ void unpack2(ull v, float &lo, float &hi) {
    asm("mov.b64 {%0, %1}, %2;" : "=f"(lo), "=f"(hi) : "l"(v));
}
__device__ __forceinline__ uint32_t smem_u32(const void* p) {
    uint32_t a;
    asm("{ .reg .u64 t; cvta.to.shared.u64 t, %1; cvt.u32.u64 %0, t; }" : "=r"(a) : "l"(p));
    return a;
}
__device__ __forceinline__ void cp16(uint32_t s, const void* g) {
    asm volatile("cp.async.cg.shared.global [%0], [%1], 16;" :: "r"(s), "l"(g));
}
#define CP_COMMIT() asm volatile("cp.async.commit_group;" ::: "memory")
#define CP_WAIT(n)  asm volatile("cp.async.wait_group %0;" :: "n"(n) : "memory")

__device__ __forceinline__ void ldsm_x4(uint32_t &r0, uint32_t &r1, uint32_t &r2, uint32_t &r3, uint32_t addr) {
    asm volatile("ldmatrix.sync.aligned.m8n8.x4.shared.b16 {%0,%1,%2,%3}, [%4];"
        : "=r"(r0), "=r"(r1), "=r"(r2), "=r"(r3) : "r"(addr));
}
__device__ __forceinline__ void ldsm_x4_t(uint32_t &r0, uint32_t &r1, uint32_t &r2, uint32_t &r3, uint32_t addr) {
    asm volatile("ldmatrix.sync.aligned.m8n8.x4.trans.shared.b16 {%0,%1,%2,%3}, [%4];"
        : "=r"(r0), "=r"(r1), "=r"(r2), "=r"(r3) : "r"(addr));
}
__device__ __forceinline__ void mma16816(float* d, const uint32_t* a, uint32_t b0, uint32_t b1) {
    asm volatile("mma.sync.aligned.m16n8k16.row.col.f32.bf16.bf16.f32 "
        "{%0,%1,%2,%3}, {%4,%5,%6,%7}, {%8,%9}, {%0,%1,%2,%3};"
        : "+f"(d[0]), "+f"(d[1]), "+f"(d[2]), "+f"(d[3])
        : "r"(a[0]), "r"(a[1]), "r"(a[2]), "r"(a[3]), "r"(b0), "r"(b1));
}

// ---------------- CW1 (layer-2 weight, fp32 [K][N]) ----------------
__global__ void k_build_cw1(const float* __restrict__ basis, const float* __restrict__ selfW,
                            float* __restrict__ CW) {
    int idx = blockIdx.x * 256 + threadIdx.x;
    if (idx >= KDIM * HDIM) return;
    int row = idx >> 9;
    int k   = idx & 511;
    CW[idx] = (row < 3072) ? basis[idx] : selfW[(size_t)k * HDIM + (row - 3072)];
}

// ---------------- AC builders: bf16 split combine operand + fp32 msg layout ----------------
__global__ void k_ac1(const int* __restrict__ adj, const float* __restrict__ comb0,
                      const float* __restrict__ comb1, __nv_bfloat16* __restrict__ AE,
                      float* __restrict__ ACm) {
    __shared__ float sc[2][12][6];
    int t = threadIdx.x;
    if (t < 72) { sc[0][t / 6][t % 6] = comb0[t]; sc[1][t / 6][t % 6] = comb1[t]; }
    __syncthreads();
    int b = blockIdx.x;
    int e = blockIdx.y * 256 + t;
    if (e >= 64 * S1) return;
    int n = e / S1, m = e % S1;
    __nv_bfloat16* rowA = AE + ((size_t)b * 64 + n) * 1120;
    if (m < 4) rowA[1116 + m] = __float2bfloat16(0.f);
    bool valid = (n < S1);
    float a[12];
#pragma unroll
    for (int r = 0; r < 12; r++)
        a[r] = valid ? (float)adj[(((size_t)b * 13 + r + 1) * S1 + n) * S1 + m] : 0.f;
#pragma unroll
    for (int q = 0; q < NQ; q++) {
        float s0 = 0.f, s1 = 0.f;
#pragma unroll
        for (int r = 0; r < 12; r++) { s0 += sc[0][r][q] * a[r]; s1 += sc[1][r][q] * a[r]; }
        __nv_bfloat16 hi = __float2bfloat16(s0);
        float lo = s0 - __bfloat162float(hi);
        int c = q * S1 + m;
        rowA[c] = hi;
        rowA[372 + c] = hi;
        rowA[744 + c] = __float2bfloat16(lo);
        if (valid)
            ACm[(((size_t)b * NQ + q) * S1 + n) * S1 + m] = s1;
    }
}

__global__ void k_ac2(const int* __restrict__ adj, const float* __restrict__ comb0,
                      const float* __restrict__ comb1, __nv_bfloat16* __restrict__ AE,
                      float* __restrict__ ACm) {
    __shared__ float sc[2][12][6];
    int t = threadIdx.x;
    if (t < 72) { sc[0][t / 6][t % 6] = comb0[t]; sc[1][t / 6][t % 6] = comb1[t]; }
    __syncthreads();
    int b = blockIdx.x;
    int e = blockIdx.y * 256 + t;
    if (e >= 64 * S2) return;
    int n = e / S2, m = e % S2;
    __nv_bfloat16* rowA = AE + ((size_t)b * 64 + n) * 1152;
    if (m < 18) rowA[1134 + m] = __float2bfloat16(0.f);
    bool valid = (n < S2);
    int oi = (n == 62) ? 63 : n;
    int oj = (m == 62) ? 63 : m;
    float a[12];
#pragma unroll
    for (int r = 0; r < 12; r++) {
        int v = 0;
        if (valid && oi < 62 && oj < 62)
            v = adj[(((size_t)b * 13 + r + 1) * S1 + oi) * S1 + oj];
        a[r] = (float)v;
    }
    if (valid) {
        int lo2 = min(oi, oj), hi2 = max(oi, oj);
        if (hi2 - lo2 == 2) {
            int ni = lo2 >> 1;
            int ch = ((lo2 & 1) == 0) ? ((ni & 1) ? 12 : 11) : ((ni & 1) ? 11 : 12);
            a[ch - 1] = 1.f;
        }
    }
#pragma unroll
    for (int q = 0; q < NQ; q++) {
        float s0 = 0.f, s1 = 0.f;
#pragma unroll
        for (int r = 0; r < 12; r++) { s0 += sc[0][r][q] * a[r]; s1 += sc[1][r][q] * a[r]; }
        __nv_bfloat16 hi = __float2bfloat16(s0);
        float lo = s0 - __bfloat162float(hi);
        int c = q * S2 + m;
        rowA[c] = hi;
        rowA[378 + c] = hi;
        rowA[756 + c] = __float2bfloat16(lo);
        if (valid)
            ACm[(((size_t)b * NQ + q) * S2 + n) * S2 + m] = s1;
    }
}

// ---------------- initial embedding (fused feature + GEMM) ----------------
__global__ __launch_bounds__(256)
void k_init(const int* __restrict__ player,
            const float* __restrict__ Ax, const float* __restrict__ Ay,
            const float* __restrict__ Bx, const float* __restrict__ By,
            const float* __restrict__ emb, const float* __restrict__ cW,
            const float* __restrict__ cb, const float* __restrict__ inW,
            const float* __restrict__ inb, float* __restrict__ INIT) {
    __shared__ __align__(16) float As[64][65];
    __shared__ __align__(16) float Bs[64][65];
    int t = threadIdx.x;
    int mb = blockIdx.x * 64, hb = blockIdx.y * 64;
#pragma unroll
    for (int j = 0; j < 16; j++) {
        int i = t + j * 256;
        int r = i >> 6, c = i & 63;
        int m = mb + r;
        int b = m >> 1, p = m & 1;
        float v;
        if (c < 32) {
            float x = p ? Bx[b] : Ax[b];
            float y = p ? By[b] : Ay[b];
            v = fmaxf(cW[c * 2] * x + cW[c * 2 + 1] * y + cb[c], 0.f);
        } else {
            v = emb[player[b * 2 + p] * 32 + (c - 32)];
        }
        As[r][c] = v;
        Bs[r][c] = inW[(hb + r) * 64 + c];
    }
    __syncthreads();
    int tx = t & 15, ty = t >> 4;
    int r0 = ty * 4, c0 = tx * 4;
    float acc[4][4] = {};
    for (int k = 0; k < 64; k++) {
        float av[4], bv[4];
#pragma unroll
        for (int i = 0; i < 4; i++) av[i] = As[r0 + i][k];
#pragma unroll
        for (int j = 0; j < 4; j++) bv[j] = Bs[c0 + j][k];
#pragma unroll
        for (int i = 0; i < 4; i++)
#pragma unroll
            for (int j = 0; j < 4; j++) acc[i][j] += av[i] * bv[j];
    }
#pragma unroll
    for (int i = 0; i < 4; i++)
#pragma unroll
        for (int j = 0; j < 4; j++)
            INIT[(size_t)(mb + r0 + i) * 512 + hb + c0 + j] = acc[i][j] + inb[hb + c0 + j];
}

// ---------------- A_ext builders (bf16 split [hi|hi|lo]) ----------------
__global__ void k_aext(const float* __restrict__ enc, const float* __restrict__ init,
                       __nv_bfloat16* __restrict__ A) {
    size_t i = (size_t)blockIdx.x * 256 + threadIdx.x;
    if (i >= (size_t)62 * B * HDIM) return;
    int m = (int)(i >> 9);
    int h = (int)(i & 511);
    int node = m >> 8, b = m & 255;
    float x = (node < NENC) ? enc[((size_t)b * NENC + node) * HDIM + h]
                            : init[((size_t)b * 2 + (node - NENC)) * HDIM + h];
    __nv_bfloat16 hi = __float2bfloat16(x);
    float lo = x - __bfloat162float(hi);
    __nv_bfloat16* row = A + (size_t)m * KEXT;
    row[h] = hi;
    row[512 + h] = hi;
    row[1024 + h] = __float2bfloat16(lo);
}

__global__ void k_aextT(const float* __restrict__ Tb, __nv_bfloat16* __restrict__ A) {
    size_t i = (size_t)blockIdx.x * 256 + threadIdx.x;
    if (i >= (size_t)4 * B * HDIM) return;
    int m = (int)(i >> 9);
    int h = (int)(i & 511);
    int j = m >> 8, b = m & 255;
    float x = Tb[((size_t)b * 4 + j) * HDIM + h];
    __nv_bfloat16 hi = __float2bfloat16(x);
    float lo = x - __bfloat162float(hi);
    __nv_bfloat16* row = A + (size_t)((62 + j) * B + b) * KEXT;
    row[h] = hi;
    row[512 + h] = hi;
    row[1024 + h] = __float2bfloat16(lo);
}

// ---------------- B_ext builder (bf16 split [hi|lo|hi]) ----------------
__global__ void k_bext(const float* __restrict__ basis, const float* __restrict__ selfW,
                       __nv_bfloat16* __restrict__ Bm) {
    size_t i = (size_t)blockIdx.x * 256 + threadIdx.x;
    if (i >= (size_t)KDIM * HDIM) return;
    int n = (int)(i >> 9);
    int k = (int)(i & 511);
    float w;
    if (n < 3072) {
        int q = n >> 9, j = n & 511;
        w = basis[((size_t)q * 512 + k) * 512 + j];
    } else {
        w = selfW[(size_t)(n - 3072) * 512 + k];
    }
    __nv_bfloat16 hi = __float2bfloat16(w);
    float lo = w - __bfloat162float(hi);
    __nv_bfloat16* row = Bm + (size_t)n * KEXT;
    row[k] = hi;
    row[512 + k] = __float2bfloat16(lo);
    row[1024 + k] = hi;
}

// ---------------- Y-GEMM mma.sync: emits YH/YL bf16 (q-part) + fp32 C (self part) ----------------
#define KT 32
#define STAGES 4
#define ASTRIDE 40
#define STAGE_ELT (128 * ASTRIDE)
#define STAGE_BYTES (STAGE_ELT * 2)

__global__ __launch_bounds__(256, 2)
void k_mma(const __nv_bfloat16* __restrict__ A, const __nv_bfloat16* __restrict__ Bm,
           float* __restrict__ C, __nv_bfloat16* __restrict__ YHp,
           __nv_bfloat16* __restrict__ YLp, int Mbase) {
    extern __shared__ __align__(16) __nv_bfloat16 sm[];
    int tid = threadIdx.x;
    int wid = tid >> 5, lane = tid & 31;
    int m0 = Mbase + blockIdx.x * 128;
    int n0 = blockIdx.y * 128;
    int wm = (wid & 3) * 32;
    int wn = (wid >> 2) * 64;

    uint32_t sA0 = smem_u32(sm);
    uint32_t sB0 = sA0 + STAGES * STAGE_BYTES;

    const __nv_bfloat16* Ag = A + (size_t)m0 * KEXT;
    const __nv_bfloat16* Bg = Bm + (size_t)n0 * KEXT;

    int r0l = (tid + 0) >> 2,   c0l = (tid + 0) & 3;
    int r1l = (tid + 256) >> 2, c1l = (tid + 256) & 3;

    float acc[2][8][4];
#pragma unroll
    for (int i = 0; i < 2; i++)
#pragma unroll
        for (int j = 0; j < 8; j++)
#pragma unroll
            for (int k = 0; k < 4; k++) acc[i][j][k] = 0.f;

#pragma unroll
    for (int s = 0; s < STAGES - 1; s++) {
        int kt = s * KT;
        cp16(sA0 + s * STAGE_BYTES + (r0l * ASTRIDE + c0l * 8) * 2, Ag + (size_t)r0l * KEXT + kt + c0l * 8);
        cp16(sA0 + s * STAGE_BYTES + (r1l * ASTRIDE + c1l * 8) * 2, Ag + (size_t)r1l * KEXT + kt + c1l * 8);
        cp16(sB0 + s * STAGE_BYTES + (r0l * ASTRIDE + c0l * 8) * 2, Bg + (size_t)r0l * KEXT + kt + c0l * 8);
        cp16(sB0 + s * STAGE_BYTES + (r1l * ASTRIDE + c1l * 8) * 2, Bg + (size_t)r1l * KEXT + kt + c1l * 8);
        CP_COMMIT();
    }

    int a_row = wm + (lane & 15);
    int a_koff = (lane >> 4) * 8;
    int b_row = wn + ((lane >> 4) * 8) + (lane & 7);
    int b_koff = ((lane >> 3) & 1) * 8;

    const int KITER = KEXT / KT;
    for (int it = 0; it < KITER; it++) {
        int s = it % STAGES;
        CP_WAIT(STAGES - 2);
        __syncthreads();

        uint32_t aBase = sA0 + s * STAGE_BYTES;
        uint32_t bBase = sB0 + s * STAGE_BYTES;
#pragma unroll
        for (int kk = 0; kk < 2; kk++) {
            uint32_t af[2][4];
#pragma unroll
            for (int mt = 0; mt < 2; mt++) {
                uint32_t addr = aBase + ((a_row + mt * 16) * ASTRIDE + kk * 16 + a_koff) * 2;
                ldsm_x4(af[mt][0], af[mt][1], af[mt][2], af[mt][3], addr);
            }
#pragma unroll
            for (int np = 0; np < 4; np++) {
                uint32_t b0, b1, b2, b3;
                uint32_t addr = bBase + ((b_row + np * 16) * ASTRIDE + kk * 16 + b_koff) * 2;
                ldsm_x4(b0, b1, b2, b3, addr);
#pragma unroll
                for (int mt = 0; mt < 2; mt++) {
                    mma16816(acc[mt][np * 2],     af[mt], b0, b1);
                    mma16816(acc[mt][np * 2 + 1], af[mt], b2, b3);
                }
            }
        }
        int nit = it + STAGES - 1;
        if (nit < KITER) {
            int ns = nit % STAGES;
            int kt = nit * KT;
            cp16(sA0 + ns * STAGE_BYTES + (r0l * ASTRIDE + c0l * 8) * 2, Ag + (size_t)r0l * KEXT + kt + c0l * 8);
            cp16(sA0 + ns * STAGE_BYTES + (r1l * ASTRIDE + c1l * 8) * 2, Ag + (size_t)r1l * KEXT + kt + c1l * 8);
            cp16(sB0 + ns * STAGE_BYTES + (r0l * ASTRIDE + c0l * 8) * 2, Bg + (size_t)r0l * KEXT + kt + c0l * 8);
            cp16(sB0 + ns * STAGE_BYTES + (r1l * ASTRIDE + c1l * 8) * 2, Bg + (size_t)r1l * KEXT + kt + c1l * 8);
        }
        CP_COMMIT();
    }

    // epilogue
    int crow = m0 + wm + (lane >> 2);
    int ccol = wn + (lane & 3) * 2;
    bool selfPart = (n0 >= 3072);
#pragma unroll
    for (int mt = 0; mt < 2; mt++) {
#pragma unroll
        for (int nt = 0; nt < 8; nt++) {
            int r1 = crow + mt * 16;
            int r2 = r1 + 8;
            int cl = ccol + nt * 8;
            int gc = n0 + cl;
            float2 v01; v01.x = acc[mt][nt][0]; v01.y = acc[mt][nt][1];
            float2 v23; v23.x = acc[mt][nt][2]; v23.y = acc[mt][nt][3];
            if (selfPart) {
                *(float2*)(C + (size_t)r1 * KDIM + gc) = v01;
                *(float2*)(C + (size_t)r2 * KDIM + gc) = v23;
            } else {
                __nv_bfloat16 h0 = __float2bfloat16(v01.x);
                __nv_bfloat16 h1 = __float2bfloat16(v01.y);
                __nv_bfloat16 h2 = __float2bfloat16(v23.x);
                __nv_bfloat16 h3 = __float2bfloat16(v23.y);
                __nv_bfloat162 hp1; hp1.x = h0; hp1.y = h1;
                __nv_bfloat162 hp2; hp2.x = h2; hp2.y = h3;
                __nv_bfloat162 lp1;
                lp1.x = __float2bfloat16(v01.x - __bfloat162float(h0));
                lp1.y = __float2bfloat16(v01.y - __bfloat162float(h1));
                __nv_bfloat162 lp2;
                lp2.x = __float2bfloat16(v23.x - __bfloat162float(h2));
                lp2.y = __float2bfloat16(v23.y - __bfloat162float(h3));
                *(__nv_bfloat162*)(YHp + (size_t)r1 * 3072 + gc) = hp1;
                *(__nv_bfloat162*)(YHp + (size_t)r2 * 3072 + gc) = hp2;
                *(__nv_bfloat162*)(YLp + (size_t)r1 * 3072 + gc) = lp1;
                *(__nv_bfloat162*)(YLp + (size_t)r2 * 3072 + gc) = lp2;
            }
        }
    }
}

// ---------------- combine via mma.sync: Z = relu(AC_split @ Y_split + Y_self) ----------------
#define BSTR 264
#define CSTG 4
template<int S, int RG>
__global__ __launch_bounds__(256, 2)
void k_combine_mma(const __nv_bfloat16* __restrict__ AE,
                   const __nv_bfloat16* __restrict__ YHp,
                   const __nv_bfloat16* __restrict__ YLp,
                   const float* __restrict__ Yf,
                   float* __restrict__ Z) {
    constexpr int KC = 6 * S;
    constexpr int KE = (S == 62) ? 1120 : 1152;
    constexpr int KIT = KE / 32;
    constexpr int RPB = KE * 8;
    extern __shared__ char dyn[];
    ull* rp = (ull*)dyn;
    uint32_t aOff = smem_u32(dyn) + RPB;
    uint32_t bOff = aOff + CSTG * 5120;

    int tid = threadIdx.x, wid = tid >> 5, lane = tid & 31;
    int b = blockIdx.y;
    int n0c = blockIdx.x * 256;

    for (int k = tid; k < KE; k += 256) {
        int p = k / KC, r = k - p * KC;
        if (p > 2) { p = 0; r = 0; }
        int q = r / S, m = r - q * S;
        int node = (RG == 1) ? m : (m < 58 ? m : (m < 62 ? 62 + (m - 58) : 61));
        const __nv_bfloat16* src = (p == 1) ? YLp : YHp;
        rp[k] = (ull)(src + ((size_t)node * B + b) * 3072 + q * 512 + n0c);
    }
    __syncthreads();

    const __nv_bfloat16* Ab = AE + (size_t)b * 64 * KE;
    int arow = tid >> 2, ac = tid & 3;

    float acc[2][8][4];
#pragma unroll
    for (int i = 0; i < 2; i++)
#pragma unroll
        for (int j = 0; j < 8; j++)
#pragma unroll
            for (int k = 0; k < 4; k++) acc[i][j][k] = 0.f;

#pragma unroll
    for (int s = 0; s < CSTG - 1; s++) {
        int kt = s * 32;
        cp16(aOff + s * 5120 + (arow * ASTRIDE + ac * 8) * 2, Ab + (size_t)arow * KE + kt + ac * 8);
#pragma unroll
        for (int j = 0; j < 4; j++) {
            int i = tid + j * 256;
            int kr = i >> 5, c = i & 31;
            cp16(bOff + s * 16896 + (kr * BSTR + c * 8) * 2, (const char*)rp[kt + kr] + c * 16);
        }
        CP_COMMIT();
    }

    int wm = (wid & 1) * 32, wn = (wid >> 1) * 64;
    int a_row = wm + (lane & 15);
    int a_koff = (lane >> 4) * 8;
    int grp = lane >> 3, lrow = lane & 7;

    for (int it = 0; it < KIT; it++) {
        CP_WAIT(CSTG - 2);
        __syncthreads();
        uint32_t aB = aOff + (it % CSTG) * 5120;
        uint32_t bB = bOff + (it % CSTG) * 16896;
#pragma unroll
        for (int kk = 0; kk < 2; kk++) {
            uint32_t af[2][4];
#pragma unroll
            for (int mt = 0; mt < 2; mt++) {
                uint32_t addr = aB + ((a_row + mt * 16) * ASTRIDE + kk * 16 + a_koff) * 2;
                ldsm_x4(af[mt][0], af[mt][1], af[mt][2], af[mt][3], addr);
            }
#pragma unroll
            for (int np = 0; np < 4; np++) {
                uint32_t b0, b1, b2, b3;
                uint32_t addr = bB + ((kk * 16 + (grp & 1) * 8 + lrow) * BSTR
                                      + wn + np * 16 + (grp >> 1) * 8) * 2;
                ldsm_x4_t(b0, b1, b2, b3, addr);
#pragma unroll
                for (int mt = 0; mt < 2; mt++) {
                    mma16816(acc[mt][np * 2],     af[mt], b0, b1);
                    mma16816(acc[mt][np * 2 + 1], af[mt], b2, b3);
                }
            }
        }
        int nit = it + CSTG - 1;
        if (nit < KIT) {
            int ns = nit % CSTG;
            int kt = nit * 32;
            cp16(aOff + ns * 5120 + (arow * ASTRIDE + ac * 8) * 2, Ab + (size_t)arow * KE + kt + ac * 8);
#pragma unroll
            for (int j = 0; j < 4; j++) {
                int i = tid + j * 256;
                int kr = i >> 5, c = i & 31;
                cp16(bOff + ns * 16896 + (kr * BSTR + c * 8) * 2, (const char*)rp[kt + kr] + c * 16);
            }
        }
        CP_COMMIT();
    }

    int crow = wm + (lane >> 2);
    int ccol = wn + (lane & 3) * 2;
#pragma unroll
    for (int mt = 0; mt < 2; mt++) {
#pragma unroll
        for (int nt = 0; nt < 8; nt++) {
            int g = n0c + ccol + nt * 8;
#pragma unroll
            for (int half = 0; half < 2; half++) {
                int n = crow + mt * 16 + half * 8;
                float x = acc[mt][nt][half * 2];
                float y = acc[mt][nt][half * 2 + 1];
                if (n < S) {
                    int node = (RG == 1) ? n : (n < 58 ? n : (n < 62 ? 62 + (n - 58) : 61));
                    const float* sp = Yf + ((size_t)node * B + b) * KDIM + 3072 + g;
                    float2 o;
                    o.x = fmaxf(x + sp[0], 0.f);
                    o.y = fmaxf(y + sp[1], 0.f);
                    *(float2*)(Z + ((size_t)b * S + n) * 512 + g) = o;
                }
            }
        }
    }
}

// ---------------- layer-2 message aggregation (fp32) ----------------
__global__ void k_msg(const float* __restrict__ ACm, const float* __restrict__ X,
                      float* __restrict__ F, int nodes, int nRows, int rowBase, int rowStride) {
    int b = blockIdx.y, i = blockIdx.x;
    int row = rowBase + i * rowStride;
    __shared__ __align__(16) ull sA[NQ][64];
    int t = threadIdx.x;
    for (int e = t; e < NQ * nodes; e += 256) {
        int q = e / nodes, m = e % nodes;
        float a = ACm[(((size_t)b * NQ + q) * nodes + row) * nodes + m];
        sA[q][m] = dup2(a);
    }
    __syncthreads();
    ull acc[NQ] = {0ULL, 0ULL, 0ULL, 0ULL, 0ULL, 0ULL};
    const float* xb = X + (size_t)b * nodes * HDIM;
    int h = t * 2;
    for (int m = 0; m < nodes; m++) {
        ull xv = *(const ull*)(xb + (size_t)m * HDIM + h);
#pragma unroll
        for (int q = 0; q < NQ; q++) fma2(acc[q], sA[q][m], xv);
    }
    float* Fp = F + ((size_t)b * nRows + i) * KDIM;
#pragma unroll
    for (int q = 0; q < NQ; q++)
        *(ull*)(Fp + q * HDIM + h) = acc[q];
    *(ull*)(Fp + 3072 + h) = *(const ull*)(xb + (size_t)row * HDIM + h);
}

// ---------------- fp32 SGEMM tile 64x64 (layer-2): C = sigmoid(A @ Bw) ----------------
__global__ __launch_bounds__(256)
void k_gemm64(const float* __restrict__ A, const float* __restrict__ Bw,
              float* __restrict__ C, int K, int lda, int ldn) {
    __shared__ __align__(16) float As[16][64];
    __shared__ __align__(16) float Bs[16][68];
    int tid = threadIdx.x;
    int mb = blockIdx.x * 64, nb = blockIdx.y * 64;

    int arow = tid >> 2, ak = (tid & 3) * 4;
    int bk = tid >> 4, bn4 = (tid & 15) * 4;
    const float* Aptr = A + (size_t)(mb + arow) * lda + ak;
    const float* Bptr = Bw + (size_t)bk * ldn + nb + bn4;

    int tx = tid & 15, ty = tid >> 4;
    int r0 = ty * 4, c0 = tx * 4;

    ull acc[4][2];
#pragma unroll
    for (int i = 0; i < 4; i++) { acc[i][0] = 0ULL; acc[i][1] = 0ULL; }

    for (int kt = 0; kt < K; kt += 16) {
        float4 av = *(const float4*)(Aptr + kt);
        float4 bv = *(const float4*)(Bptr + (size_t)kt * ldn);
        As[ak + 0][arow] = av.x;
        As[ak + 1][arow] = av.y;
        As[ak + 2][arow] = av.z;
        As[ak + 3][arow] = av.w;
        *(float4*)&Bs[bk][bn4] = bv;
        __syncthreads();
#pragma unroll
        for (int k = 0; k < 16; k++) {
            float4 a4 = *(const float4*)&As[k][r0];
            ulonglong2 b2 = *(const ulonglong2*)&Bs[k][c0];
            float aa[4] = {a4.x, a4.y, a4.z, a4.w};
#pragma unroll
            for (int i = 0; i < 4; i++) {
                ull ad = dup2(aa[i]);
                fma2(acc[i][0], ad, b2.x);
                fma2(acc[i][1], ad, b2.y);
            }
        }
        __syncthreads();
    }

#pragma unroll
    for (int i = 0; i < 4; i++) {
        float* Cp = C + (size_t)(mb + r0 + i) * ldn + nb + c0;
        float l0, h0, l1, h1;
        unpack2(acc[i][0], l0, h0);
        unpack2(acc[i][1], l1, h1);
        float4 o;
        o.x = 1.f / (1.f + expf(-l0));
        o.y = 1.f / (1.f + expf(-h0));
        o.z = 1.f / (1.f + expf(-l1));
        o.w = 1.f / (1.f + expf(-h1));
        *(float4*)Cp = o;
    }
}

// ---------------- final logits ----------------
__global__ void k_logits(const float* __restrict__ U, const float* __restrict__ tW,
                         const float* __restrict__ tb, float* __restrict__ out) {
    int b = blockIdx.x;
    int w = threadIdx.x >> 5, lane = threadIdx.x & 31;
    if (w >= 11) return;
    const float* black = U + ((size_t)b * 2 + 1) * HDIM;
    const float* white = U + ((size_t)b * 2 + 0) * HDIM;
    const float* row = tW + w * 1024;
    float s = 0.f;
    for (int j = lane; j < HDIM; j += 32)
        s += black[j] * row[j] + white[j] * row[HDIM + j];
#pragma unroll
    for (int o = 16; o; o >>= 1) s += __shfl_down_sync(0xffffffffu, s, o);
    if (lane == 0) out[b * 11 + w] = s + tb[w];
}

// ---------------- host ----------------
extern "C" void kernel_launch(void* const* d_in, const int* in_sizes, int n_in,
                              void* d_out, int out_size) {
    int s = (n_in >= 21 && in_sizes[1] == 1) ? 1 : 0;

    const int*   player = (const int*)d_in[0];
    const float* enc    = (const float*)d_in[1 + s];
    const int*   adj    = (const int*)d_in[2 + s];
    const float* Ax     = (const float*)d_in[3 + s];
    const float* Ay     = (const float*)d_in[4 + s];
    const float* Bx     = (const float*)d_in[5 + s];
    const float* By     = (const float*)d_in[6 + s];
    const float* emb    = (const float*)d_in[7 + s];
    const float* coordW = (const float*)d_in[8 + s];
    const float* coordB = (const float*)d_in[9 + s];
    const float* inW    = (const float*)d_in[10 + s];
    const float* inB    = (const float*)d_in[11 + s];
    const float* basis0 = (const float*)d_in[12 + s];
    const float* comb0  = (const float*)d_in[13 + s];
    const float* self0  = (const float*)d_in[14 + s];
    const float* basis1 = (const float*)d_in[15 + s];
    const float* comb1  = (const float*)d_in[16 + s];
    const float* self1  = (const float*)d_in[17 + s];
    const float* typeW  = (const float*)d_in[18 + s];
    const float* typeB  = (const float*)d_in[19 + s];

    float* base = nullptr;
    cudaGetSymbolAddress((void**)&base, g_scratch);
    float* CW1  = base;
    float* INIT = base + 1835008;
    float* Y    = base + 2129920;
    float* Z1   = base + 62685184;
    float* Z2   = base + 70811648;
    float* Tb   = base + 79069184;
    float* U    = base + 79593472;
    float* AC1m = base + 79855616;
    float* AC2m = base + 85760000;
    float* F    = base + 91856384;
    __nv_bfloat16* AEXT = (__nv_bfloat16*)(base + 95526400);
    __nv_bfloat16* BEXT = (__nv_bfloat16*)(base + 108502528);
    __nv_bfloat16* YH   = (__nv_bfloat16*)(base + 111255040);
    __nv_bfloat16* YL   = (__nv_bfloat16*)(base + 137207296);
    __nv_bfloat16* A1E  = (__nv_bfloat16*)(base + 163159552);
    __nv_bfloat16* A2E  = (__nv_bfloat16*)(base + 172334592);

    const int mma_smem = 2 * STAGES * STAGE_BYTES;           // 81920
    const int c1_smem = 1120 * 8 + CSTG * (5120 + 16896);    // 97024
    const int c2_smem = 1152 * 8 + CSTG * (5120 + 16896);    // 97280

    static cudaStream_t s2 = nullptr;
    static cudaEvent_t evA = nullptr, evB = nullptr, evC = nullptr;
    static int once = 0;
    if (!once) {
        cudaFuncSetAttribute(k_mma, cudaFuncAttributeMaxDynamicSharedMemorySize, mma_smem);
        cudaFuncSetAttribute(k_combine_mma<62, 1>, cudaFuncAttributeMaxDynamicSharedMemorySize, c1_smem);
        cudaFuncSetAttribute(k_combine_mma<63, 2>, cudaFuncAttributeMaxDynamicSharedMemorySize, c2_smem);
        cudaStreamCreateWithFlags(&s2, cudaStreamNonBlocking);
        cudaEventCreateWithFlags(&evA, cudaEventDisableTiming);
        cudaEventCreateWithFlags(&evB, cudaEventDisableTiming);
        cudaEventCreateWithFlags(&evC, cudaEventDisableTiming);
        once = 1;
    }

    // fork side stream from the capture (default) stream
    cudaEventRecord(evA, 0);
    cudaStreamWaitEvent(s2, evA, 0);

    // side stream: BEXT (independent of everything)               launch #1
    k_bext<<<(KDIM * HDIM + 255) / 256, 256, 0, s2>>>(basis0, self0, BEXT);
    cudaEventRecord(evB, s2);

    // main stream: INIT + AEXT                                    launches #2, #3
    k_init<<<dim3(8, 8), 256>>>(player, Ax, Ay, Bx, By, emb, coordW, coordB, inW, inB, INIT);
    k_aext<<<(62 * B * HDIM + 255) / 256, 256>>>(enc, INIT, AEXT);

    // join BEXT, then the big Y projection                        launch #4 (ncu profiles this)
    cudaStreamWaitEvent(0, evB, 0);
    k_mma<<<dim3(62 * B / 128, KDIM / 128), 256, mma_smem>>>(AEXT, BEXT, Y, YH, YL, 0);

    // side stream overlaps prep with the Y projection
    k_ac1<<<dim3(B, 16), 256, 0, s2>>>(adj, comb0, comb1, A1E, AC1m);
    k_ac2<<<dim3(B, 16), 256, 0, s2>>>(adj, comb0, comb1, A2E, AC2m);
    k_build_cw1<<<(KDIM * HDIM + 255) / 256, 256, 0, s2>>>(basis1, self1, CW1);
    cudaEventRecord(evC, s2);
    cudaStreamWaitEvent(0, evC, 0);

    // rgcn1 layer1 combine (mma) -> Z1
    k_combine_mma<62, 1><<<dim3(2, B), 256, c1_smem>>>(A1E, YH, YL, Y, Z1);
    // rgcn1 layer2 (rows 58..61) -> Tb
    k_msg<<<dim3(4, B), 256>>>(AC1m, Z1, F, S1, 4, 58, 1);
    k_gemm64<<<dim3(4 * B / 64, HDIM / 64), 256>>>(F, CW1, Tb, KDIM, KDIM, HDIM);

    // T nodes -> AEXT rows 62..65, project
    k_aextT<<<(4 * B * HDIM + 255) / 256, 256>>>(Tb, AEXT);
    k_mma<<<dim3(4 * B / 128, KDIM / 128), 256, mma_smem>>>(AEXT, BEXT, Y, YH, YL, 62 * B);

    // rgcn2 layer1 combine (mma) -> Z2
    k_combine_mma<63, 2><<<dim3(2, B), 256, c2_smem>>>(A2E, YH, YL, Y, Z2);
    // rgcn2 layer2 (rows 60, 62) -> U
    k_msg<<<dim3(2, B), 256>>>(AC2m, Z2, F, S2, 2, 60, 2);
    k_gemm64<<<dim3(2 * B / 64, HDIM / 64), 256>>>(F, CW1, U, KDIM, KDIM, HDIM);

    k_logits<<<B, 352>>>(U, typeW, typeB, (float*)d_out);
}

// round 9
// speedup vs baseline: 3.9267x; 1.0639x over previous
#include <cuda_runtime.h>
#include <cuda_bf16.h>
#include <math.h>
#include <stdint.h>

#define B      256
#define HDIM   512
#define NENC   60
#define S1     62
#define S2     63
#define NQ     6
#define KDIM   3584      // 6*512 + 512
#define KEXT   1536      // Y-GEMM split K (hi|hi|lo x hi|lo|hi)

typedef unsigned long long ull;

// ---------------- scratch (float offsets) ----------------
static __device__ float g_scratch[181771776];

// ---------------- helpers ----------------
__device__ __forceinline__ ull dup2(float a) {
    ull d; asm("mov.b64 %0, {%1, %1};" : "=l"(d) : "f"(a)); return d;
}
__device__ __forceinline__ void fma2(ull &acc, ull a, ull b) {
    asm("fma.rn.f32x2 %0, %1, %2, %0;" : "+l"(acc) : "l"(a), "l"(b));
}
__device__ __forceinline__ void unpack2(ull v, float &lo, float &hi) {
    asm("mov.b64 {%0, %1}, %2;" : "=f"(lo), "=f"(hi) : "l"(v));
}
__device__ __forceinline__ uint32_t smem_u32(const void* p) {
    uint32_t a;
    asm("{ .reg .u64 t; cvta.to.shared.u64 t, %1; cvt.u32.u64 %0, t; }" : "=r"(a) : "l"(p));
    return a;
}
__device__ __forceinline__ void cp16(uint32_t s, const void* g) {
    asm volatile("cp.async.cg.shared.global [%0], [%1], 16;" :: "r"(s), "l"(g));
}
#define CP_COMMIT() asm volatile("cp.async.commit_group;" ::: "memory")
#define CP_WAIT(n)  asm volatile("cp.async.wait_group %0;" :: "n"(n) : "memory")

__device__ __forceinline__ void ldsm_x4(uint32_t &r0, uint32_t &r1, uint32_t &r2, uint32_t &r3, uint32_t addr) {
    asm volatile("ldmatrix.sync.aligned.m8n8.x4.shared.b16 {%0,%1,%2,%3}, [%4];"
        : "=r"(r0), "=r"(r1), "=r"(r2), "=r"(r3) : "r"(addr));
}
__device__ __forceinline__ void ldsm_x4_t(uint32_t &r0, uint32_t &r1, uint32_t &r2, uint32_t &r3, uint32_t addr) {
    asm volatile("ldmatrix.sync.aligned.m8n8.x4.trans.shared.b16 {%0,%1,%2,%3}, [%4];"
        : "=r"(r0), "=r"(r1), "=r"(r2), "=r"(r3) : "r"(addr));
}
__device__ __forceinline__ void mma16816(float* d, const uint32_t* a, uint32_t b0, uint32_t b1) {
    asm volatile("mma.sync.aligned.m16n8k16.row.col.f32.bf16.bf16.f32 "
        "{%0,%1,%2,%3}, {%4,%5,%6,%7}, {%8,%9}, {%0,%1,%2,%3};"
        : "+f"(d[0]), "+f"(d[1]), "+f"(d[2]), "+f"(d[3])
        : "r"(a[0]), "r"(a[1]), "r"(a[2]), "r"(a[3]), "r"(b0), "r"(b1));
}

// ---------------- CW1 (layer-2 weight, fp32 [K][N]) ----------------
__global__ void k_build_cw1(const float* __restrict__ basis, const float* __restrict__ selfW,
                            float* __restrict__ CW) {
    int idx = blockIdx.x * 256 + threadIdx.x;
    if (idx >= KDIM * HDIM) return;
    int row = idx >> 9;
    int k   = idx & 511;
    CW[idx] = (row < 3072) ? basis[idx] : selfW[(size_t)k * HDIM + (row - 3072)];
}

// ---------------- AC builders: bf16 split combine operand + fp32 msg layout ----------------
__global__ void k_ac1(const int* __restrict__ adj, const float* __restrict__ comb0,
                      const float* __restrict__ comb1, __nv_bfloat16* __restrict__ AE,
                      float* __restrict__ ACm) {
    __shared__ float sc[2][12][6];
    int t = threadIdx.x;
    if (t < 72) { sc[0][t / 6][t % 6] = comb0[t]; sc[1][t / 6][t % 6] = comb1[t]; }
    __syncthreads();
    int b = blockIdx.x;
    int e = blockIdx.y * 256 + t;
    if (e >= 64 * S1) return;
    int n = e / S1, m = e % S1;
    __nv_bfloat16* rowA = AE + ((size_t)b * 64 + n) * 1120;
    if (m < 4) rowA[1116 + m] = __float2bfloat16(0.f);
    bool valid = (n < S1);
    float a[12];
#pragma unroll
    for (int r = 0; r < 12; r++)
        a[r] = valid ? (float)adj[(((size_t)b * 13 + r + 1) * S1 + n) * S1 + m] : 0.f;
#pragma unroll
    for (int q = 0; q < NQ; q++) {
        float s0 = 0.f, s1 = 0.f;
#pragma unroll
        for (int r = 0; r < 12; r++) { s0 += sc[0][r][q] * a[r]; s1 += sc[1][r][q] * a[r]; }
        __nv_bfloat16 hi = __float2bfloat16(s0);
        float lo = s0 - __bfloat162float(hi);
        int c = q * S1 + m;
        rowA[c] = hi;
        rowA[372 + c] = hi;
        rowA[744 + c] = __float2bfloat16(lo);
        if (valid)
            ACm[(((size_t)b * NQ + q) * S1 + n) * S1 + m] = s1;
    }
}

__global__ void k_ac2(const int* __restrict__ adj, const float* __restrict__ comb0,
                      const float* __restrict__ comb1, __nv_bfloat16* __restrict__ AE,
                      float* __restrict__ ACm) {
    __shared__ float sc[2][12][6];
    int t = threadIdx.x;
    if (t < 72) { sc[0][t / 6][t % 6] = comb0[t]; sc[1][t / 6][t % 6] = comb1[t]; }
    __syncthreads();
    int b = blockIdx.x;
    int e = blockIdx.y * 256 + t;
    if (e >= 64 * S2) return;
    int n = e / S2, m = e % S2;
    __nv_bfloat16* rowA = AE + ((size_t)b * 64 + n) * 1152;
    if (m < 18) rowA[1134 + m] = __float2bfloat16(0.f);
    bool valid = (n < S2);
    int oi = (n == 62) ? 63 : n;
    int oj = (m == 62) ? 63 : m;
    float a[12];
#pragma unroll
    for (int r = 0; r < 12; r++) {
        int v = 0;
        if (valid && oi < 62 && oj < 62)
            v = adj[(((size_t)b * 13 + r + 1) * S1 + oi) * S1 + oj];
        a[r] = (float)v;
    }
    if (valid) {
        int lo2 = min(oi, oj), hi2 = max(oi, oj);
        if (hi2 - lo2 == 2) {
            int ni = lo2 >> 1;
            int ch = ((lo2 & 1) == 0) ? ((ni & 1) ? 12 : 11) : ((ni & 1) ? 11 : 12);
            a[ch - 1] = 1.f;
        }
    }
#pragma unroll
    for (int q = 0; q < NQ; q++) {
        float s0 = 0.f, s1 = 0.f;
#pragma unroll
        for (int r = 0; r < 12; r++) { s0 += sc[0][r][q] * a[r]; s1 += sc[1][r][q] * a[r]; }
        __nv_bfloat16 hi = __float2bfloat16(s0);
        float lo = s0 - __bfloat162float(hi);
        int c = q * S2 + m;
        rowA[c] = hi;
        rowA[378 + c] = hi;
        rowA[756 + c] = __float2bfloat16(lo);
        if (valid)
            ACm[(((size_t)b * NQ + q) * S2 + n) * S2 + m] = s1;
    }
}

// ---------------- initial embedding (fused feature + GEMM) ----------------
__global__ __launch_bounds__(256)
void k_init(const int* __restrict__ player,
            const float* __restrict__ Ax, const float* __restrict__ Ay,
            const float* __restrict__ Bx, const float* __restrict__ By,
            const float* __restrict__ emb, const float* __restrict__ cW,
            const float* __restrict__ cb, const float* __restrict__ inW,
            const float* __restrict__ inb, float* __restrict__ INIT) {
    __shared__ __align__(16) float As[64][65];
    __shared__ __align__(16) float Bs[64][65];
    int t = threadIdx.x;
    int mb = blockIdx.x * 64, hb = blockIdx.y * 64;
#pragma unroll
    for (int j = 0; j < 16; j++) {
        int i = t + j * 256;
        int r = i >> 6, c = i & 63;
        int m = mb + r;
        int b = m >> 1, p = m & 1;
        float v;
        if (c < 32) {
            float x = p ? Bx[b] : Ax[b];
            float y = p ? By[b] : Ay[b];
            v = fmaxf(cW[c * 2] * x + cW[c * 2 + 1] * y + cb[c], 0.f);
        } else {
            v = emb[player[b * 2 + p] * 32 + (c - 32)];
        }
        As[r][c] = v;
        Bs[r][c] = inW[(hb + r) * 64 + c];
    }
    __syncthreads();
    int tx = t & 15, ty = t >> 4;
    int r0 = ty * 4, c0 = tx * 4;
    float acc[4][4] = {};
    for (int k = 0; k < 64; k++) {
        float av[4], bv[4];
#pragma unroll
        for (int i = 0; i < 4; i++) av[i] = As[r0 + i][k];
#pragma unroll
        for (int j = 0; j < 4; j++) bv[j] = Bs[c0 + j][k];
#pragma unroll
        for (int i = 0; i < 4; i++)
#pragma unroll
            for (int j = 0; j < 4; j++) acc[i][j] += av[i] * bv[j];
    }
#pragma unroll
    for (int i = 0; i < 4; i++)
#pragma unroll
        for (int j = 0; j < 4; j++)
            INIT[(size_t)(mb + r0 + i) * 512 + hb + c0 + j] = acc[i][j] + inb[hb + c0 + j];
}

// ---------------- A_ext builders (bf16 split [hi|hi|lo]) ----------------
__global__ void k_aext(const float* __restrict__ enc, const float* __restrict__ init,
                       __nv_bfloat16* __restrict__ A) {
    size_t i = (size_t)blockIdx.x * 256 + threadIdx.x;
    if (i >= (size_t)62 * B * HDIM) return;
    int m = (int)(i >> 9);
    int h = (int)(i & 511);
    int node = m >> 8, b = m & 255;
    float x = (node < NENC) ? enc[((size_t)b * NENC + node) * HDIM + h]
                            : init[((size_t)b * 2 + (node - NENC)) * HDIM + h];
    __nv_bfloat16 hi = __float2bfloat16(x);
    float lo = x - __bfloat162float(hi);
    __nv_bfloat16* row = A + (size_t)m * KEXT;
    row[h] = hi;
    row[512 + h] = hi;
    row[1024 + h] = __float2bfloat16(lo);
}

__global__ void k_aextT(const float* __restrict__ Tb, __nv_bfloat16* __restrict__ A) {
    size_t i = (size_t)blockIdx.x * 256 + threadIdx.x;
    if (i >= (size_t)4 * B * HDIM) return;
    int m = (int)(i >> 9);
    int h = (int)(i & 511);
    int j = m >> 8, b = m & 255;
    float x = Tb[((size_t)b * 4 + j) * HDIM + h];
    __nv_bfloat16 hi = __float2bfloat16(x);
    float lo = x - __bfloat162float(hi);
    __nv_bfloat16* row = A + (size_t)((62 + j) * B + b) * KEXT;
    row[h] = hi;
    row[512 + h] = hi;
    row[1024 + h] = __float2bfloat16(lo);
}

// ---------------- B_ext builder (bf16 split [hi|lo|hi]) ----------------
__global__ void k_bext(const float* __restrict__ basis, const float* __restrict__ selfW,
                       __nv_bfloat16* __restrict__ Bm) {
    size_t i = (size_t)blockIdx.x * 256 + threadIdx.x;
    if (i >= (size_t)KDIM * HDIM) return;
    int n = (int)(i >> 9);
    int k = (int)(i & 511);
    float w;
    if (n < 3072) {
        int q = n >> 9, j = n & 511;
        w = basis[((size_t)q * 512 + k) * 512 + j];
    } else {
        w = selfW[(size_t)(n - 3072) * 512 + k];
    }
    __nv_bfloat16 hi = __float2bfloat16(w);
    float lo = w - __bfloat162float(hi);
    __nv_bfloat16* row = Bm + (size_t)n * KEXT;
    row[k] = hi;
    row[512 + k] = __float2bfloat16(lo);
    row[1024 + k] = hi;
}

// ---------------- Y-GEMM mma.sync: 4 warps x (64x64) tile, 128 threads ----------------
#define KT 32
#define STAGES 4
#define ASTRIDE 40
#define STAGE_ELT (128 * ASTRIDE)
#define STAGE_BYTES (STAGE_ELT * 2)

__global__ __launch_bounds__(128, 2)
void k_mma(const __nv_bfloat16* __restrict__ A, const __nv_bfloat16* __restrict__ Bm,
           float* __restrict__ C, __nv_bfloat16* __restrict__ YHp,
           __nv_bfloat16* __restrict__ YLp, int Mbase) {
    extern __shared__ __align__(16) __nv_bfloat16 sm[];
    int tid = threadIdx.x;          // 0..127
    int wid = tid >> 5, lane = tid & 31;
    int m0 = Mbase + blockIdx.x * 128;
    int n0 = blockIdx.y * 128;
    int wm = (wid & 1) * 64;        // warp tile 64x64
    int wn = (wid >> 1) * 64;

    uint32_t sA0 = smem_u32(sm);
    uint32_t sB0 = sA0 + STAGES * STAGE_BYTES;

    const __nv_bfloat16* Ag = A + (size_t)m0 * KEXT;
    const __nv_bfloat16* Bg = Bm + (size_t)n0 * KEXT;

    float acc[4][8][4];
#pragma unroll
    for (int i = 0; i < 4; i++)
#pragma unroll
        for (int j = 0; j < 8; j++)
#pragma unroll
            for (int k = 0; k < 4; k++) acc[i][j][k] = 0.f;

    // loads: 512 A chunks + 512 B chunks per stage; 4 each per thread (128 thr)
#pragma unroll
    for (int s = 0; s < STAGES - 1; s++) {
        int kt = s * KT;
#pragma unroll
        for (int j = 0; j < 4; j++) {
            int i = tid + j * 128;
            int r = i >> 2, c = i & 3;
            cp16(sA0 + s * STAGE_BYTES + (r * ASTRIDE + c * 8) * 2, Ag + (size_t)r * KEXT + kt + c * 8);
            cp16(sB0 + s * STAGE_BYTES + (r * ASTRIDE + c * 8) * 2, Bg + (size_t)r * KEXT + kt + c * 8);
        }
        CP_COMMIT();
    }

    int a_row = wm + (lane & 15);
    int a_koff = (lane >> 4) * 8;
    int b_row = wn + ((lane >> 4) * 8) + (lane & 7);
    int b_koff = ((lane >> 3) & 1) * 8;

    const int KITER = KEXT / KT;
    for (int it = 0; it < KITER; it++) {
        int s = it % STAGES;
        CP_WAIT(STAGES - 2);
        __syncthreads();

        uint32_t aBase = sA0 + s * STAGE_BYTES;
        uint32_t bBase = sB0 + s * STAGE_BYTES;
#pragma unroll
        for (int kk = 0; kk < 2; kk++) {
            uint32_t af[4][4];
#pragma unroll
            for (int mt = 0; mt < 4; mt++) {
                uint32_t addr = aBase + ((a_row + mt * 16) * ASTRIDE + kk * 16 + a_koff) * 2;
                ldsm_x4(af[mt][0], af[mt][1], af[mt][2], af[mt][3], addr);
            }
#pragma unroll
            for (int np = 0; np < 4; np++) {
                uint32_t b0, b1, b2, b3;
                uint32_t addr = bBase + ((b_row + np * 16) * ASTRIDE + kk * 16 + b_koff) * 2;
                ldsm_x4(b0, b1, b2, b3, addr);
#pragma unroll
                for (int mt = 0; mt < 4; mt++) {
                    mma16816(acc[mt][np * 2],     af[mt], b0, b1);
                    mma16816(acc[mt][np * 2 + 1], af[mt], b2, b3);
                }
            }
        }
        int nit = it + STAGES - 1;
        if (nit < KITER) {
            int ns = nit % STAGES;
            int kt = nit * KT;
#pragma unroll
            for (int j = 0; j < 4; j++) {
                int i = tid + j * 128;
                int r = i >> 2, c = i & 3;
                cp16(sA0 + ns * STAGE_BYTES + (r * ASTRIDE + c * 8) * 2, Ag + (size_t)r * KEXT + kt + c * 8);
                cp16(sB0 + ns * STAGE_BYTES + (r * ASTRIDE + c * 8) * 2, Bg + (size_t)r * KEXT + kt + c * 8);
            }
        }
        CP_COMMIT();
    }

    // epilogue
    int crow = m0 + wm + (lane >> 2);
    int ccol = wn + (lane & 3) * 2;
    bool selfPart = (n0 >= 3072);
#pragma unroll
    for (int mt = 0; mt < 4; mt++) {
#pragma unroll
        for (int nt = 0; nt < 8; nt++) {
            int r1 = crow + mt * 16;
            int r2 = r1 + 8;
            int cl = ccol + nt * 8;
            int gc = n0 + cl;
            float2 v01; v01.x = acc[mt][nt][0]; v01.y = acc[mt][nt][1];
            float2 v23; v23.x = acc[mt][nt][2]; v23.y = acc[mt][nt][3];
            if (selfPart) {
                *(float2*)(C + (size_t)r1 * KDIM + gc) = v01;
                *(float2*)(C + (size_t)r2 * KDIM + gc) = v23;
            } else {
                __nv_bfloat16 h0 = __float2bfloat16(v01.x);
                __nv_bfloat16 h1 = __float2bfloat16(v01.y);
                __nv_bfloat16 h2 = __float2bfloat16(v23.x);
                __nv_bfloat16 h3 = __float2bfloat16(v23.y);
                __nv_bfloat162 hp1; hp1.x = h0; hp1.y = h1;
                __nv_bfloat162 hp2; hp2.x = h2; hp2.y = h3;
                __nv_bfloat162 lp1;
                lp1.x = __float2bfloat16(v01.x - __bfloat162float(h0));
                lp1.y = __float2bfloat16(v01.y - __bfloat162float(h1));
                __nv_bfloat162 lp2;
                lp2.x = __float2bfloat16(v23.x - __bfloat162float(h2));
                lp2.y = __float2bfloat16(v23.y - __bfloat162float(h3));
                *(__nv_bfloat162*)(YHp + (size_t)r1 * 3072 + gc) = hp1;
                *(__nv_bfloat162*)(YHp + (size_t)r2 * 3072 + gc) = hp2;
                *(__nv_bfloat162*)(YLp + (size_t)r1 * 3072 + gc) = lp1;
                *(__nv_bfloat162*)(YLp + (size_t)r2 * 3072 + gc) = lp2;
            }
        }
    }
}

// ---------------- combine via mma.sync: Z = relu(AC_split @ Y_split + Y_self) ----------------
#define BSTR 264
#define CSTG 4
template<int S, int RG>
__global__ __launch_bounds__(256, 2)
void k_combine_mma(const __nv_bfloat16* __restrict__ AE,
                   const __nv_bfloat16* __restrict__ YHp,
                   const __nv_bfloat16* __restrict__ YLp,
                   const float* __restrict__ Yf,
                   float* __restrict__ Z) {
    constexpr int KC = 6 * S;
    constexpr int KE = (S == 62) ? 1120 : 1152;
    constexpr int KIT = KE / 32;
    constexpr int RPB = KE * 8;
    extern __shared__ char dyn[];
    ull* rp = (ull*)dyn;
    uint32_t aOff = smem_u32(dyn) + RPB;
    uint32_t bOff = aOff + CSTG * 5120;

    int tid = threadIdx.x, wid = tid >> 5, lane = tid & 31;
    int b = blockIdx.y;
    int n0c = blockIdx.x * 256;

    for (int k = tid; k < KE; k += 256) {
        int p = k / KC, r = k - p * KC;
        if (p > 2) { p = 0; r = 0; }
        int q = r / S, m = r - q * S;
        int node = (RG == 1) ? m : (m < 58 ? m : (m < 62 ? 62 + (m - 58) : 61));
        const __nv_bfloat16* src = (p == 1) ? YLp : YHp;
        rp[k] = (ull)(src + ((size_t)node * B + b) * 3072 + q * 512 + n0c);
    }
    __syncthreads();

    const __nv_bfloat16* Ab = AE + (size_t)b * 64 * KE;
    int arow = tid >> 2, ac = tid & 3;

    float acc[2][8][4];
#pragma unroll
    for (int i = 0; i < 2; i++)
#pragma unroll
        for (int j = 0; j < 8; j++)
#pragma unroll
            for (int k = 0; k < 4; k++) acc[i][j][k] = 0.f;

#pragma unroll
    for (int s = 0; s < CSTG - 1; s++) {
        int kt = s * 32;
        cp16(aOff + s * 5120 + (arow * ASTRIDE + ac * 8) * 2, Ab + (size_t)arow * KE + kt + ac * 8);
#pragma unroll
        for (int j = 0; j < 4; j++) {
            int i = tid + j * 256;
            int kr = i >> 5, c = i & 31;
            cp16(bOff + s * 16896 + (kr * BSTR + c * 8) * 2, (const char*)rp[kt + kr] + c * 16);
        }
        CP_COMMIT();
    }

    int wm = (wid & 1) * 32, wn = (wid >> 1) * 64;
    int a_row = wm + (lane & 15);
    int a_koff = (lane >> 4) * 8;
    int grp = lane >> 3, lrow = lane & 7;

    for (int it = 0; it < KIT; it++) {
        CP_WAIT(CSTG - 2);
        __syncthreads();
        uint32_t aB = aOff + (it % CSTG) * 5120;
        uint32_t bB = bOff + (it % CSTG) * 16896;
#pragma unroll
        for (int kk = 0; kk < 2; kk++) {
            uint32_t af[2][4];
#pragma unroll
            for (int mt = 0; mt < 2; mt++) {
                uint32_t addr = aB + ((a_row + mt * 16) * ASTRIDE + kk * 16 + a_koff) * 2;
                ldsm_x4(af[mt][0], af[mt][1], af[mt][2], af[mt][3], addr);
            }
#pragma unroll
            for (int np = 0; np < 4; np++) {
                uint32_t b0, b1, b2, b3;
                uint32_t addr = bB + ((kk * 16 + (grp & 1) * 8 + lrow) * BSTR
                                      + wn + np * 16 + (grp >> 1) * 8) * 2;
                ldsm_x4_t(b0, b1, b2, b3, addr);
#pragma unroll
                for (int mt = 0; mt < 2; mt++) {
                    mma16816(acc[mt][np * 2],     af[mt], b0, b1);
                    mma16816(acc[mt][np * 2 + 1], af[mt], b2, b3);
                }
            }
        }
        int nit = it + CSTG - 1;
        if (nit < KIT) {
            int ns = nit % CSTG;
            int kt = nit * 32;
            cp16(aOff + ns * 5120 + (arow * ASTRIDE + ac * 8) * 2, Ab + (size_t)arow * KE + kt + ac * 8);
#pragma unroll
            for (int j = 0; j < 4; j++) {
                int i = tid + j * 256;
                int kr = i >> 5, c = i & 31;
                cp16(bOff + ns * 16896 + (kr * BSTR + c * 8) * 2, (const char*)rp[kt + kr] + c * 16);
            }
        }
        CP_COMMIT();
    }

    int crow = wm + (lane >> 2);
    int ccol = wn + (lane & 3) * 2;
#pragma unroll
    for (int mt = 0; mt < 2; mt++) {
#pragma unroll
        for (int nt = 0; nt < 8; nt++) {
            int g = n0c + ccol + nt * 8;
#pragma unroll
            for (int half = 0; half < 2; half++) {
                int n = crow + mt * 16 + half * 8;
                float x = acc[mt][nt][half * 2];
                float y = acc[mt][nt][half * 2 + 1];
                if (n < S) {
                    int node = (RG == 1) ? n : (n < 58 ? n : (n < 62 ? 62 + (n - 58) : 61));
                    const float* sp = Yf + ((size_t)node * B + b) * KDIM + 3072 + g;
                    float2 o;
                    o.x = fmaxf(x + sp[0], 0.f);
                    o.y = fmaxf(y + sp[1], 0.f);
                    *(float2*)(Z + ((size_t)b * S + n) * 512 + g) = o;
                }
            }
        }
    }
}

// ---------------- layer-2 message aggregation (fp32) ----------------
__global__ void k_msg(const float* __restrict__ ACm, const float* __restrict__ X,
                      float* __restrict__ F, int nodes, int nRows, int rowBase, int rowStride) {
    int b = blockIdx.y, i = blockIdx.x;
    int row = rowBase + i * rowStride;
    __shared__ __align__(16) ull sA[NQ][64];
    int t = threadIdx.x;
    for (int e = t; e < NQ * nodes; e += 256) {
        int q = e / nodes, m = e % nodes;
        float a = ACm[(((size_t)b * NQ + q) * nodes + row) * nodes + m];
        sA[q][m] = dup2(a);
    }
    __syncthreads();
    ull acc[NQ] = {0ULL, 0ULL, 0ULL, 0ULL, 0ULL, 0ULL};
    const float* xb = X + (size_t)b * nodes * HDIM;
    int h = t * 2;
    for (int m = 0; m < nodes; m++) {
        ull xv = *(const ull*)(xb + (size_t)m * HDIM + h);
#pragma unroll
        for (int q = 0; q < NQ; q++) fma2(acc[q], sA[q][m], xv);
    }
    float* Fp = F + ((size_t)b * nRows + i) * KDIM;
#pragma unroll
    for (int q = 0; q < NQ; q++)
        *(ull*)(Fp + q * HDIM + h) = acc[q];
    *(ull*)(Fp + 3072 + h) = *(const ull*)(xb + (size_t)row * HDIM + h);
}

// ---------------- fp32 SGEMM tile 64x64 (layer-2): C = sigmoid(A @ Bw) ----------------
__global__ __launch_bounds__(256)
void k_gemm64(const float* __restrict__ A, const float* __restrict__ Bw,
              float* __restrict__ C, int K, int lda, int ldn) {
    __shared__ __align__(16) float As[16][64];
    __shared__ __align__(16) float Bs[16][68];
    int tid = threadIdx.x;
    int mb = blockIdx.x * 64, nb = blockIdx.y * 64;

    int arow = tid >> 2, ak = (tid & 3) * 4;
    int bk = tid >> 4, bn4 = (tid & 15) * 4;
    const float* Aptr = A + (size_t)(mb + arow) * lda + ak;
    const float* Bptr = Bw + (size_t)bk * ldn + nb + bn4;

    int tx = tid & 15, ty = tid >> 4;
    int r0 = ty * 4, c0 = tx * 4;

    ull acc[4][2];
#pragma unroll
    for (int i = 0; i < 4; i++) { acc[i][0] = 0ULL; acc[i][1] = 0ULL; }

    for (int kt = 0; kt < K; kt += 16) {
        float4 av = *(const float4*)(Aptr + kt);
        float4 bv = *(const float4*)(Bptr + (size_t)kt * ldn);
        As[ak + 0][arow] = av.x;
        As[ak + 1][arow] = av.y;
        As[ak + 2][arow] = av.z;
        As[ak + 3][arow] = av.w;
        *(float4*)&Bs[bk][bn4] = bv;
        __syncthreads();
#pragma unroll
        for (int k = 0; k < 16; k++) {
            float4 a4 = *(const float4*)&As[k][r0];
            ulonglong2 b2 = *(const ulonglong2*)&Bs[k][c0];
            float aa[4] = {a4.x, a4.y, a4.z, a4.w};
#pragma unroll
            for (int i = 0; i < 4; i++) {
                ull ad = dup2(aa[i]);
                fma2(acc[i][0], ad, b2.x);
                fma2(acc[i][1], ad, b2.y);
            }
        }
        __syncthreads();
    }

#pragma unroll
    for (int i = 0; i < 4; i++) {
        float* Cp = C + (size_t)(mb + r0 + i) * ldn + nb + c0;
        float l0, h0, l1, h1;
        unpack2(acc[i][0], l0, h0);
        unpack2(acc[i][1], l1, h1);
        float4 o;
        o.x = 1.f / (1.f + expf(-l0));
        o.y = 1.f / (1.f + expf(-h0));
        o.z = 1.f / (1.f + expf(-l1));
        o.w = 1.f / (1.f + expf(-h1));
        *(float4*)Cp = o;
    }
}

// ---------------- final logits ----------------
__global__ void k_logits(const float* __restrict__ U, const float* __restrict__ tW,
                         const float* __restrict__ tb, float* __restrict__ out) {
    int b = blockIdx.x;
    int w = threadIdx.x >> 5, lane = threadIdx.x & 31;
    if (w >= 11) return;
    const float* black = U + ((size_t)b * 2 + 1) * HDIM;
    const float* white = U + ((size_t)b * 2 + 0) * HDIM;
    const float* row = tW + w * 1024;
    float s = 0.f;
    for (int j = lane; j < HDIM; j += 32)
        s += black[j] * row[j] + white[j] * row[HDIM + j];
#pragma unroll
    for (int o = 16; o; o >>= 1) s += __shfl_down_sync(0xffffffffu, s, o);
    if (lane == 0) out[b * 11 + w] = s + tb[w];
}

// ---------------- host ----------------
extern "C" void kernel_launch(void* const* d_in, const int* in_sizes, int n_in,
                              void* d_out, int out_size) {
    int s = (n_in >= 21 && in_sizes[1] == 1) ? 1 : 0;

    const int*   player = (const int*)d_in[0];
    const float* enc    = (const float*)d_in[1 + s];
    const int*   adj    = (const int*)d_in[2 + s];
    const float* Ax     = (const float*)d_in[3 + s];
    const float* Ay     = (const float*)d_in[4 + s];
    const float* Bx     = (const float*)d_in[5 + s];
    const float* By     = (const float*)d_in[6 + s];
    const float* emb    = (const float*)d_in[7 + s];
    const float* coordW = (const float*)d_in[8 + s];
    const float* coordB = (const float*)d_in[9 + s];
    const float* inW    = (const float*)d_in[10 + s];
    const float* inB    = (const float*)d_in[11 + s];
    const float* basis0 = (const float*)d_in[12 + s];
    const float* comb0  = (const float*)d_in[13 + s];
    const float* self0  = (const float*)d_in[14 + s];
    const float* basis1 = (const float*)d_in[15 + s];
    const float* comb1  = (const float*)d_in[16 + s];
    const float* self1  = (const float*)d_in[17 + s];
    const float* typeW  = (const float*)d_in[18 + s];
    const float* typeB  = (const float*)d_in[19 + s];

    float* base = nullptr;
    cudaGetSymbolAddress((void**)&base, g_scratch);
    float* CW1  = base;
    float* INIT = base + 1835008;
    float* Y    = base + 2129920;
    float* Z1   = base + 62685184;
    float* Z2   = base + 70811648;
    float* Tb   = base + 79069184;
    float* U    = base + 79593472;
    float* AC1m = base + 79855616;
    float* AC2m = base + 85760000;
    float* F    = base + 91856384;
    __nv_bfloat16* AEXT = (__nv_bfloat16*)(base + 95526400);
    __nv_bfloat16* BEXT = (__nv_bfloat16*)(base + 108502528);
    __nv_bfloat16* YH   = (__nv_bfloat16*)(base + 111255040);
    __nv_bfloat16* YL   = (__nv_bfloat16*)(base + 137207296);
    __nv_bfloat16* A1E  = (__nv_bfloat16*)(base + 163159552);
    __nv_bfloat16* A2E  = (__nv_bfloat16*)(base + 172334592);

    const int mma_smem = 2 * STAGES * STAGE_BYTES;           // 81920
    const int c1_smem = 1120 * 8 + CSTG * (5120 + 16896);    // 97024
    const int c2_smem = 1152 * 8 + CSTG * (5120 + 16896);    // 97280

    static cudaStream_t s2 = nullptr;
    static cudaEvent_t evA = nullptr, evB = nullptr, evC = nullptr;
    static int once = 0;
    if (!once) {
        cudaFuncSetAttribute(k_mma, cudaFuncAttributeMaxDynamicSharedMemorySize, mma_smem);
        cudaFuncSetAttribute(k_combine_mma<62, 1>, cudaFuncAttributeMaxDynamicSharedMemorySize, c1_smem);
        cudaFuncSetAttribute(k_combine_mma<63, 2>, cudaFuncAttributeMaxDynamicSharedMemorySize, c2_smem);
        cudaStreamCreateWithFlags(&s2, cudaStreamNonBlocking);
        cudaEventCreateWithFlags(&evA, cudaEventDisableTiming);
        cudaEventCreateWithFlags(&evB, cudaEventDisableTiming);
        cudaEventCreateWithFlags(&evC, cudaEventDisableTiming);
        once = 1;
    }

    // fork side stream from the capture (default) stream
    cudaEventRecord(evA, 0);
    cudaStreamWaitEvent(s2, evA, 0);

    // side stream: BEXT (independent of everything)               launch #1
    k_bext<<<(KDIM * HDIM + 255) / 256, 256, 0, s2>>>(basis0, self0, BEXT);
    cudaEventRecord(evB, s2);

    // main stream: INIT + AEXT                                    launches #2, #3
    k_init<<<dim3(8, 8), 256>>>(player, Ax, Ay, Bx, By, emb, coordW, coordB, inW, inB, INIT);
    k_aext<<<(62 * B * HDIM + 255) / 256, 256>>>(enc, INIT, AEXT);

    // join BEXT, then the big Y projection                        launch #4 (ncu profiles this)
    cudaStreamWaitEvent(0, evB, 0);
    k_mma<<<dim3(62 * B / 128, KDIM / 128), 128, mma_smem>>>(AEXT, BEXT, Y, YH, YL, 0);

    // side stream overlaps prep with the Y projection
    k_ac1<<<dim3(B, 16), 256, 0, s2>>>(adj, comb0, comb1, A1E, AC1m);
    k_ac2<<<dim3(B, 16), 256, 0, s2>>>(adj, comb0, comb1, A2E, AC2m);
    k_build_cw1<<<(KDIM * HDIM + 255) / 256, 256, 0, s2>>>(basis1, self1, CW1);
    cudaEventRecord(evC, s2);
    cudaStreamWaitEvent(0, evC, 0);

    // rgcn1 layer1 combine (mma) -> Z1
    k_combine_mma<62, 1><<<dim3(2, B), 256, c1_smem>>>(A1E, YH, YL, Y, Z1);
    // rgcn1 layer2 (rows 58..61) -> Tb
    k_msg<<<dim3(4, B), 256>>>(AC1m, Z1, F, S1, 4, 58, 1);
    k_gemm64<<<dim3(4 * B / 64, HDIM / 64), 256>>>(F, CW1, Tb, KDIM, KDIM, HDIM);

    // T nodes -> AEXT rows 62..65, project
    k_aextT<<<(4 * B * HDIM + 255) / 256, 256>>>(Tb, AEXT);
    k_mma<<<dim3(4 * B / 128, KDIM / 128), 128, mma_smem>>>(AEXT, BEXT, Y, YH, YL, 62 * B);

    // rgcn2 layer1 combine (mma) -> Z2
    k_combine_mma<63, 2><<<dim3(2, B), 256, c2_smem>>>(A2E, YH, YL, Y, Z2);
    // rgcn2 layer2 (rows 60, 62) -> U
    k_msg<<<dim3(2, B), 256>>>(AC2m, Z2, F, S2, 2, 60, 2);
    k_gemm64<<<dim3(2 * B / 64, HDIM / 64), 256>>>(F, CW1, U, KDIM, KDIM, HDIM);

    k_logits<<<B, 352>>>(U, typeW, typeB, (float*)d_out);
}